// round 1
// baseline (speedup 1.0000x reference)
#include <cuda_runtime.h>
#include <cuda_bf16.h>

#define BATCH 4
#define SEQ   2048
#define EMB   1024
#define MTOT  (BATCH * SEQ)   // 8192

// Scratch (allocation-free rule: __device__ globals)
__device__ float g_Q[BATCH * SEQ * EMB];   // 32 MB
__device__ float g_K[BATCH * SEQ * EMB];   // 32 MB
__device__ float g_V[BATCH * SEQ * EMB];   // 32 MB
__device__ float g_P[(long)BATCH * SEQ * SEQ]; // 64 MB scores/probs

// ---------------------------------------------------------------------------
// Generic 128x128x8 SGEMM, 256 threads, 8x8 per thread.
//   TRANSB : B stored [N, K] (reduce along contiguous K)  — used for W^T and K^T
//   CAUSAL : skip tiles strictly above the diagonal (QK^T)
//   TRUNCK : PV — probs are zero for k > q, stop K loop at (by+1)*128
//   BIAS   : add bias[col] in epilogue (projections)
// ---------------------------------------------------------------------------
template<bool TRANSB, bool CAUSAL, bool TRUNCK, bool BIAS>
__global__ void __launch_bounds__(256)
gemm128x128(const float* __restrict__ A, const float* __restrict__ B,
            float* __restrict__ C, int M, int N, int K, float alpha,
            const float* __restrict__ bias,
            long strideA, long strideB, long strideC)
{
    const int bx = blockIdx.x, by = blockIdx.y, bz = blockIdx.z;
    if (CAUSAL && bx > by) return;

    A += (long)bz * strideA;
    B += (long)bz * strideB;
    C += (long)bz * strideC;

    int kEnd = K;
    if (TRUNCK) kEnd = min(K, (by + 1) * 128);

    constexpr int BK = 8;
    __shared__ float As[BK][128];
    __shared__ float Bs[BK][128];

    const int tid = threadIdx.x;

    // A tile loads (transposed into As): 128 rows x 8 cols, float4 per thread
    const int arow = tid >> 1;
    const int acol = (tid & 1) * 4;
    // B tile loads
    const int browT = tid >> 1;          // TRANSB: n-index
    const int bcolT = (tid & 1) * 4;     // TRANSB: k-index
    const int brow  = tid >> 5;          // !TRANSB: k-index (0..7)
    const int bcol  = (tid & 31) * 4;    // !TRANSB: n-index

    const int tr = (tid / 16) * 8;
    const int tc = (tid % 16) * 8;

    float acc[8][8] = {};
    float ar[8], br[8];

    const float* Aptr = A + (long)(by * 128 + arow) * K;

    for (int k0 = 0; k0 < kEnd; k0 += BK) {
        float4 a4 = *reinterpret_cast<const float4*>(Aptr + k0 + acol);
        As[acol + 0][arow] = a4.x;
        As[acol + 1][arow] = a4.y;
        As[acol + 2][arow] = a4.z;
        As[acol + 3][arow] = a4.w;

        if (TRANSB) {
            float4 b4 = *reinterpret_cast<const float4*>(
                B + (long)(bx * 128 + browT) * K + k0 + bcolT);
            Bs[bcolT + 0][browT] = b4.x;
            Bs[bcolT + 1][browT] = b4.y;
            Bs[bcolT + 2][browT] = b4.z;
            Bs[bcolT + 3][browT] = b4.w;
        } else {
            float4 b4 = *reinterpret_cast<const float4*>(
                B + (long)(k0 + brow) * N + bx * 128 + bcol);
            *reinterpret_cast<float4*>(&Bs[brow][bcol]) = b4;
        }
        __syncthreads();

        #pragma unroll
        for (int kk = 0; kk < BK; kk++) {
            #pragma unroll
            for (int i = 0; i < 8; i++) ar[i] = As[kk][tr + i];
            #pragma unroll
            for (int j = 0; j < 8; j++) br[j] = Bs[kk][tc + j];
            #pragma unroll
            for (int i = 0; i < 8; i++)
                #pragma unroll
                for (int j = 0; j < 8; j++)
                    acc[i][j] += ar[i] * br[j];
        }
        __syncthreads();
    }

    #pragma unroll
    for (int i = 0; i < 8; i++) {
        const long crow = by * 128 + tr + i;
        #pragma unroll
        for (int j = 0; j < 8; j += 4) {
            const int ccol = bx * 128 + tc + j;
            float4 v;
            v.x = acc[i][j + 0] * alpha;
            v.y = acc[i][j + 1] * alpha;
            v.z = acc[i][j + 2] * alpha;
            v.w = acc[i][j + 3] * alpha;
            if (BIAS) {
                v.x += bias[ccol + 0];
                v.y += bias[ccol + 1];
                v.z += bias[ccol + 2];
                v.w += bias[ccol + 3];
            }
            *reinterpret_cast<float4*>(C + crow * (long)N + ccol) = v;
        }
    }
}

// ---------------------------------------------------------------------------
// Causal row softmax over g_P: one block per (b,q) row.
// Valid region: k in [0, q]; writes zeros for k in (q, SEQ).
// ---------------------------------------------------------------------------
__global__ void __launch_bounds__(256) softmax_causal(float* __restrict__ P)
{
    const int row = blockIdx.x;           // b*SEQ + q
    const int q   = row & (SEQ - 1);
    float* p = P + (long)row * SEQ;
    const int n = q + 1;
    const int tid = threadIdx.x;

    __shared__ float red[8];

    // pass 1: max
    float m = -3.4e38f;
    for (int i = tid; i < n; i += 256) m = fmaxf(m, p[i]);
    #pragma unroll
    for (int o = 16; o > 0; o >>= 1)
        m = fmaxf(m, __shfl_xor_sync(0xffffffffu, m, o));
    if ((tid & 31) == 0) red[tid >> 5] = m;
    __syncthreads();
    m = red[0];
    #pragma unroll
    for (int w = 1; w < 8; w++) m = fmaxf(m, red[w]);
    __syncthreads();

    // pass 2: exp + sum (store exp in place)
    float s = 0.f;
    for (int i = tid; i < n; i += 256) {
        float e = __expf(p[i] - m);
        p[i] = e;
        s += e;
    }
    #pragma unroll
    for (int o = 16; o > 0; o >>= 1)
        s += __shfl_xor_sync(0xffffffffu, s, o);
    if ((tid & 31) == 0) red[tid >> 5] = s;
    __syncthreads();
    float tot = red[0];
    #pragma unroll
    for (int w = 1; w < 8; w++) tot += red[w];
    const float inv = 1.f / tot;

    // pass 3: normalize + zero the masked tail
    for (int i = tid; i < n; i += 256) p[i] *= inv;
    for (int i = n + tid; i < SEQ; i += 256) p[i] = 0.f;
}

// ---------------------------------------------------------------------------
extern "C" void kernel_launch(void* const* d_in, const int* in_sizes, int n_in,
                              void* d_out, int out_size)
{
    (void)in_sizes; (void)n_in; (void)out_size;
    const float* xq = (const float*)d_in[0];
    const float* xk = (const float*)d_in[1];
    const float* xv = (const float*)d_in[2];
    const float* Wq = (const float*)d_in[3];
    const float* bq = (const float*)d_in[4];
    // d_in[5] = att_mask (unused; causality implemented directly)
    float* out = (float*)d_out;

    float *Q, *K, *V, *P;
    cudaGetSymbolAddress((void**)&Q, g_Q);
    cudaGetSymbolAddress((void**)&K, g_K);
    cudaGetSymbolAddress((void**)&V, g_V);
    cudaGetSymbolAddress((void**)&P, g_P);

    const float scale = 0.03125f;  // 1/sqrt(1024)

    // 1) Projections: Q/K/V = x @ Wq^T + bq   (M=8192, N=1024, K=1024)
    {
        dim3 grid(EMB / 128, MTOT / 128, 1);
        gemm128x128<true, false, false, true><<<grid, 256>>>(
            xq, Wq, Q, MTOT, EMB, EMB, 1.0f, bq, 0, 0, 0);
        gemm128x128<true, false, false, true><<<grid, 256>>>(
            xk, Wq, K, MTOT, EMB, EMB, 1.0f, bq, 0, 0, 0);
        gemm128x128<true, false, false, true><<<grid, 256>>>(
            xv, Wq, V, MTOT, EMB, EMB, 1.0f, bq, 0, 0, 0);
    }

    // 2) Scores = scale * Q @ K^T, causal tile skip  (per batch: 2048x2048x1024)
    {
        dim3 grid(SEQ / 128, SEQ / 128, BATCH);
        gemm128x128<true, true, false, false><<<grid, 256>>>(
            Q, K, P, SEQ, SEQ, EMB, scale, nullptr,
            (long)SEQ * EMB, (long)SEQ * EMB, (long)SEQ * SEQ);
    }

    // 3) Causal softmax (writes zeros beyond the diagonal)
    softmax_causal<<<MTOT, 256>>>(P);

    // 4) Out = P @ V, K-loop truncated at the diagonal tile (per batch)
    {
        dim3 grid(EMB / 128, SEQ / 128, BATCH);
        gemm128x128<false, false, true, false><<<grid, 256>>>(
            P, V, out, SEQ, EMB, SEQ, 1.0f, nullptr,
            (long)SEQ * SEQ, (long)SEQ * EMB, (long)SEQ * EMB);
    }
}

// round 3
// speedup vs baseline: 2.3843x; 2.3843x over previous
#include <cuda_runtime.h>
#include <cuda_bf16.h>
#include <cstdint>

#define BATCH 4
#define SEQ   2048
#define EMB   1024
#define MTOT  (BATCH * SEQ)                 // 8192
#define NELEM ((long)MTOT * EMB)            // 8388608
#define NP    ((long)BATCH * SEQ * SEQ)     // 16777216

// ---------------------------------------------------------------------------
// Scratch (__device__ globals). hi/lo planes: [2][...]
// ---------------------------------------------------------------------------
__device__ __nv_bfloat16 g_xq2[2 * NELEM];
__device__ __nv_bfloat16 g_xk2[2 * NELEM];
__device__ __nv_bfloat16 g_xv2[2 * NELEM];
__device__ __nv_bfloat16 g_W2[2L * EMB * EMB];
__device__ __nv_bfloat16 g_Q2[2 * NELEM];
__device__ __nv_bfloat16 g_K2[2 * NELEM];
__device__ __nv_bfloat16 g_V2[2 * NELEM];
__device__ __nv_bfloat16 g_VT2[2 * NELEM];   // [2][B][E][S]
__device__ __nv_bfloat16 g_P2[2 * NP];       // probs hi/lo
__device__ float         g_Pf[NP];           // fp32 scores

// ---------------------------------------------------------------------------
__device__ __forceinline__ uint32_t smem_u32(const void* p) {
    uint32_t a;
    asm("{ .reg .u64 t; cvta.to.shared.u64 t, %1; cvt.u32.u64 %0, t; }" : "=r"(a) : "l"(p));
    return a;
}

#define LDSM4(r, addr) \
    asm volatile("ldmatrix.sync.aligned.m8n8.x4.shared.b16 {%0,%1,%2,%3}, [%4];" \
        : "=r"((r)[0]), "=r"((r)[1]), "=r"((r)[2]), "=r"((r)[3]) : "r"(addr))

#define MMA_BF16(d, a, b0, b1) \
    asm volatile("mma.sync.aligned.m16n8k16.row.col.f32.bf16.bf16.f32 " \
        "{%0,%1,%2,%3}, {%4,%5,%6,%7}, {%8,%9}, {%0,%1,%2,%3};" \
        : "+f"((d)[0]), "+f"((d)[1]), "+f"((d)[2]), "+f"((d)[3]) \
        : "r"((a)[0]), "r"((a)[1]), "r"((a)[2]), "r"((a)[3]), "r"(b0), "r"(b1))

// smem geometry: per stage: A hi(10240) A lo(10240) B hi(10240) B lo(10240) = 40960
// row pitch 80B (32 bf16 + 8 pad) -> ldmatrix conflict-free
#define STAGE_B   40960
#define SMEM_REQ  (2 * STAGE_B)

// ---------------------------------------------------------------------------
// Split-bf16 tensor-core GEMM: C[128x128] = alpha * A @ B^T (+ bias)
// A: [2][rowsA][K] bf16 (hi plane then lo, planeA elems apart)
// B: [2][rowsB][K] bf16
// ---------------------------------------------------------------------------
template <bool CAUSAL, bool TRUNCK, bool BIAS, bool WF32, bool WBF16>
__global__ void __launch_bounds__(256)
gemm_mma(const __nv_bfloat16* __restrict__ A, long strideAz, long planeA,
         const __nv_bfloat16* __restrict__ B, long strideBz, long planeB,
         int K, float alpha, const float* __restrict__ bias,
         float* __restrict__ Cf, __nv_bfloat16* __restrict__ Ch,
         __nv_bfloat16* __restrict__ Cl, int ldc, long strideCz)
{
    const int bx = blockIdx.x, by = blockIdx.y, bz = blockIdx.z;
    if (CAUSAL && bx > by) return;

    extern __shared__ char smem[];
    const uint32_t sbase = smem_u32(smem);

    const __nv_bfloat16* Ab = A + (long)bz * strideAz;
    const __nv_bfloat16* Bb = B + (long)bz * strideBz;

    const int tid = threadIdx.x, wid = tid >> 5, l = tid & 31;
    const int wr = wid >> 1, wc = wid & 1;     // warp 32m x 64n
    const int kEnd = TRUNCK ? min(K, (by + 1) * 128) : K;
    const int nst = kEnd >> 5;                 // BK=32 stages
    const int rowA0 = by * 128, rowB0 = bx * 128;

    float acc[2][8][4];
#pragma unroll
    for (int m = 0; m < 2; m++)
#pragma unroll
        for (int n = 0; n < 8; n++)
#pragma unroll
            for (int j = 0; j < 4; j++) acc[m][n][j] = 0.f;

    // --- async stage loader: 2048 x 16B chunks, 8 per thread ---
#define LOAD_STAGE(sidx, buf) do { \
        const int k0_ = (sidx) * 32; \
        const uint32_t st_ = sbase + (buf) * STAGE_B; \
        _Pragma("unroll") \
        for (int i_ = 0; i_ < 8; i_++) { \
            int c_ = i_ * 256 + tid; \
            int half_ = c_ >> 10; \
            int w_ = c_ & 1023; \
            int plane_ = w_ >> 9; \
            int row_ = (w_ & 511) >> 2; \
            int seg_ = w_ & 3; \
            uint32_t dst_ = st_ + half_ * 20480 + plane_ * 10240 + row_ * 80 + seg_ * 16; \
            const __nv_bfloat16* gp_ = half_ \
                ? (Bb + plane_ * planeB + (long)(rowB0 + row_) * K) \
                : (Ab + plane_ * planeA + (long)(rowA0 + row_) * K); \
            const void* src_ = gp_ + k0_ + seg_ * 8; \
            asm volatile("cp.async.cg.shared.global [%0], [%1], 16;" :: "r"(dst_), "l"(src_)); \
        } \
        asm volatile("cp.async.commit_group;"); \
    } while (0)

    LOAD_STAGE(0, 0);

    const int lr = l & 15, lh = l >> 4;

    for (int s = 0; s < nst; s++) {
        const int b = s & 1;
        if (s + 1 < nst) {
            LOAD_STAGE(s + 1, b ^ 1);
            asm volatile("cp.async.wait_group 1;");
        } else {
            asm volatile("cp.async.wait_group 0;");
        }
        __syncthreads();

        const uint32_t st = sbase + b * STAGE_B;
#pragma unroll
        for (int kk = 0; kk < 32; kk += 16) {
            uint32_t AH[2][4], AL[2][4], BB[4][4];
            const uint32_t kb = (kk + lh * 8) * 2;
#pragma unroll
            for (int mt = 0; mt < 2; mt++) {
                uint32_t a0 = st + (wr * 32 + mt * 16 + lr) * 80 + kb;
                LDSM4(AH[mt], a0);
                LDSM4(AL[mt], a0 + 10240);
            }
#pragma unroll
            for (int np = 0; np < 4; np++) {
                uint32_t b0 = st + 20480 + (wc * 64 + np * 16 + lr) * 80 + kb;
                LDSM4(BB[np], b0);
            }
            // Ah*Bh + Al*Bh
#pragma unroll
            for (int mt = 0; mt < 2; mt++)
#pragma unroll
                for (int np = 0; np < 4; np++) {
                    MMA_BF16(acc[mt][2 * np],     AH[mt], BB[np][0], BB[np][2]);
                    MMA_BF16(acc[mt][2 * np + 1], AH[mt], BB[np][1], BB[np][3]);
                    MMA_BF16(acc[mt][2 * np],     AL[mt], BB[np][0], BB[np][2]);
                    MMA_BF16(acc[mt][2 * np + 1], AL[mt], BB[np][1], BB[np][3]);
                }
            // reload B lo over BB, then Ah*Bl
#pragma unroll
            for (int np = 0; np < 4; np++) {
                uint32_t b0 = st + 20480 + 10240 + (wc * 64 + np * 16 + lr) * 80 + kb;
                LDSM4(BB[np], b0);
            }
#pragma unroll
            for (int mt = 0; mt < 2; mt++)
#pragma unroll
                for (int np = 0; np < 4; np++) {
                    MMA_BF16(acc[mt][2 * np],     AH[mt], BB[np][0], BB[np][2]);
                    MMA_BF16(acc[mt][2 * np + 1], AH[mt], BB[np][1], BB[np][3]);
                }
        }
        __syncthreads();
    }
#undef LOAD_STAGE

    // --- epilogue ---
    const int rql = l >> 2, cpl = (l & 3) * 2;
#pragma unroll
    for (int mt = 0; mt < 2; mt++) {
#pragma unroll
        for (int nt = 0; nt < 8; nt++) {
            const int col = bx * 128 + wc * 64 + nt * 8 + cpl;
            const long row = (long)by * 128 + wr * 32 + mt * 16 + rql;
            float v0 = acc[mt][nt][0] * alpha, v1 = acc[mt][nt][1] * alpha;
            float v2 = acc[mt][nt][2] * alpha, v3 = acc[mt][nt][3] * alpha;
            if (BIAS) {
                float b0 = bias[col], b1 = bias[col + 1];
                v0 += b0; v1 += b1; v2 += b0; v3 += b1;
            }
            const long o0 = (long)bz * strideCz + row * ldc + col;
            const long o1 = o0 + 8L * ldc;
            if (WF32) {
                *reinterpret_cast<float2*>(Cf + o0) = make_float2(v0, v1);
                *reinterpret_cast<float2*>(Cf + o1) = make_float2(v2, v3);
            }
            if (WBF16) {
                __nv_bfloat16 h0 = __float2bfloat16(v0), h1 = __float2bfloat16(v1);
                __nv_bfloat16 h2 = __float2bfloat16(v2), h3 = __float2bfloat16(v3);
                __nv_bfloat16 l0 = __float2bfloat16(v0 - __bfloat162float(h0));
                __nv_bfloat16 l1 = __float2bfloat16(v1 - __bfloat162float(h1));
                __nv_bfloat16 l2 = __float2bfloat16(v2 - __bfloat162float(h2));
                __nv_bfloat16 l3 = __float2bfloat16(v3 - __bfloat162float(h3));
                uint32_t hA = (uint32_t)__bfloat16_as_ushort(h0) | ((uint32_t)__bfloat16_as_ushort(h1) << 16);
                uint32_t hB = (uint32_t)__bfloat16_as_ushort(h2) | ((uint32_t)__bfloat16_as_ushort(h3) << 16);
                uint32_t lA = (uint32_t)__bfloat16_as_ushort(l0) | ((uint32_t)__bfloat16_as_ushort(l1) << 16);
                uint32_t lB = (uint32_t)__bfloat16_as_ushort(l2) | ((uint32_t)__bfloat16_as_ushort(l3) << 16);
                *reinterpret_cast<uint32_t*>(Ch + o0) = hA;
                *reinterpret_cast<uint32_t*>(Ch + o1) = hB;
                *reinterpret_cast<uint32_t*>(Cl + o0) = lA;
                *reinterpret_cast<uint32_t*>(Cl + o1) = lB;
            }
        }
    }
}

// ---------------------------------------------------------------------------
// fp32 -> bf16 hi/lo split
// ---------------------------------------------------------------------------
__global__ void __launch_bounds__(256) split4(const float* __restrict__ in,
                                              __nv_bfloat16* __restrict__ out, long n)
{
    long i = ((long)blockIdx.x * 256 + threadIdx.x) * 4;
    if (i >= n) return;
    float4 v = *reinterpret_cast<const float4*>(in + i);
    __nv_bfloat16 h0 = __float2bfloat16(v.x), h1 = __float2bfloat16(v.y);
    __nv_bfloat16 h2 = __float2bfloat16(v.z), h3 = __float2bfloat16(v.w);
    __nv_bfloat16 l0 = __float2bfloat16(v.x - __bfloat162float(h0));
    __nv_bfloat16 l1 = __float2bfloat16(v.y - __bfloat162float(h1));
    __nv_bfloat16 l2 = __float2bfloat16(v.z - __bfloat162float(h2));
    __nv_bfloat16 l3 = __float2bfloat16(v.w - __bfloat162float(h3));
    uint32_t hA = (uint32_t)__bfloat16_as_ushort(h0) | ((uint32_t)__bfloat16_as_ushort(h1) << 16);
    uint32_t hB = (uint32_t)__bfloat16_as_ushort(h2) | ((uint32_t)__bfloat16_as_ushort(h3) << 16);
    uint32_t lA = (uint32_t)__bfloat16_as_ushort(l0) | ((uint32_t)__bfloat16_as_ushort(l1) << 16);
    uint32_t lB = (uint32_t)__bfloat16_as_ushort(l2) | ((uint32_t)__bfloat16_as_ushort(l3) << 16);
    *reinterpret_cast<uint2*>(out + i) = make_uint2(hA, hB);
    *reinterpret_cast<uint2*>(out + n + i) = make_uint2(lA, lB);
}

// ---------------------------------------------------------------------------
// bf16 transpose: [2][B][S][E] -> [2][B][E][S]
// ---------------------------------------------------------------------------
__global__ void __launch_bounds__(256) transpose_bf16(const __nv_bfloat16* __restrict__ in,
                                                      __nv_bfloat16* __restrict__ out)
{
    __shared__ unsigned short t[32][33];
    const int plane = blockIdx.z / BATCH, b = blockIdx.z % BATCH;
    const long off = ((long)plane * BATCH + b) * (long)SEQ * EMB;
    const unsigned short* ip = reinterpret_cast<const unsigned short*>(in) + off;
    unsigned short* op = reinterpret_cast<unsigned short*>(out) + off;
    const int c0 = blockIdx.x * 32, r0 = blockIdx.y * 32;
    for (int i = threadIdx.y; i < 32; i += 8)
        t[i][threadIdx.x] = ip[(long)(r0 + i) * EMB + c0 + threadIdx.x];
    __syncthreads();
    for (int i = threadIdx.y; i < 32; i += 8)
        op[(long)(c0 + i) * SEQ + r0 + threadIdx.x] = t[threadIdx.x][i];
}

// ---------------------------------------------------------------------------
// Causal row softmax: fp32 scores -> bf16 hi/lo probs (zero tail)
// ---------------------------------------------------------------------------
__global__ void __launch_bounds__(256)
softmax_causal(float* __restrict__ P, __nv_bfloat16* __restrict__ Ph,
               __nv_bfloat16* __restrict__ Pl)
{
    const int row = blockIdx.x;
    const int q = row & (SEQ - 1);
    float* p = P + (long)row * SEQ;
    __nv_bfloat16* ph = Ph + (long)row * SEQ;
    __nv_bfloat16* pl = Pl + (long)row * SEQ;
    const int n = q + 1;
    const int tid = threadIdx.x;

    __shared__ float red[8];

    float m = -3.4e38f;
    for (int i = tid; i < n; i += 256) m = fmaxf(m, p[i]);
#pragma unroll
    for (int o = 16; o > 0; o >>= 1) m = fmaxf(m, __shfl_xor_sync(0xffffffffu, m, o));
    if ((tid & 31) == 0) red[tid >> 5] = m;
    __syncthreads();
    m = red[0];
#pragma unroll
    for (int w = 1; w < 8; w++) m = fmaxf(m, red[w]);
    __syncthreads();

    float s = 0.f;
    for (int i = tid; i < n; i += 256) {
        float e = __expf(p[i] - m);
        p[i] = e;
        s += e;
    }
#pragma unroll
    for (int o = 16; o > 0; o >>= 1) s += __shfl_xor_sync(0xffffffffu, s, o);
    if ((tid & 31) == 0) red[tid >> 5] = s;
    __syncthreads();
    float tot = red[0];
#pragma unroll
    for (int w = 1; w < 8; w++) tot += red[w];
    const float inv = 1.f / tot;

    for (int i = tid; i < n; i += 256) {
        float pr = p[i] * inv;
        __nv_bfloat16 h = __float2bfloat16(pr);
        __nv_bfloat16 lo = __float2bfloat16(pr - __bfloat162float(h));
        ph[i] = h;
        pl[i] = lo;
    }
    const __nv_bfloat16 z = __float2bfloat16(0.f);
    for (int i = n + tid; i < SEQ; i += 256) { ph[i] = z; pl[i] = z; }
}

// ---------------------------------------------------------------------------
extern "C" void kernel_launch(void* const* d_in, const int* in_sizes, int n_in,
                              void* d_out, int out_size)
{
    (void)in_sizes; (void)n_in; (void)out_size;
    const float* xq = (const float*)d_in[0];
    const float* xk = (const float*)d_in[1];
    const float* xv = (const float*)d_in[2];
    const float* Wq = (const float*)d_in[3];
    const float* bq = (const float*)d_in[4];
    float* out = (float*)d_out;

    void *xq2, *xk2, *xv2, *W2, *Q2, *K2, *V2, *VT2, *P2, *Pf;
    cudaGetSymbolAddress(&xq2, g_xq2);
    cudaGetSymbolAddress(&xk2, g_xk2);
    cudaGetSymbolAddress(&xv2, g_xv2);
    cudaGetSymbolAddress(&W2, g_W2);
    cudaGetSymbolAddress(&Q2, g_Q2);
    cudaGetSymbolAddress(&K2, g_K2);
    cudaGetSymbolAddress(&V2, g_V2);
    cudaGetSymbolAddress(&VT2, g_VT2);
    cudaGetSymbolAddress(&P2, g_P2);
    cudaGetSymbolAddress(&Pf, g_Pf);

    auto kProj = gemm_mma<false, false, true, false, true>;
    auto kQK   = gemm_mma<true,  false, false, true, false>;
    auto kPV   = gemm_mma<false, true,  false, true, false>;
    cudaFuncSetAttribute(kProj, cudaFuncAttributeMaxDynamicSharedMemorySize, SMEM_REQ);
    cudaFuncSetAttribute(kQK,   cudaFuncAttributeMaxDynamicSharedMemorySize, SMEM_REQ);
    cudaFuncSetAttribute(kPV,   cudaFuncAttributeMaxDynamicSharedMemorySize, SMEM_REQ);

    // 1) split inputs to bf16 hi/lo
    split4<<<(unsigned)((NELEM / 4 + 255) / 256), 256>>>(xq, (__nv_bfloat16*)xq2, NELEM);
    split4<<<(unsigned)((NELEM / 4 + 255) / 256), 256>>>(xk, (__nv_bfloat16*)xk2, NELEM);
    split4<<<(unsigned)((NELEM / 4 + 255) / 256), 256>>>(xv, (__nv_bfloat16*)xv2, NELEM);
    split4<<<(unsigned)(((long)EMB * EMB / 4 + 255) / 256), 256>>>(Wq, (__nv_bfloat16*)W2, (long)EMB * EMB);

    // 2) projections: Q/K/V = x @ W^T + b -> bf16 hi/lo
    {
        dim3 g(EMB / 128, MTOT / 128, 1);
        kProj<<<g, 256, SMEM_REQ>>>((const __nv_bfloat16*)xq2, 0, NELEM,
                                    (const __nv_bfloat16*)W2, 0, (long)EMB * EMB,
                                    EMB, 1.0f, bq, nullptr,
                                    (__nv_bfloat16*)Q2, (__nv_bfloat16*)Q2 + NELEM, EMB, 0);
        kProj<<<g, 256, SMEM_REQ>>>((const __nv_bfloat16*)xk2, 0, NELEM,
                                    (const __nv_bfloat16*)W2, 0, (long)EMB * EMB,
                                    EMB, 1.0f, bq, nullptr,
                                    (__nv_bfloat16*)K2, (__nv_bfloat16*)K2 + NELEM, EMB, 0);
        kProj<<<g, 256, SMEM_REQ>>>((const __nv_bfloat16*)xv2, 0, NELEM,
                                    (const __nv_bfloat16*)W2, 0, (long)EMB * EMB,
                                    EMB, 1.0f, bq, nullptr,
                                    (__nv_bfloat16*)V2, (__nv_bfloat16*)V2 + NELEM, EMB, 0);
    }

    // 3) V transpose -> [2][B][E][S]
    transpose_bf16<<<dim3(EMB / 32, SEQ / 32, 2 * BATCH), dim3(32, 8)>>>(
        (const __nv_bfloat16*)V2, (__nv_bfloat16*)VT2);

    // 4) scores = scale * Q @ K^T (causal tile skip) -> fp32
    {
        dim3 g(SEQ / 128, SEQ / 128, BATCH);
        kQK<<<g, 256, SMEM_REQ>>>((const __nv_bfloat16*)Q2, (long)SEQ * EMB, NELEM,
                                  (const __nv_bfloat16*)K2, (long)SEQ * EMB, NELEM,
                                  EMB, 0.03125f, nullptr,
                                  (float*)Pf, nullptr, nullptr, SEQ, (long)SEQ * SEQ);
    }

    // 5) softmax -> bf16 hi/lo probs
    softmax_causal<<<MTOT, 256>>>((float*)Pf, (__nv_bfloat16*)P2,
                                  (__nv_bfloat16*)P2 + NP);

    // 6) out = P @ VT^T (K-truncated at diagonal) -> fp32
    {
        dim3 g(EMB / 128, SEQ / 128, BATCH);
        kPV<<<g, 256, SMEM_REQ>>>((const __nv_bfloat16*)P2, (long)SEQ * SEQ, NP,
                                  (const __nv_bfloat16*)VT2, (long)SEQ * EMB, NELEM,
                                  SEQ, 1.0f, nullptr,
                                  out, nullptr, nullptr, EMB, (long)SEQ * EMB);
    }
}

// round 4
// speedup vs baseline: 2.4461x; 1.0259x over previous
#include <cuda_runtime.h>
#include <cuda_bf16.h>
#include <cstdint>

#define BATCH 4
#define SEQ   2048
#define EMB   1024
#define MTOT  (BATCH * SEQ)                 // 8192
#define NELEM ((long)MTOT * EMB)            // 8388608
#define NP    ((long)BATCH * SEQ * SEQ)     // 16777216

// ---------------------------------------------------------------------------
// Scratch (__device__ globals). hi/lo planes: [2][...]
// ---------------------------------------------------------------------------
__device__ __nv_bfloat16 g_xq2[2 * NELEM];
__device__ __nv_bfloat16 g_xk2[2 * NELEM];
__device__ __nv_bfloat16 g_xv2[2 * NELEM];
__device__ __nv_bfloat16 g_W2[2L * EMB * EMB];
__device__ __nv_bfloat16 g_Q2[2 * NELEM];
__device__ __nv_bfloat16 g_K2[2 * NELEM];
__device__ __nv_bfloat16 g_V2[2 * NELEM];
__device__ __nv_bfloat16 g_VT2[2 * NELEM];   // [2][B][E][S]
__device__ __nv_bfloat16 g_P2[2 * NP];       // probs hi/lo
__device__ float         g_Pf[NP];           // fp32 scores

// ---------------------------------------------------------------------------
__device__ __forceinline__ uint32_t smem_u32(const void* p) {
    uint32_t a;
    asm("{ .reg .u64 t; cvta.to.shared.u64 t, %1; cvt.u32.u64 %0, t; }" : "=r"(a) : "l"(p));
    return a;
}

#define LDSM4(r, addr) \
    asm volatile("ldmatrix.sync.aligned.m8n8.x4.shared.b16 {%0,%1,%2,%3}, [%4];" \
        : "=r"((r)[0]), "=r"((r)[1]), "=r"((r)[2]), "=r"((r)[3]) : "r"(addr))

#define MMA_BF16(d, a, b0, b1) \
    asm volatile("mma.sync.aligned.m16n8k16.row.col.f32.bf16.bf16.f32 " \
        "{%0,%1,%2,%3}, {%4,%5,%6,%7}, {%8,%9}, {%0,%1,%2,%3};" \
        : "+f"((d)[0]), "+f"((d)[1]), "+f"((d)[2]), "+f"((d)[3]) \
        : "r"((a)[0]), "r"((a)[1]), "r"((a)[2]), "r"((a)[3]), "r"(b0), "r"(b1))

// per stage: A hi(10240) A lo(10240) B hi(10240) B lo(10240) = 40960
// row pitch 80B (32 bf16 + 8 pad) -> ldmatrix conflict-free
#define STAGE_B   40960
#define SMEM_REQ  (2 * STAGE_B)

// ---------------------------------------------------------------------------
// Split-bf16 tensor-core GEMM: C[128x128] = alpha * A @ B^T (+ bias)
// 128 threads, 4 warps, each warp computes 64x64.
// A: [2][rowsA][K] bf16 (hi plane then lo, planeA elems apart); B likewise.
// ---------------------------------------------------------------------------
template <bool CAUSAL, bool TRUNCK, bool BIAS, bool WF32, bool WBF16>
__global__ void __launch_bounds__(128, 2)
gemm_mma(const __nv_bfloat16* __restrict__ A, long strideAz, long planeA,
         const __nv_bfloat16* __restrict__ B, long strideBz, long planeB,
         int K, float alpha, const float* __restrict__ bias,
         float* __restrict__ Cf, __nv_bfloat16* __restrict__ Ch,
         __nv_bfloat16* __restrict__ Cl, int ldc, long strideCz)
{
    const int bx = blockIdx.x, by = blockIdx.y, bz = blockIdx.z;
    if (CAUSAL && bx > by) return;

    extern __shared__ char smem[];
    const uint32_t sbase = smem_u32(smem);

    const __nv_bfloat16* Ab = A + (long)bz * strideAz;
    const __nv_bfloat16* Bb = B + (long)bz * strideBz;

    const int tid = threadIdx.x, wid = tid >> 5, l = tid & 31;
    const int wr = wid >> 1, wc = wid & 1;     // warp 64m x 64n within 128x128
    const int kEnd = TRUNCK ? min(K, (by + 1) * 128) : K;
    const int nst = kEnd >> 5;                 // BK=32 stages
    const int rowA0 = by * 128, rowB0 = bx * 128;

    float acc[4][8][4];
#pragma unroll
    for (int m = 0; m < 4; m++)
#pragma unroll
        for (int n = 0; n < 8; n++)
#pragma unroll
            for (int j = 0; j < 4; j++) acc[m][n][j] = 0.f;

    // --- async stage loader: 2048 x 16B data chunks, 16 per thread ---
#define LOAD_STAGE(sidx, buf) do { \
        const int k0_ = (sidx) * 32; \
        const uint32_t st_ = sbase + (buf) * STAGE_B; \
        _Pragma("unroll") \
        for (int i_ = 0; i_ < 16; i_++) { \
            int c_ = i_ * 128 + tid; \
            int half_ = c_ >> 10; \
            int w_ = c_ & 1023; \
            int plane_ = w_ >> 9; \
            int row_ = (w_ & 511) >> 2; \
            int seg_ = w_ & 3; \
            uint32_t dst_ = st_ + half_ * 20480 + plane_ * 10240 + row_ * 80 + seg_ * 16; \
            const __nv_bfloat16* gp_ = half_ \
                ? (Bb + plane_ * planeB + (long)(rowB0 + row_) * K) \
                : (Ab + plane_ * planeA + (long)(rowA0 + row_) * K); \
            const void* src_ = gp_ + k0_ + seg_ * 8; \
            asm volatile("cp.async.cg.shared.global [%0], [%1], 16;" :: "r"(dst_), "l"(src_)); \
        } \
        asm volatile("cp.async.commit_group;"); \
    } while (0)

    LOAD_STAGE(0, 0);

    const int lr = l & 15, lh = l >> 4;

    for (int s = 0; s < nst; s++) {
        const int b = s & 1;
        if (s + 1 < nst) {
            LOAD_STAGE(s + 1, b ^ 1);
            asm volatile("cp.async.wait_group 1;");
        } else {
            asm volatile("cp.async.wait_group 0;");
        }
        __syncthreads();

        const uint32_t st = sbase + b * STAGE_B;
#pragma unroll
        for (int kk = 0; kk < 32; kk += 16) {
            uint32_t AH[4][4], AL[4][4], BH[4][4], BL[4][4];
            const uint32_t kb = (kk + lh * 8) * 2;
#pragma unroll
            for (int mt = 0; mt < 4; mt++) {
                uint32_t a0 = st + (wr * 64 + mt * 16 + lr) * 80 + kb;
                LDSM4(AH[mt], a0);
                LDSM4(AL[mt], a0 + 10240);
            }
#pragma unroll
            for (int np = 0; np < 4; np++) {
                uint32_t b0 = st + 20480 + (wc * 64 + np * 16 + lr) * 80 + kb;
                LDSM4(BH[np], b0);
                LDSM4(BL[np], b0 + 10240);
            }
#pragma unroll
            for (int mt = 0; mt < 4; mt++)
#pragma unroll
                for (int np = 0; np < 4; np++) {
                    MMA_BF16(acc[mt][2 * np],     AH[mt], BH[np][0], BH[np][2]);
                    MMA_BF16(acc[mt][2 * np + 1], AH[mt], BH[np][1], BH[np][3]);
                    MMA_BF16(acc[mt][2 * np],     AL[mt], BH[np][0], BH[np][2]);
                    MMA_BF16(acc[mt][2 * np + 1], AL[mt], BH[np][1], BH[np][3]);
                    MMA_BF16(acc[mt][2 * np],     AH[mt], BL[np][0], BL[np][2]);
                    MMA_BF16(acc[mt][2 * np + 1], AH[mt], BL[np][1], BL[np][3]);
                }
        }
        __syncthreads();
    }
#undef LOAD_STAGE

    // --- epilogue ---
    const int rql = l >> 2, cpl = (l & 3) * 2;
#pragma unroll
    for (int mt = 0; mt < 4; mt++) {
#pragma unroll
        for (int nt = 0; nt < 8; nt++) {
            const int col = bx * 128 + wc * 64 + nt * 8 + cpl;
            const long row = (long)by * 128 + wr * 64 + mt * 16 + rql;
            float v0 = acc[mt][nt][0] * alpha, v1 = acc[mt][nt][1] * alpha;
            float v2 = acc[mt][nt][2] * alpha, v3 = acc[mt][nt][3] * alpha;
            if (BIAS) {
                float b0 = bias[col], b1 = bias[col + 1];
                v0 += b0; v1 += b1; v2 += b0; v3 += b1;
            }
            const long o0 = (long)bz * strideCz + row * ldc + col;
            const long o1 = o0 + 8L * ldc;
            if (WF32) {
                *reinterpret_cast<float2*>(Cf + o0) = make_float2(v0, v1);
                *reinterpret_cast<float2*>(Cf + o1) = make_float2(v2, v3);
            }
            if (WBF16) {
                __nv_bfloat16 h0 = __float2bfloat16(v0), h1 = __float2bfloat16(v1);
                __nv_bfloat16 h2 = __float2bfloat16(v2), h3 = __float2bfloat16(v3);
                __nv_bfloat16 l0 = __float2bfloat16(v0 - __bfloat162float(h0));
                __nv_bfloat16 l1 = __float2bfloat16(v1 - __bfloat162float(h1));
                __nv_bfloat16 l2 = __float2bfloat16(v2 - __bfloat162float(h2));
                __nv_bfloat16 l3 = __float2bfloat16(v3 - __bfloat162float(h3));
                uint32_t hA = (uint32_t)__bfloat16_as_ushort(h0) | ((uint32_t)__bfloat16_as_ushort(h1) << 16);
                uint32_t hB = (uint32_t)__bfloat16_as_ushort(h2) | ((uint32_t)__bfloat16_as_ushort(h3) << 16);
                uint32_t lA = (uint32_t)__bfloat16_as_ushort(l0) | ((uint32_t)__bfloat16_as_ushort(l1) << 16);
                uint32_t lB = (uint32_t)__bfloat16_as_ushort(l2) | ((uint32_t)__bfloat16_as_ushort(l3) << 16);
                *reinterpret_cast<uint32_t*>(Ch + o0) = hA;
                *reinterpret_cast<uint32_t*>(Ch + o1) = hB;
                *reinterpret_cast<uint32_t*>(Cl + o0) = lA;
                *reinterpret_cast<uint32_t*>(Cl + o1) = lB;
            }
        }
    }
}

// ---------------------------------------------------------------------------
// fp32 -> bf16 hi/lo split
// ---------------------------------------------------------------------------
__global__ void __launch_bounds__(256) split4(const float* __restrict__ in,
                                              __nv_bfloat16* __restrict__ out, long n)
{
    long i = ((long)blockIdx.x * 256 + threadIdx.x) * 4;
    if (i >= n) return;
    float4 v = *reinterpret_cast<const float4*>(in + i);
    __nv_bfloat16 h0 = __float2bfloat16(v.x), h1 = __float2bfloat16(v.y);
    __nv_bfloat16 h2 = __float2bfloat16(v.z), h3 = __float2bfloat16(v.w);
    __nv_bfloat16 l0 = __float2bfloat16(v.x - __bfloat162float(h0));
    __nv_bfloat16 l1 = __float2bfloat16(v.y - __bfloat162float(h1));
    __nv_bfloat16 l2 = __float2bfloat16(v.z - __bfloat162float(h2));
    __nv_bfloat16 l3 = __float2bfloat16(v.w - __bfloat162float(h3));
    uint32_t hA = (uint32_t)__bfloat16_as_ushort(h0) | ((uint32_t)__bfloat16_as_ushort(h1) << 16);
    uint32_t hB = (uint32_t)__bfloat16_as_ushort(h2) | ((uint32_t)__bfloat16_as_ushort(h3) << 16);
    uint32_t lA = (uint32_t)__bfloat16_as_ushort(l0) | ((uint32_t)__bfloat16_as_ushort(l1) << 16);
    uint32_t lB = (uint32_t)__bfloat16_as_ushort(l2) | ((uint32_t)__bfloat16_as_ushort(l3) << 16);
    *reinterpret_cast<uint2*>(out + i) = make_uint2(hA, hB);
    *reinterpret_cast<uint2*>(out + n + i) = make_uint2(lA, lB);
}

// ---------------------------------------------------------------------------
// bf16 transpose: [2][B][S][E] -> [2][B][E][S]
// ---------------------------------------------------------------------------
__global__ void __launch_bounds__(256) transpose_bf16(const __nv_bfloat16* __restrict__ in,
                                                      __nv_bfloat16* __restrict__ out)
{
    __shared__ unsigned short t[32][33];
    const int plane = blockIdx.z / BATCH, b = blockIdx.z % BATCH;
    const long off = ((long)plane * BATCH + b) * (long)SEQ * EMB;
    const unsigned short* ip = reinterpret_cast<const unsigned short*>(in) + off;
    unsigned short* op = reinterpret_cast<unsigned short*>(out) + off;
    const int c0 = blockIdx.x * 32, r0 = blockIdx.y * 32;
    for (int i = threadIdx.y; i < 32; i += 8)
        t[i][threadIdx.x] = ip[(long)(r0 + i) * EMB + c0 + threadIdx.x];
    __syncthreads();
    for (int i = threadIdx.y; i < 32; i += 8)
        op[(long)(c0 + i) * SEQ + r0 + threadIdx.x] = t[threadIdx.x][i];
}

// ---------------------------------------------------------------------------
// Causal row softmax: fp32 scores -> bf16 hi/lo probs (zero tail)
// ---------------------------------------------------------------------------
__global__ void __launch_bounds__(256)
softmax_causal(float* __restrict__ P, __nv_bfloat16* __restrict__ Ph,
               __nv_bfloat16* __restrict__ Pl)
{
    const int row = blockIdx.x;
    const int q = row & (SEQ - 1);
    float* p = P + (long)row * SEQ;
    __nv_bfloat16* ph = Ph + (long)row * SEQ;
    __nv_bfloat16* pl = Pl + (long)row * SEQ;
    const int n = q + 1;
    const int tid = threadIdx.x;

    __shared__ float red[8];

    float m = -3.4e38f;
    for (int i = tid; i < n; i += 256) m = fmaxf(m, p[i]);
#pragma unroll
    for (int o = 16; o > 0; o >>= 1) m = fmaxf(m, __shfl_xor_sync(0xffffffffu, m, o));
    if ((tid & 31) == 0) red[tid >> 5] = m;
    __syncthreads();
    m = red[0];
#pragma unroll
    for (int w = 1; w < 8; w++) m = fmaxf(m, red[w]);
    __syncthreads();

    float s = 0.f;
    for (int i = tid; i < n; i += 256) {
        float e = __expf(p[i] - m);
        p[i] = e;
        s += e;
    }
#pragma unroll
    for (int o = 16; o > 0; o >>= 1) s += __shfl_xor_sync(0xffffffffu, s, o);
    if ((tid & 31) == 0) red[tid >> 5] = s;
    __syncthreads();
    float tot = red[0];
#pragma unroll
    for (int w = 1; w < 8; w++) tot += red[w];
    const float inv = 1.f / tot;

    for (int i = tid; i < n; i += 256) {
        float pr = p[i] * inv;
        __nv_bfloat16 h = __float2bfloat16(pr);
        __nv_bfloat16 lo = __float2bfloat16(pr - __bfloat162float(h));
        ph[i] = h;
        pl[i] = lo;
    }
    const __nv_bfloat16 z = __float2bfloat16(0.f);
    for (int i = n + tid; i < SEQ; i += 256) { ph[i] = z; pl[i] = z; }
}

// ---------------------------------------------------------------------------
extern "C" void kernel_launch(void* const* d_in, const int* in_sizes, int n_in,
                              void* d_out, int out_size)
{
    (void)in_sizes; (void)n_in; (void)out_size;
    const float* xq = (const float*)d_in[0];
    const float* xk = (const float*)d_in[1];
    const float* xv = (const float*)d_in[2];
    const float* Wq = (const float*)d_in[3];
    const float* bq = (const float*)d_in[4];
    float* out = (float*)d_out;

    void *xq2, *xk2, *xv2, *W2, *Q2, *K2, *V2, *VT2, *P2, *Pf;
    cudaGetSymbolAddress(&xq2, g_xq2);
    cudaGetSymbolAddress(&xk2, g_xk2);
    cudaGetSymbolAddress(&xv2, g_xv2);
    cudaGetSymbolAddress(&W2, g_W2);
    cudaGetSymbolAddress(&Q2, g_Q2);
    cudaGetSymbolAddress(&K2, g_K2);
    cudaGetSymbolAddress(&V2, g_V2);
    cudaGetSymbolAddress(&VT2, g_VT2);
    cudaGetSymbolAddress(&P2, g_P2);
    cudaGetSymbolAddress(&Pf, g_Pf);

    auto kProj = gemm_mma<false, false, true, false, true>;
    auto kQK   = gemm_mma<true,  false, false, true, false>;
    auto kPV   = gemm_mma<false, true,  false, true, false>;
    cudaFuncSetAttribute(kProj, cudaFuncAttributeMaxDynamicSharedMemorySize, SMEM_REQ);
    cudaFuncSetAttribute(kQK,   cudaFuncAttributeMaxDynamicSharedMemorySize, SMEM_REQ);
    cudaFuncSetAttribute(kPV,   cudaFuncAttributeMaxDynamicSharedMemorySize, SMEM_REQ);

    // 1) split inputs to bf16 hi/lo
    split4<<<(unsigned)((NELEM / 4 + 255) / 256), 256>>>(xq, (__nv_bfloat16*)xq2, NELEM);
    split4<<<(unsigned)((NELEM / 4 + 255) / 256), 256>>>(xk, (__nv_bfloat16*)xk2, NELEM);
    split4<<<(unsigned)((NELEM / 4 + 255) / 256), 256>>>(xv, (__nv_bfloat16*)xv2, NELEM);
    split4<<<(unsigned)(((long)EMB * EMB / 4 + 255) / 256), 256>>>(Wq, (__nv_bfloat16*)W2, (long)EMB * EMB);

    // 2) projections: Q/K/V = x @ W^T + b -> bf16 hi/lo
    {
        dim3 g(EMB / 128, MTOT / 128, 1);
        kProj<<<g, 128, SMEM_REQ>>>((const __nv_bfloat16*)xq2, 0, NELEM,
                                    (const __nv_bfloat16*)W2, 0, (long)EMB * EMB,
                                    EMB, 1.0f, bq, nullptr,
                                    (__nv_bfloat16*)Q2, (__nv_bfloat16*)Q2 + NELEM, EMB, 0);
        kProj<<<g, 128, SMEM_REQ>>>((const __nv_bfloat16*)xk2, 0, NELEM,
                                    (const __nv_bfloat16*)W2, 0, (long)EMB * EMB,
                                    EMB, 1.0f, bq, nullptr,
                                    (__nv_bfloat16*)K2, (__nv_bfloat16*)K2 + NELEM, EMB, 0);
        kProj<<<g, 128, SMEM_REQ>>>((const __nv_bfloat16*)xv2, 0, NELEM,
                                    (const __nv_bfloat16*)W2, 0, (long)EMB * EMB,
                                    EMB, 1.0f, bq, nullptr,
                                    (__nv_bfloat16*)V2, (__nv_bfloat16*)V2 + NELEM, EMB, 0);
    }

    // 3) V transpose -> [2][B][E][S]
    transpose_bf16<<<dim3(EMB / 32, SEQ / 32, 2 * BATCH), dim3(32, 8)>>>(
        (const __nv_bfloat16*)V2, (__nv_bfloat16*)VT2);

    // 4) scores = scale * Q @ K^T (causal tile skip) -> fp32
    {
        dim3 g(SEQ / 128, SEQ / 128, BATCH);
        kQK<<<g, 128, SMEM_REQ>>>((const __nv_bfloat16*)Q2, (long)SEQ * EMB, NELEM,
                                  (const __nv_bfloat16*)K2, (long)SEQ * EMB, NELEM,
                                  EMB, 0.03125f, nullptr,
                                  (float*)Pf, nullptr, nullptr, SEQ, (long)SEQ * SEQ);
    }

    // 5) softmax -> bf16 hi/lo probs
    softmax_causal<<<MTOT, 256>>>((float*)Pf, (__nv_bfloat16*)P2,
                                  (__nv_bfloat16*)P2 + NP);

    // 6) out = P @ VT^T (K-truncated at diagonal) -> fp32
    {
        dim3 g(EMB / 128, SEQ / 128, BATCH);
        kPV<<<g, 128, SMEM_REQ>>>((const __nv_bfloat16*)P2, (long)SEQ * SEQ, NP,
                                  (const __nv_bfloat16*)VT2, (long)SEQ * EMB, NELEM,
                                  SEQ, 1.0f, nullptr,
                                  out, nullptr, nullptr, EMB, (long)SEQ * EMB);
    }
}

// round 5
// speedup vs baseline: 2.5106x; 1.0264x over previous
#include <cuda_runtime.h>
#include <cuda_bf16.h>
#include <cstdint>

#define BATCH 4
#define SEQ   2048
#define EMB   1024
#define MTOT  (BATCH * SEQ)                 // 8192
#define NELEM ((long)MTOT * EMB)            // 8388608
#define NP    ((long)BATCH * SEQ * SEQ)     // 16777216

// ---------------------------------------------------------------------------
// Scratch (__device__ globals). hi/lo planes: [2][...]
// ---------------------------------------------------------------------------
__device__ __nv_bfloat16 g_xq2[2 * NELEM];
__device__ __nv_bfloat16 g_xk2[2 * NELEM];
__device__ __nv_bfloat16 g_xv2[2 * NELEM];
__device__ __nv_bfloat16 g_W2[2L * EMB * EMB];
__device__ __nv_bfloat16 g_Q2[2 * NELEM];
__device__ __nv_bfloat16 g_K2[2 * NELEM];
__device__ __nv_bfloat16 g_V2[2 * NELEM];
__device__ __nv_bfloat16 g_VT2[2 * NELEM];   // [2][B][E][S]
__device__ __nv_bfloat16 g_P2[2 * NP];       // probs hi/lo
__device__ float         g_Pf[NP];           // fp32 scores

// ---------------------------------------------------------------------------
__device__ __forceinline__ uint32_t smem_u32(const void* p) {
    uint32_t a;
    asm("{ .reg .u64 t; cvta.to.shared.u64 t, %1; cvt.u32.u64 %0, t; }" : "=r"(a) : "l"(p));
    return a;
}

#define LDSM4(r, addr) \
    asm volatile("ldmatrix.sync.aligned.m8n8.x4.shared.b16 {%0,%1,%2,%3}, [%4];" \
        : "=r"((r)[0]), "=r"((r)[1]), "=r"((r)[2]), "=r"((r)[3]) : "r"(addr))

#define MMA_BF16(d, a, b0, b1) \
    asm volatile("mma.sync.aligned.m16n8k16.row.col.f32.bf16.bf16.f32 " \
        "{%0,%1,%2,%3}, {%4,%5,%6,%7}, {%8,%9}, {%0,%1,%2,%3};" \
        : "+f"((d)[0]), "+f"((d)[1]), "+f"((d)[2]), "+f"((d)[3]) \
        : "r"((a)[0]), "r"((a)[1]), "r"((a)[2]), "r"((a)[3]), "r"(b0), "r"(b1))

// per stage: A hi(10240) A lo(10240) B hi(10240) B lo(10240) = 40960
// row pitch 80B (32 bf16 + 8 pad) -> ldmatrix conflict-free
#define STAGE_B   40960
#define SMEM_REQ  (2 * STAGE_B)

// ---------------------------------------------------------------------------
// Split-bf16 tensor-core GEMM: C[128x128] = alpha * A @ B^T (+ bias)
// 128 threads, 4 warps, each warp computes 64x64.
// A: [2][rowsA][K] bf16 (hi plane then lo, planeA elems apart); B likewise.
// ---------------------------------------------------------------------------
template <bool CAUSAL, bool TRUNCK, bool BIAS, bool WF32, bool WBF16>
__global__ void __launch_bounds__(128, 2)
gemm_mma(const __nv_bfloat16* __restrict__ A, long strideAz, long planeA,
         const __nv_bfloat16* __restrict__ B, long strideBz, long planeB,
         int K, float alpha, const float* __restrict__ bias,
         float* __restrict__ Cf, __nv_bfloat16* __restrict__ Ch,
         __nv_bfloat16* __restrict__ Cl, int ldc, long strideCz)
{
    const int bx = blockIdx.x, bz = blockIdx.z;
    // TRUNCK (PV): longest K first -> better wave balance
    const int by = TRUNCK ? (gridDim.y - 1 - blockIdx.y) : blockIdx.y;
    if (CAUSAL && bx > by) return;

    extern __shared__ char smem[];
    const uint32_t sbase = smem_u32(smem);

    const __nv_bfloat16* Ab = A + (long)bz * strideAz;
    const __nv_bfloat16* Bb = B + (long)bz * strideBz;

    const int tid = threadIdx.x, wid = tid >> 5, l = tid & 31;
    const int wr = wid >> 1, wc = wid & 1;     // warp 64m x 64n within 128x128
    const int kEnd = TRUNCK ? min(K, (by + 1) * 128) : K;
    const int nst = kEnd >> 5;                 // BK=32 stages
    const int rowA0 = by * 128, rowB0 = bx * 128;

    float acc[4][8][4];
#pragma unroll
    for (int m = 0; m < 4; m++)
#pragma unroll
        for (int n = 0; n < 8; n++)
#pragma unroll
            for (int j = 0; j < 4; j++) acc[m][n][j] = 0.f;

    // --- async stage loader: 2048 x 16B data chunks, 16 per thread ---
#define LOAD_STAGE(sidx, buf) do { \
        const int k0_ = (sidx) * 32; \
        const uint32_t st_ = sbase + (buf) * STAGE_B; \
        _Pragma("unroll") \
        for (int i_ = 0; i_ < 16; i_++) { \
            int c_ = i_ * 128 + tid; \
            int half_ = c_ >> 10; \
            int w_ = c_ & 1023; \
            int plane_ = w_ >> 9; \
            int row_ = (w_ & 511) >> 2; \
            int seg_ = w_ & 3; \
            uint32_t dst_ = st_ + half_ * 20480 + plane_ * 10240 + row_ * 80 + seg_ * 16; \
            const __nv_bfloat16* gp_ = half_ \
                ? (Bb + plane_ * planeB + (long)(rowB0 + row_) * K) \
                : (Ab + plane_ * planeA + (long)(rowA0 + row_) * K); \
            const void* src_ = gp_ + k0_ + seg_ * 8; \
            asm volatile("cp.async.cg.shared.global [%0], [%1], 16;" :: "r"(dst_), "l"(src_)); \
        } \
        asm volatile("cp.async.commit_group;"); \
    } while (0)

    LOAD_STAGE(0, 0);

    const int lr = l & 15, lh = l >> 4;

    for (int s = 0; s < nst; s++) {
        const int b = s & 1;
        // publish stage s (own cp.asyncs done) + prove everyone left buffer b^1
        asm volatile("cp.async.wait_group 0;");
        __syncthreads();
        if (s + 1 < nst) LOAD_STAGE(s + 1, b ^ 1);   // overlaps with compute below

        const uint32_t st = sbase + b * STAGE_B;
#pragma unroll
        for (int kk = 0; kk < 32; kk += 16) {
            uint32_t AH[4][4], AL[4][4], BH[4][4], BL[4][4];
            const uint32_t kb = (kk + lh * 8) * 2;
#pragma unroll
            for (int mt = 0; mt < 4; mt++) {
                uint32_t a0 = st + (wr * 64 + mt * 16 + lr) * 80 + kb;
                LDSM4(AH[mt], a0);
                LDSM4(AL[mt], a0 + 10240);
            }
#pragma unroll
            for (int np = 0; np < 4; np++) {
                uint32_t b0 = st + 20480 + (wc * 64 + np * 16 + lr) * 80 + kb;
                LDSM4(BH[np], b0);
                LDSM4(BL[np], b0 + 10240);
            }
            // term-major: same-acc MMAs are 32 issues apart (no RAW chains)
#pragma unroll
            for (int mt = 0; mt < 4; mt++)
#pragma unroll
                for (int np = 0; np < 4; np++) {
                    MMA_BF16(acc[mt][2 * np],     AH[mt], BH[np][0], BH[np][2]);
                    MMA_BF16(acc[mt][2 * np + 1], AH[mt], BH[np][1], BH[np][3]);
                }
#pragma unroll
            for (int mt = 0; mt < 4; mt++)
#pragma unroll
                for (int np = 0; np < 4; np++) {
                    MMA_BF16(acc[mt][2 * np],     AL[mt], BH[np][0], BH[np][2]);
                    MMA_BF16(acc[mt][2 * np + 1], AL[mt], BH[np][1], BH[np][3]);
                }
#pragma unroll
            for (int mt = 0; mt < 4; mt++)
#pragma unroll
                for (int np = 0; np < 4; np++) {
                    MMA_BF16(acc[mt][2 * np],     AH[mt], BL[np][0], BL[np][2]);
                    MMA_BF16(acc[mt][2 * np + 1], AH[mt], BL[np][1], BL[np][3]);
                }
        }
    }
#undef LOAD_STAGE

    // --- epilogue ---
    const int rql = l >> 2, cpl = (l & 3) * 2;
#pragma unroll
    for (int mt = 0; mt < 4; mt++) {
#pragma unroll
        for (int nt = 0; nt < 8; nt++) {
            const int col = bx * 128 + wc * 64 + nt * 8 + cpl;
            const long row = (long)by * 128 + wr * 64 + mt * 16 + rql;
            float v0 = acc[mt][nt][0] * alpha, v1 = acc[mt][nt][1] * alpha;
            float v2 = acc[mt][nt][2] * alpha, v3 = acc[mt][nt][3] * alpha;
            if (BIAS) {
                float b0 = bias[col], b1 = bias[col + 1];
                v0 += b0; v1 += b1; v2 += b0; v3 += b1;
            }
            const long o0 = (long)bz * strideCz + row * ldc + col;
            const long o1 = o0 + 8L * ldc;
            if (WF32) {
                *reinterpret_cast<float2*>(Cf + o0) = make_float2(v0, v1);
                *reinterpret_cast<float2*>(Cf + o1) = make_float2(v2, v3);
            }
            if (WBF16) {
                __nv_bfloat16 h0 = __float2bfloat16(v0), h1 = __float2bfloat16(v1);
                __nv_bfloat16 h2 = __float2bfloat16(v2), h3 = __float2bfloat16(v3);
                __nv_bfloat16 l0 = __float2bfloat16(v0 - __bfloat162float(h0));
                __nv_bfloat16 l1 = __float2bfloat16(v1 - __bfloat162float(h1));
                __nv_bfloat16 l2 = __float2bfloat16(v2 - __bfloat162float(h2));
                __nv_bfloat16 l3 = __float2bfloat16(v3 - __bfloat162float(h3));
                uint32_t hA = (uint32_t)__bfloat16_as_ushort(h0) | ((uint32_t)__bfloat16_as_ushort(h1) << 16);
                uint32_t hB = (uint32_t)__bfloat16_as_ushort(h2) | ((uint32_t)__bfloat16_as_ushort(h3) << 16);
                uint32_t lA = (uint32_t)__bfloat16_as_ushort(l0) | ((uint32_t)__bfloat16_as_ushort(l1) << 16);
                uint32_t lB = (uint32_t)__bfloat16_as_ushort(l2) | ((uint32_t)__bfloat16_as_ushort(l3) << 16);
                *reinterpret_cast<uint32_t*>(Ch + o0) = hA;
                *reinterpret_cast<uint32_t*>(Ch + o1) = hB;
                *reinterpret_cast<uint32_t*>(Cl + o0) = lA;
                *reinterpret_cast<uint32_t*>(Cl + o1) = lB;
            }
        }
    }
}

// ---------------------------------------------------------------------------
// fp32 -> bf16 hi/lo split; y-dim selects among up to 3 arrays
// ---------------------------------------------------------------------------
__global__ void __launch_bounds__(256) split4x3(const float* __restrict__ i0,
                                                const float* __restrict__ i1,
                                                const float* __restrict__ i2,
                                                __nv_bfloat16* __restrict__ o0,
                                                __nv_bfloat16* __restrict__ o1,
                                                __nv_bfloat16* __restrict__ o2,
                                                long n)
{
    const float* in = (blockIdx.y == 0) ? i0 : (blockIdx.y == 1) ? i1 : i2;
    __nv_bfloat16* out = (blockIdx.y == 0) ? o0 : (blockIdx.y == 1) ? o1 : o2;
    long i = ((long)blockIdx.x * 256 + threadIdx.x) * 4;
    if (i >= n) return;
    float4 v = *reinterpret_cast<const float4*>(in + i);
    __nv_bfloat16 h0 = __float2bfloat16(v.x), h1 = __float2bfloat16(v.y);
    __nv_bfloat16 h2 = __float2bfloat16(v.z), h3 = __float2bfloat16(v.w);
    __nv_bfloat16 l0 = __float2bfloat16(v.x - __bfloat162float(h0));
    __nv_bfloat16 l1 = __float2bfloat16(v.y - __bfloat162float(h1));
    __nv_bfloat16 l2 = __float2bfloat16(v.z - __bfloat162float(h2));
    __nv_bfloat16 l3 = __float2bfloat16(v.w - __bfloat162float(h3));
    uint32_t hA = (uint32_t)__bfloat16_as_ushort(h0) | ((uint32_t)__bfloat16_as_ushort(h1) << 16);
    uint32_t hB = (uint32_t)__bfloat16_as_ushort(h2) | ((uint32_t)__bfloat16_as_ushort(h3) << 16);
    uint32_t lA = (uint32_t)__bfloat16_as_ushort(l0) | ((uint32_t)__bfloat16_as_ushort(l1) << 16);
    uint32_t lB = (uint32_t)__bfloat16_as_ushort(l2) | ((uint32_t)__bfloat16_as_ushort(l3) << 16);
    *reinterpret_cast<uint2*>(out + i) = make_uint2(hA, hB);
    *reinterpret_cast<uint2*>(out + n + i) = make_uint2(lA, lB);
}

// ---------------------------------------------------------------------------
// bf16 transpose: [2][B][S][E] -> [2][B][E][S]
// ---------------------------------------------------------------------------
__global__ void __launch_bounds__(256) transpose_bf16(const __nv_bfloat16* __restrict__ in,
                                                      __nv_bfloat16* __restrict__ out)
{
    __shared__ unsigned short t[32][33];
    const int plane = blockIdx.z / BATCH, b = blockIdx.z % BATCH;
    const long off = ((long)plane * BATCH + b) * (long)SEQ * EMB;
    const unsigned short* ip = reinterpret_cast<const unsigned short*>(in) + off;
    unsigned short* op = reinterpret_cast<unsigned short*>(out) + off;
    const int c0 = blockIdx.x * 32, r0 = blockIdx.y * 32;
    for (int i = threadIdx.y; i < 32; i += 8)
        t[i][threadIdx.x] = ip[(long)(r0 + i) * EMB + c0 + threadIdx.x];
    __syncthreads();
    for (int i = threadIdx.y; i < 32; i += 8)
        op[(long)(c0 + i) * SEQ + r0 + threadIdx.x] = t[threadIdx.x][i];
}

// ---------------------------------------------------------------------------
// Causal row softmax: fp32 scores -> bf16 hi/lo probs (zero tail)
// ---------------------------------------------------------------------------
__global__ void __launch_bounds__(256)
softmax_causal(float* __restrict__ P, __nv_bfloat16* __restrict__ Ph,
               __nv_bfloat16* __restrict__ Pl)
{
    const int row = blockIdx.x;
    const int q = row & (SEQ - 1);
    float* p = P + (long)row * SEQ;
    __nv_bfloat16* ph = Ph + (long)row * SEQ;
    __nv_bfloat16* pl = Pl + (long)row * SEQ;
    const int n = q + 1;
    const int tid = threadIdx.x;

    __shared__ float red[8];

    float m = -3.4e38f;
    for (int i = tid; i < n; i += 256) m = fmaxf(m, p[i]);
#pragma unroll
    for (int o = 16; o > 0; o >>= 1) m = fmaxf(m, __shfl_xor_sync(0xffffffffu, m, o));
    if ((tid & 31) == 0) red[tid >> 5] = m;
    __syncthreads();
    m = red[0];
#pragma unroll
    for (int w = 1; w < 8; w++) m = fmaxf(m, red[w]);
    __syncthreads();

    float s = 0.f;
    for (int i = tid; i < n; i += 256) {
        float e = __expf(p[i] - m);
        p[i] = e;
        s += e;
    }
#pragma unroll
    for (int o = 16; o > 0; o >>= 1) s += __shfl_xor_sync(0xffffffffu, s, o);
    if ((tid & 31) == 0) red[tid >> 5] = s;
    __syncthreads();
    float tot = red[0];
#pragma unroll
    for (int w = 1; w < 8; w++) tot += red[w];
    const float inv = 1.f / tot;

    for (int i = tid; i < n; i += 256) {
        float pr = p[i] * inv;
        __nv_bfloat16 h = __float2bfloat16(pr);
        __nv_bfloat16 lo = __float2bfloat16(pr - __bfloat162float(h));
        ph[i] = h;
        pl[i] = lo;
    }
    const __nv_bfloat16 z = __float2bfloat16(0.f);
    for (int i = n + tid; i < SEQ; i += 256) { ph[i] = z; pl[i] = z; }
}

// ---------------------------------------------------------------------------
extern "C" void kernel_launch(void* const* d_in, const int* in_sizes, int n_in,
                              void* d_out, int out_size)
{
    (void)in_sizes; (void)n_in; (void)out_size;
    const float* xq = (const float*)d_in[0];
    const float* xk = (const float*)d_in[1];
    const float* xv = (const float*)d_in[2];
    const float* Wq = (const float*)d_in[3];
    const float* bq = (const float*)d_in[4];
    float* out = (float*)d_out;

    void *xq2, *xk2, *xv2, *W2, *Q2, *K2, *V2, *VT2, *P2, *Pf;
    cudaGetSymbolAddress(&xq2, g_xq2);
    cudaGetSymbolAddress(&xk2, g_xk2);
    cudaGetSymbolAddress(&xv2, g_xv2);
    cudaGetSymbolAddress(&W2, g_W2);
    cudaGetSymbolAddress(&Q2, g_Q2);
    cudaGetSymbolAddress(&K2, g_K2);
    cudaGetSymbolAddress(&V2, g_V2);
    cudaGetSymbolAddress(&VT2, g_VT2);
    cudaGetSymbolAddress(&P2, g_P2);
    cudaGetSymbolAddress(&Pf, g_Pf);

    auto kProj = gemm_mma<false, false, true, false, true>;
    auto kQK   = gemm_mma<true,  false, false, true, false>;
    auto kPV   = gemm_mma<false, true,  false, true, false>;
    cudaFuncSetAttribute(kProj, cudaFuncAttributeMaxDynamicSharedMemorySize, SMEM_REQ);
    cudaFuncSetAttribute(kQK,   cudaFuncAttributeMaxDynamicSharedMemorySize, SMEM_REQ);
    cudaFuncSetAttribute(kPV,   cudaFuncAttributeMaxDynamicSharedMemorySize, SMEM_REQ);

    // 1) split inputs to bf16 hi/lo (one launch for xq/xk/xv, one for W)
    split4x3<<<dim3((unsigned)(NELEM / 4 / 256), 3), 256>>>(
        xq, xk, xv, (__nv_bfloat16*)xq2, (__nv_bfloat16*)xk2, (__nv_bfloat16*)xv2, NELEM);
    split4x3<<<dim3((unsigned)((long)EMB * EMB / 4 / 256), 1), 256>>>(
        Wq, nullptr, nullptr, (__nv_bfloat16*)W2, nullptr, nullptr, (long)EMB * EMB);

    // 2) projections: Q/K/V = x @ W^T + b -> bf16 hi/lo
    {
        dim3 g(EMB / 128, MTOT / 128, 1);
        kProj<<<g, 128, SMEM_REQ>>>((const __nv_bfloat16*)xq2, 0, NELEM,
                                    (const __nv_bfloat16*)W2, 0, (long)EMB * EMB,
                                    EMB, 1.0f, bq, nullptr,
                                    (__nv_bfloat16*)Q2, (__nv_bfloat16*)Q2 + NELEM, EMB, 0);
        kProj<<<g, 128, SMEM_REQ>>>((const __nv_bfloat16*)xk2, 0, NELEM,
                                    (const __nv_bfloat16*)W2, 0, (long)EMB * EMB,
                                    EMB, 1.0f, bq, nullptr,
                                    (__nv_bfloat16*)K2, (__nv_bfloat16*)K2 + NELEM, EMB, 0);
        kProj<<<g, 128, SMEM_REQ>>>((const __nv_bfloat16*)xv2, 0, NELEM,
                                    (const __nv_bfloat16*)W2, 0, (long)EMB * EMB,
                                    EMB, 1.0f, bq, nullptr,
                                    (__nv_bfloat16*)V2, (__nv_bfloat16*)V2 + NELEM, EMB, 0);
    }

    // 3) V transpose -> [2][B][E][S]
    transpose_bf16<<<dim3(EMB / 32, SEQ / 32, 2 * BATCH), dim3(32, 8)>>>(
        (const __nv_bfloat16*)V2, (__nv_bfloat16*)VT2);

    // 4) scores = scale * Q @ K^T (causal tile skip) -> fp32
    {
        dim3 g(SEQ / 128, SEQ / 128, BATCH);
        kQK<<<g, 128, SMEM_REQ>>>((const __nv_bfloat16*)Q2, (long)SEQ * EMB, NELEM,
                                  (const __nv_bfloat16*)K2, (long)SEQ * EMB, NELEM,
                                  EMB, 0.03125f, nullptr,
                                  (float*)Pf, nullptr, nullptr, SEQ, (long)SEQ * SEQ);
    }

    // 5) softmax -> bf16 hi/lo probs
    softmax_causal<<<MTOT, 256>>>((float*)Pf, (__nv_bfloat16*)P2,
                                  (__nv_bfloat16*)P2 + NP);

    // 6) out = P @ VT^T (K-truncated at diagonal, longest-first) -> fp32
    {
        dim3 g(EMB / 128, SEQ / 128, BATCH);
        kPV<<<g, 128, SMEM_REQ>>>((const __nv_bfloat16*)P2, (long)SEQ * SEQ, NP,
                                  (const __nv_bfloat16*)VT2, (long)SEQ * EMB, NELEM,
                                  SEQ, 1.0f, nullptr,
                                  out, nullptr, nullptr, EMB, (long)SEQ * EMB);
    }
}

// round 6
// speedup vs baseline: 2.5449x; 1.0137x over previous
#include <cuda_runtime.h>
#include <cuda_bf16.h>
#include <cstdint>

#define BATCH 4
#define SEQ   2048
#define EMB   1024
#define MTOT  (BATCH * SEQ)                 // 8192
#define NELEM ((long)MTOT * EMB)            // 8388608
#define NP    ((long)BATCH * SEQ * SEQ)     // 16777216

// ---------------------------------------------------------------------------
// Scratch (__device__ globals). hi/lo planes: [2][...]
// ---------------------------------------------------------------------------
__device__ __nv_bfloat16 g_xq2[2 * NELEM];
__device__ __nv_bfloat16 g_xk2[2 * NELEM];
__device__ __nv_bfloat16 g_xv2[2 * NELEM];
__device__ __nv_bfloat16 g_W2[2L * EMB * EMB];
__device__ __nv_bfloat16 g_Q2[2 * NELEM];
__device__ __nv_bfloat16 g_K2[2 * NELEM];
__device__ __nv_bfloat16 g_V2[2 * NELEM];
__device__ __nv_bfloat16 g_VT2[2 * NELEM];   // [2][B][E][S]
__device__ __nv_bfloat16 g_P2[2 * NP];       // probs hi/lo
__device__ float         g_Pf[NP];           // fp32 scores

// ---------------------------------------------------------------------------
__device__ __forceinline__ uint32_t smem_u32(const void* p) {
    uint32_t a;
    asm("{ .reg .u64 t; cvta.to.shared.u64 t, %1; cvt.u32.u64 %0, t; }" : "=r"(a) : "l"(p));
    return a;
}

#define LDSM4(r, addr) \
    asm volatile("ldmatrix.sync.aligned.m8n8.x4.shared.b16 {%0,%1,%2,%3}, [%4];" \
        : "=r"((r)[0]), "=r"((r)[1]), "=r"((r)[2]), "=r"((r)[3]) : "r"(addr))

#define MMA_BF16(d, a, b0, b1) \
    asm volatile("mma.sync.aligned.m16n8k16.row.col.f32.bf16.bf16.f32 " \
        "{%0,%1,%2,%3}, {%4,%5,%6,%7}, {%8,%9}, {%0,%1,%2,%3};" \
        : "+f"((d)[0]), "+f"((d)[1]), "+f"((d)[2]), "+f"((d)[3]) \
        : "r"((a)[0]), "r"((a)[1]), "r"((a)[2]), "r"((a)[3]), "r"(b0), "r"(b1))

// CTA tile 128x64, BK=32. Per stage: A hi/lo 2x10240, B hi/lo 2x5120 = 30720.
// row pitch 80B (32 bf16 + 8 pad) -> ldmatrix conflict-free
#define STAGE_B   30720
#define SMEM_REQ  (2 * STAGE_B)

// ---------------------------------------------------------------------------
// Split-bf16 tensor-core GEMM: C[128x64] tile = alpha * A @ B^T (+ bias)
// 128 threads, 4 warps (2m x 2n), warp tile 64x32. 3 CTAs/SM.
// A: [2][rowsA][K] bf16 (hi plane then lo, planeA elems apart); B likewise.
// ---------------------------------------------------------------------------
template <bool CAUSAL, bool TRUNCK, bool BIAS, bool WF32, bool WBF16>
__global__ void __launch_bounds__(128, 3)
gemm_mma(const __nv_bfloat16* __restrict__ A, long strideAz, long planeA,
         const __nv_bfloat16* __restrict__ B, long strideBz, long planeB,
         int K, float alpha, const float* __restrict__ bias,
         float* __restrict__ Cf, __nv_bfloat16* __restrict__ Ch,
         __nv_bfloat16* __restrict__ Cl, int ldc, long strideCz)
{
    const int bx = blockIdx.x, bz = blockIdx.z;
    // TRUNCK (PV): longest K first -> better wave balance
    const int by = TRUNCK ? (gridDim.y - 1 - blockIdx.y) : blockIdx.y;
    if (CAUSAL && bx > 2 * by + 1) return;   // 64-wide col tile vs 128-high row tile

    extern __shared__ char smem[];
    const uint32_t sbase = smem_u32(smem);

    const __nv_bfloat16* Ab = A + (long)bz * strideAz;
    const __nv_bfloat16* Bb = B + (long)bz * strideBz;

    const int tid = threadIdx.x, wid = tid >> 5, l = tid & 31;
    const int wr = wid >> 1, wc = wid & 1;     // warp 64m x 32n within 128x64
    const int kEnd = TRUNCK ? min(K, (by + 1) * 128) : K;
    const int nst = kEnd >> 5;                 // BK=32 stages
    const int rowA0 = by * 128, rowB0 = bx * 64;

    float acc[4][4][4];
#pragma unroll
    for (int m = 0; m < 4; m++)
#pragma unroll
        for (int n = 0; n < 4; n++)
#pragma unroll
            for (int j = 0; j < 4; j++) acc[m][n][j] = 0.f;

    // --- async stage loader: 1536 x 16B chunks, 12 per thread ---
    // A: 1024 chunks (2 planes x 128 rows x 4 segs), B: 512 (2 x 64 x 4)
#define LOAD_STAGE(sidx, buf) do { \
        const int k0_ = (sidx) * 32; \
        const uint32_t st_ = sbase + (buf) * STAGE_B; \
        _Pragma("unroll") \
        for (int i_ = 0; i_ < 12; i_++) { \
            int c_ = i_ * 128 + tid; \
            uint32_t dst_; const void* src_; \
            if (c_ < 1024) { \
                int plane_ = c_ >> 9, row_ = (c_ >> 2) & 127, seg_ = c_ & 3; \
                dst_ = st_ + plane_ * 10240 + row_ * 80 + seg_ * 16; \
                src_ = Ab + plane_ * planeA + (long)(rowA0 + row_) * K + k0_ + seg_ * 8; \
            } else { \
                int w_ = c_ - 1024; \
                int plane_ = w_ >> 8, row_ = (w_ >> 2) & 63, seg_ = w_ & 3; \
                dst_ = st_ + 20480 + plane_ * 5120 + row_ * 80 + seg_ * 16; \
                src_ = Bb + plane_ * planeB + (long)(rowB0 + row_) * K + k0_ + seg_ * 8; \
            } \
            asm volatile("cp.async.cg.shared.global [%0], [%1], 16;" :: "r"(dst_), "l"(src_)); \
        } \
        asm volatile("cp.async.commit_group;"); \
    } while (0)

    LOAD_STAGE(0, 0);

    const int lr = l & 15, lh = l >> 4;

    for (int s = 0; s < nst; s++) {
        const int b = s & 1;
        asm volatile("cp.async.wait_group 0;");
        __syncthreads();
        if (s + 1 < nst) LOAD_STAGE(s + 1, b ^ 1);   // overlaps with compute below

        const uint32_t st = sbase + b * STAGE_B;
#pragma unroll
        for (int kk = 0; kk < 32; kk += 16) {
            uint32_t AH[4][4], AL[4][4], BH[2][4], BL[2][4];
            const uint32_t kb = (kk + lh * 8) * 2;
#pragma unroll
            for (int mt = 0; mt < 4; mt++) {
                uint32_t a0 = st + (wr * 64 + mt * 16 + lr) * 80 + kb;
                LDSM4(AH[mt], a0);
                LDSM4(AL[mt], a0 + 10240);
            }
#pragma unroll
            for (int np = 0; np < 2; np++) {
                uint32_t b0 = st + 20480 + (wc * 32 + np * 16 + lr) * 80 + kb;
                LDSM4(BH[np], b0);
                LDSM4(BL[np], b0 + 5120);
            }
            // term-major: same-acc MMAs far apart (no RAW chains)
#pragma unroll
            for (int mt = 0; mt < 4; mt++)
#pragma unroll
                for (int np = 0; np < 2; np++) {
                    MMA_BF16(acc[mt][2 * np],     AH[mt], BH[np][0], BH[np][2]);
                    MMA_BF16(acc[mt][2 * np + 1], AH[mt], BH[np][1], BH[np][3]);
                }
#pragma unroll
            for (int mt = 0; mt < 4; mt++)
#pragma unroll
                for (int np = 0; np < 2; np++) {
                    MMA_BF16(acc[mt][2 * np],     AL[mt], BH[np][0], BH[np][2]);
                    MMA_BF16(acc[mt][2 * np + 1], AL[mt], BH[np][1], BH[np][3]);
                }
#pragma unroll
            for (int mt = 0; mt < 4; mt++)
#pragma unroll
                for (int np = 0; np < 2; np++) {
                    MMA_BF16(acc[mt][2 * np],     AH[mt], BL[np][0], BL[np][2]);
                    MMA_BF16(acc[mt][2 * np + 1], AH[mt], BL[np][1], BL[np][3]);
                }
        }
    }
#undef LOAD_STAGE

    // --- epilogue ---
    const int rql = l >> 2, cpl = (l & 3) * 2;
#pragma unroll
    for (int mt = 0; mt < 4; mt++) {
#pragma unroll
        for (int nt = 0; nt < 4; nt++) {
            const int col = bx * 64 + wc * 32 + nt * 8 + cpl;
            const long row = (long)by * 128 + wr * 64 + mt * 16 + rql;
            float v0 = acc[mt][nt][0] * alpha, v1 = acc[mt][nt][1] * alpha;
            float v2 = acc[mt][nt][2] * alpha, v3 = acc[mt][nt][3] * alpha;
            if (BIAS) {
                float b0 = bias[col], b1 = bias[col + 1];
                v0 += b0; v1 += b1; v2 += b0; v3 += b1;
            }
            const long o0 = (long)bz * strideCz + row * ldc + col;
            const long o1 = o0 + 8L * ldc;
            if (WF32) {
                *reinterpret_cast<float2*>(Cf + o0) = make_float2(v0, v1);
                *reinterpret_cast<float2*>(Cf + o1) = make_float2(v2, v3);
            }
            if (WBF16) {
                __nv_bfloat16 h0 = __float2bfloat16(v0), h1 = __float2bfloat16(v1);
                __nv_bfloat16 h2 = __float2bfloat16(v2), h3 = __float2bfloat16(v3);
                __nv_bfloat16 l0 = __float2bfloat16(v0 - __bfloat162float(h0));
                __nv_bfloat16 l1 = __float2bfloat16(v1 - __bfloat162float(h1));
                __nv_bfloat16 l2 = __float2bfloat16(v2 - __bfloat162float(h2));
                __nv_bfloat16 l3 = __float2bfloat16(v3 - __bfloat162float(h3));
                uint32_t hA = (uint32_t)__bfloat16_as_ushort(h0) | ((uint32_t)__bfloat16_as_ushort(h1) << 16);
                uint32_t hB = (uint32_t)__bfloat16_as_ushort(h2) | ((uint32_t)__bfloat16_as_ushort(h3) << 16);
                uint32_t lA = (uint32_t)__bfloat16_as_ushort(l0) | ((uint32_t)__bfloat16_as_ushort(l1) << 16);
                uint32_t lB = (uint32_t)__bfloat16_as_ushort(l2) | ((uint32_t)__bfloat16_as_ushort(l3) << 16);
                *reinterpret_cast<uint32_t*>(Ch + o0) = hA;
                *reinterpret_cast<uint32_t*>(Ch + o1) = hB;
                *reinterpret_cast<uint32_t*>(Cl + o0) = lA;
                *reinterpret_cast<uint32_t*>(Cl + o1) = lB;
            }
        }
    }
}

// ---------------------------------------------------------------------------
// fp32 -> bf16 hi/lo split; y-dim selects among up to 3 arrays
// ---------------------------------------------------------------------------
__global__ void __launch_bounds__(256) split4x3(const float* __restrict__ i0,
                                                const float* __restrict__ i1,
                                                const float* __restrict__ i2,
                                                __nv_bfloat16* __restrict__ o0,
                                                __nv_bfloat16* __restrict__ o1,
                                                __nv_bfloat16* __restrict__ o2,
                                                long n)
{
    const float* in = (blockIdx.y == 0) ? i0 : (blockIdx.y == 1) ? i1 : i2;
    __nv_bfloat16* out = (blockIdx.y == 0) ? o0 : (blockIdx.y == 1) ? o1 : o2;
    long i = ((long)blockIdx.x * 256 + threadIdx.x) * 4;
    if (i >= n) return;
    float4 v = *reinterpret_cast<const float4*>(in + i);
    __nv_bfloat16 h0 = __float2bfloat16(v.x), h1 = __float2bfloat16(v.y);
    __nv_bfloat16 h2 = __float2bfloat16(v.z), h3 = __float2bfloat16(v.w);
    __nv_bfloat16 l0 = __float2bfloat16(v.x - __bfloat162float(h0));
    __nv_bfloat16 l1 = __float2bfloat16(v.y - __bfloat162float(h1));
    __nv_bfloat16 l2 = __float2bfloat16(v.z - __bfloat162float(h2));
    __nv_bfloat16 l3 = __float2bfloat16(v.w - __bfloat162float(h3));
    uint32_t hA = (uint32_t)__bfloat16_as_ushort(h0) | ((uint32_t)__bfloat16_as_ushort(h1) << 16);
    uint32_t hB = (uint32_t)__bfloat16_as_ushort(h2) | ((uint32_t)__bfloat16_as_ushort(h3) << 16);
    uint32_t lA = (uint32_t)__bfloat16_as_ushort(l0) | ((uint32_t)__bfloat16_as_ushort(l1) << 16);
    uint32_t lB = (uint32_t)__bfloat16_as_ushort(l2) | ((uint32_t)__bfloat16_as_ushort(l3) << 16);
    *reinterpret_cast<uint2*>(out + i) = make_uint2(hA, hB);
    *reinterpret_cast<uint2*>(out + n + i) = make_uint2(lA, lB);
}

// ---------------------------------------------------------------------------
// bf16 transpose: [2][B][S][E] -> [2][B][E][S]
// ---------------------------------------------------------------------------
__global__ void __launch_bounds__(256) transpose_bf16(const __nv_bfloat16* __restrict__ in,
                                                      __nv_bfloat16* __restrict__ out)
{
    __shared__ unsigned short t[32][33];
    const int plane = blockIdx.z / BATCH, b = blockIdx.z % BATCH;
    const long off = ((long)plane * BATCH + b) * (long)SEQ * EMB;
    const unsigned short* ip = reinterpret_cast<const unsigned short*>(in) + off;
    unsigned short* op = reinterpret_cast<unsigned short*>(out) + off;
    const int c0 = blockIdx.x * 32, r0 = blockIdx.y * 32;
    for (int i = threadIdx.y; i < 32; i += 8)
        t[i][threadIdx.x] = ip[(long)(r0 + i) * EMB + c0 + threadIdx.x];
    __syncthreads();
    for (int i = threadIdx.y; i < 32; i += 8)
        op[(long)(c0 + i) * SEQ + r0 + threadIdx.x] = t[threadIdx.x][i];
}

// ---------------------------------------------------------------------------
// Causal row softmax: fp32 scores -> bf16 hi/lo probs (zero tail)
// ---------------------------------------------------------------------------
__global__ void __launch_bounds__(256)
softmax_causal(float* __restrict__ P, __nv_bfloat16* __restrict__ Ph,
               __nv_bfloat16* __restrict__ Pl)
{
    const int row = blockIdx.x;
    const int q = row & (SEQ - 1);
    float* p = P + (long)row * SEQ;
    __nv_bfloat16* ph = Ph + (long)row * SEQ;
    __nv_bfloat16* pl = Pl + (long)row * SEQ;
    const int n = q + 1;
    const int tid = threadIdx.x;

    __shared__ float red[8];

    float m = -3.4e38f;
    for (int i = tid; i < n; i += 256) m = fmaxf(m, p[i]);
#pragma unroll
    for (int o = 16; o > 0; o >>= 1) m = fmaxf(m, __shfl_xor_sync(0xffffffffu, m, o));
    if ((tid & 31) == 0) red[tid >> 5] = m;
    __syncthreads();
    m = red[0];
#pragma unroll
    for (int w = 1; w < 8; w++) m = fmaxf(m, red[w]);
    __syncthreads();

    float s = 0.f;
    for (int i = tid; i < n; i += 256) {
        float e = __expf(p[i] - m);
        p[i] = e;
        s += e;
    }
#pragma unroll
    for (int o = 16; o > 0; o >>= 1) s += __shfl_xor_sync(0xffffffffu, s, o);
    if ((tid & 31) == 0) red[tid >> 5] = s;
    __syncthreads();
    float tot = red[0];
#pragma unroll
    for (int w = 1; w < 8; w++) tot += red[w];
    const float inv = 1.f / tot;

    for (int i = tid; i < n; i += 256) {
        float pr = p[i] * inv;
        __nv_bfloat16 h = __float2bfloat16(pr);
        __nv_bfloat16 lo = __float2bfloat16(pr - __bfloat162float(h));
        ph[i] = h;
        pl[i] = lo;
    }
    const __nv_bfloat16 z = __float2bfloat16(0.f);
    for (int i = n + tid; i < SEQ; i += 256) { ph[i] = z; pl[i] = z; }
}

// ---------------------------------------------------------------------------
extern "C" void kernel_launch(void* const* d_in, const int* in_sizes, int n_in,
                              void* d_out, int out_size)
{
    (void)in_sizes; (void)n_in; (void)out_size;
    const float* xq = (const float*)d_in[0];
    const float* xk = (const float*)d_in[1];
    const float* xv = (const float*)d_in[2];
    const float* Wq = (const float*)d_in[3];
    const float* bq = (const float*)d_in[4];
    float* out = (float*)d_out;

    void *xq2, *xk2, *xv2, *W2, *Q2, *K2, *V2, *VT2, *P2, *Pf;
    cudaGetSymbolAddress(&xq2, g_xq2);
    cudaGetSymbolAddress(&xk2, g_xk2);
    cudaGetSymbolAddress(&xv2, g_xv2);
    cudaGetSymbolAddress(&W2, g_W2);
    cudaGetSymbolAddress(&Q2, g_Q2);
    cudaGetSymbolAddress(&K2, g_K2);
    cudaGetSymbolAddress(&V2, g_V2);
    cudaGetSymbolAddress(&VT2, g_VT2);
    cudaGetSymbolAddress(&P2, g_P2);
    cudaGetSymbolAddress(&Pf, g_Pf);

    auto kProj = gemm_mma<false, false, true, false, true>;
    auto kQK   = gemm_mma<true,  false, false, true, false>;
    auto kPV   = gemm_mma<false, true,  false, true, false>;
    cudaFuncSetAttribute(kProj, cudaFuncAttributeMaxDynamicSharedMemorySize, SMEM_REQ);
    cudaFuncSetAttribute(kQK,   cudaFuncAttributeMaxDynamicSharedMemorySize, SMEM_REQ);
    cudaFuncSetAttribute(kPV,   cudaFuncAttributeMaxDynamicSharedMemorySize, SMEM_REQ);

    // 1) split inputs to bf16 hi/lo (one launch for xq/xk/xv, one for W)
    split4x3<<<dim3((unsigned)(NELEM / 4 / 256), 3), 256>>>(
        xq, xk, xv, (__nv_bfloat16*)xq2, (__nv_bfloat16*)xk2, (__nv_bfloat16*)xv2, NELEM);
    split4x3<<<dim3((unsigned)((long)EMB * EMB / 4 / 256), 1), 256>>>(
        Wq, nullptr, nullptr, (__nv_bfloat16*)W2, nullptr, nullptr, (long)EMB * EMB);

    // 2) projections: Q/K/V = x @ W^T + b -> bf16 hi/lo
    {
        dim3 g(EMB / 64, MTOT / 128, 1);
        kProj<<<g, 128, SMEM_REQ>>>((const __nv_bfloat16*)xq2, 0, NELEM,
                                    (const __nv_bfloat16*)W2, 0, (long)EMB * EMB,
                                    EMB, 1.0f, bq, nullptr,
                                    (__nv_bfloat16*)Q2, (__nv_bfloat16*)Q2 + NELEM, EMB, 0);
        kProj<<<g, 128, SMEM_REQ>>>((const __nv_bfloat16*)xk2, 0, NELEM,
                                    (const __nv_bfloat16*)W2, 0, (long)EMB * EMB,
                                    EMB, 1.0f, bq, nullptr,
                                    (__nv_bfloat16*)K2, (__nv_bfloat16*)K2 + NELEM, EMB, 0);
        kProj<<<g, 128, SMEM_REQ>>>((const __nv_bfloat16*)xv2, 0, NELEM,
                                    (const __nv_bfloat16*)W2, 0, (long)EMB * EMB,
                                    EMB, 1.0f, bq, nullptr,
                                    (__nv_bfloat16*)V2, (__nv_bfloat16*)V2 + NELEM, EMB, 0);
    }

    // 3) V transpose -> [2][B][E][S]
    transpose_bf16<<<dim3(EMB / 32, SEQ / 32, 2 * BATCH), dim3(32, 8)>>>(
        (const __nv_bfloat16*)V2, (__nv_bfloat16*)VT2);

    // 4) scores = scale * Q @ K^T (causal tile skip) -> fp32
    {
        dim3 g(SEQ / 64, SEQ / 128, BATCH);
        kQK<<<g, 128, SMEM_REQ>>>((const __nv_bfloat16*)Q2, (long)SEQ * EMB, NELEM,
                                  (const __nv_bfloat16*)K2, (long)SEQ * EMB, NELEM,
                                  EMB, 0.03125f, nullptr,
                                  (float*)Pf, nullptr, nullptr, SEQ, (long)SEQ * SEQ);
    }

    // 5) softmax -> bf16 hi/lo probs
    softmax_causal<<<MTOT, 256>>>((float*)Pf, (__nv_bfloat16*)P2,
                                  (__nv_bfloat16*)P2 + NP);

    // 6) out = P @ VT^T (K-truncated at diagonal, longest-first) -> fp32
    {
        dim3 g(EMB / 64, SEQ / 128, BATCH);
        kPV<<<g, 128, SMEM_REQ>>>((const __nv_bfloat16*)P2, (long)SEQ * SEQ, NP,
                                  (const __nv_bfloat16*)VT2, (long)SEQ * EMB, NELEM,
                                  SEQ, 1.0f, nullptr,
                                  out, nullptr, nullptr, EMB, (long)SEQ * EMB);
    }
}

// round 7
// speedup vs baseline: 3.6007x; 1.4149x over previous
#include <cuda_runtime.h>
#include <cuda_fp16.h>
#include <cstdint>

#define BATCH 4
#define SEQ   2048
#define EMB   1024
#define MTOT  (BATCH * SEQ)                 // 8192
#define NELEM ((long)MTOT * EMB)            // 8388608
#define NP    ((long)BATCH * SEQ * SEQ)     // 16777216

// ---------------------------------------------------------------------------
// Scratch. A-role tensors: fp16 hi+lo planes. B-role tensors: fp16 hi only.
// ---------------------------------------------------------------------------
__device__ __half g_xq2[2 * NELEM];
__device__ __half g_xk2[2 * NELEM];
__device__ __half g_xv2[2 * NELEM];
__device__ __half g_W1[(long)EMB * EMB];     // B in proj (hi only)
__device__ __half g_Q2[2 * NELEM];           // A in QK (hi/lo)
__device__ __half g_K1[NELEM];               // B in QK (hi only)
__device__ __half g_V1[NELEM];               // hi only
__device__ __half g_VT1[NELEM];              // [B][E][S] (B in PV)
__device__ __half g_P2[2 * NP];              // A in PV (hi/lo)
__device__ float  g_Pf[NP];                  // fp32 scores

// ---------------------------------------------------------------------------
__device__ __forceinline__ uint32_t smem_u32(const void* p) {
    uint32_t a;
    asm("{ .reg .u64 t; cvta.to.shared.u64 t, %1; cvt.u32.u64 %0, t; }" : "=r"(a) : "l"(p));
    return a;
}

#define LDSM4(r, addr) \
    asm volatile("ldmatrix.sync.aligned.m8n8.x4.shared.b16 {%0,%1,%2,%3}, [%4];" \
        : "=r"((r)[0]), "=r"((r)[1]), "=r"((r)[2]), "=r"((r)[3]) : "r"(addr))

#define MMA_F16(d, a, b0, b1) \
    asm volatile("mma.sync.aligned.m16n8k16.row.col.f32.f16.f16.f32 " \
        "{%0,%1,%2,%3}, {%4,%5,%6,%7}, {%8,%9}, {%0,%1,%2,%3};" \
        : "+f"((d)[0]), "+f"((d)[1]), "+f"((d)[2]), "+f"((d)[3]) \
        : "r"((a)[0]), "r"((a)[1]), "r"((a)[2]), "r"((a)[3]), "r"(b0), "r"(b1))

// CTA tile 128x64, BK=32. Stage: A hi 10240 + A lo 10240 + B hi 5120 = 25600.
// row pitch 80B (32 fp16 + 8 pad) -> ldmatrix conflict-free
#define STAGE_B   25600
#define SMEM_REQ  (2 * STAGE_B)

// ---------------------------------------------------------------------------
// 2-term fp16 TC GEMM: C[128x64] = alpha * (Ah+Al) @ Bh^T (+ bias)
// 128 threads, 4 warps (2m x 2n), warp tile 64x32, 3 CTAs/SM.
// A: [2][rowsA][K] fp16 (hi, lo planeA apart); B: [rowsB][K] fp16 hi.
// Output: WF32 fp32 | WHL fp16 hi+lo | WH fp16 hi.
// ---------------------------------------------------------------------------
template <bool CAUSAL, bool TRUNCK, bool BIAS, bool WF32, bool WHL, bool WH>
__global__ void __launch_bounds__(128, 3)
gemm_mma(const __half* __restrict__ A, long strideAz, long planeA,
         const __half* __restrict__ B, long strideBz,
         int K, float alpha, const float* __restrict__ bias,
         float* __restrict__ Cf, __half* __restrict__ Ch, long planeC,
         int ldc, long strideCz)
{
    const int bx = blockIdx.x, bz = blockIdx.z;
    const int by = TRUNCK ? (gridDim.y - 1 - blockIdx.y) : blockIdx.y;
    if (CAUSAL && bx > 2 * by + 1) return;   // 64-col tile vs 128-row tile

    extern __shared__ char smem[];
    const uint32_t sbase = smem_u32(smem);

    const __half* Ab = A + (long)bz * strideAz;
    const __half* Bb = B + (long)bz * strideBz;

    const int tid = threadIdx.x, wid = tid >> 5, l = tid & 31;
    const int wr = wid >> 1, wc = wid & 1;     // warp 64m x 32n
    const int kEnd = TRUNCK ? min(K, (by + 1) * 128) : K;
    const int nst = kEnd >> 5;                 // BK=32 stages
    const int rowA0 = by * 128, rowB0 = bx * 64;

    float acc[4][4][4];
#pragma unroll
    for (int m = 0; m < 4; m++)
#pragma unroll
        for (int n = 0; n < 4; n++)
#pragma unroll
            for (int j = 0; j < 4; j++) acc[m][n][j] = 0.f;

    // 1280 x 16B chunks per stage: A 1024 (2 planes x 128 rows x 4), B 256
#define LOAD_STAGE(sidx, buf) do { \
        const int k0_ = (sidx) * 32; \
        const uint32_t st_ = sbase + (buf) * STAGE_B; \
        _Pragma("unroll") \
        for (int i_ = 0; i_ < 10; i_++) { \
            int c_ = i_ * 128 + tid; \
            uint32_t dst_; const void* src_; \
            if (c_ < 1024) { \
                int plane_ = c_ >> 9, row_ = (c_ >> 2) & 127, seg_ = c_ & 3; \
                dst_ = st_ + plane_ * 10240 + row_ * 80 + seg_ * 16; \
                src_ = Ab + plane_ * planeA + (long)(rowA0 + row_) * K + k0_ + seg_ * 8; \
            } else { \
                int w_ = c_ - 1024; \
                int row_ = w_ >> 2, seg_ = w_ & 3; \
                dst_ = st_ + 20480 + row_ * 80 + seg_ * 16; \
                src_ = Bb + (long)(rowB0 + row_) * K + k0_ + seg_ * 8; \
            } \
            asm volatile("cp.async.cg.shared.global [%0], [%1], 16;" :: "r"(dst_), "l"(src_)); \
        } \
        asm volatile("cp.async.commit_group;"); \
    } while (0)

    LOAD_STAGE(0, 0);

    const int lr = l & 15, lh = l >> 4;

    for (int s = 0; s < nst; s++) {
        const int b = s & 1;
        asm volatile("cp.async.wait_group 0;");
        __syncthreads();
        if (s + 1 < nst) LOAD_STAGE(s + 1, b ^ 1);

        const uint32_t st = sbase + b * STAGE_B;
#pragma unroll
        for (int kk = 0; kk < 32; kk += 16) {
            uint32_t AH[4][4], AL[4][4], BH[2][4];
            const uint32_t kb = (kk + lh * 8) * 2;
#pragma unroll
            for (int mt = 0; mt < 4; mt++) {
                uint32_t a0 = st + (wr * 64 + mt * 16 + lr) * 80 + kb;
                LDSM4(AH[mt], a0);
                LDSM4(AL[mt], a0 + 10240);
            }
#pragma unroll
            for (int np = 0; np < 2; np++) {
                uint32_t b0 = st + 20480 + (wc * 32 + np * 16 + lr) * 80 + kb;
                LDSM4(BH[np], b0);
            }
#pragma unroll
            for (int mt = 0; mt < 4; mt++)
#pragma unroll
                for (int np = 0; np < 2; np++) {
                    MMA_F16(acc[mt][2 * np],     AH[mt], BH[np][0], BH[np][2]);
                    MMA_F16(acc[mt][2 * np + 1], AH[mt], BH[np][1], BH[np][3]);
                }
#pragma unroll
            for (int mt = 0; mt < 4; mt++)
#pragma unroll
                for (int np = 0; np < 2; np++) {
                    MMA_F16(acc[mt][2 * np],     AL[mt], BH[np][0], BH[np][2]);
                    MMA_F16(acc[mt][2 * np + 1], AL[mt], BH[np][1], BH[np][3]);
                }
        }
    }
#undef LOAD_STAGE

    // --- epilogue ---
    const int rql = l >> 2, cpl = (l & 3) * 2;
#pragma unroll
    for (int mt = 0; mt < 4; mt++) {
#pragma unroll
        for (int nt = 0; nt < 4; nt++) {
            const int col = bx * 64 + wc * 32 + nt * 8 + cpl;
            const long row = (long)by * 128 + wr * 64 + mt * 16 + rql;
            float v0 = acc[mt][nt][0] * alpha, v1 = acc[mt][nt][1] * alpha;
            float v2 = acc[mt][nt][2] * alpha, v3 = acc[mt][nt][3] * alpha;
            if (BIAS) {
                float b0 = bias[col], b1 = bias[col + 1];
                v0 += b0; v1 += b1; v2 += b0; v3 += b1;
            }
            const long o0 = (long)bz * strideCz + row * ldc + col;
            const long o1 = o0 + 8L * ldc;
            if (WF32) {
                *reinterpret_cast<float2*>(Cf + o0) = make_float2(v0, v1);
                *reinterpret_cast<float2*>(Cf + o1) = make_float2(v2, v3);
            }
            if (WHL || WH) {
                __half h0 = __float2half(v0), h1 = __float2half(v1);
                __half h2 = __float2half(v2), h3 = __float2half(v3);
                uint32_t hA = (uint32_t)__half_as_ushort(h0) | ((uint32_t)__half_as_ushort(h1) << 16);
                uint32_t hB = (uint32_t)__half_as_ushort(h2) | ((uint32_t)__half_as_ushort(h3) << 16);
                *reinterpret_cast<uint32_t*>(Ch + o0) = hA;
                *reinterpret_cast<uint32_t*>(Ch + o1) = hB;
                if (WHL) {
                    __half l0 = __float2half(v0 - __half2float(h0));
                    __half l1 = __float2half(v1 - __half2float(h1));
                    __half l2 = __float2half(v2 - __half2float(h2));
                    __half l3 = __float2half(v3 - __half2float(h3));
                    uint32_t lA = (uint32_t)__half_as_ushort(l0) | ((uint32_t)__half_as_ushort(l1) << 16);
                    uint32_t lB = (uint32_t)__half_as_ushort(l2) | ((uint32_t)__half_as_ushort(l3) << 16);
                    *reinterpret_cast<uint32_t*>(Ch + planeC + o0) = lA;
                    *reinterpret_cast<uint32_t*>(Ch + planeC + o1) = lB;
                }
            }
        }
    }
}

// ---------------------------------------------------------------------------
// fp32 -> fp16 hi/lo split; y-dim selects among 3 arrays
// ---------------------------------------------------------------------------
__global__ void __launch_bounds__(256) split4x3(const float* __restrict__ i0,
                                                const float* __restrict__ i1,
                                                const float* __restrict__ i2,
                                                __half* __restrict__ o0,
                                                __half* __restrict__ o1,
                                                __half* __restrict__ o2,
                                                long n)
{
    const float* in = (blockIdx.y == 0) ? i0 : (blockIdx.y == 1) ? i1 : i2;
    __half* out = (blockIdx.y == 0) ? o0 : (blockIdx.y == 1) ? o1 : o2;
    long i = ((long)blockIdx.x * 256 + threadIdx.x) * 4;
    if (i >= n) return;
    float4 v = *reinterpret_cast<const float4*>(in + i);
    __half h0 = __float2half(v.x), h1 = __float2half(v.y);
    __half h2 = __float2half(v.z), h3 = __float2half(v.w);
    __half l0 = __float2half(v.x - __half2float(h0));
    __half l1 = __float2half(v.y - __half2float(h1));
    __half l2 = __float2half(v.z - __half2float(h2));
    __half l3 = __float2half(v.w - __half2float(h3));
    uint32_t hA = (uint32_t)__half_as_ushort(h0) | ((uint32_t)__half_as_ushort(h1) << 16);
    uint32_t hB = (uint32_t)__half_as_ushort(h2) | ((uint32_t)__half_as_ushort(h3) << 16);
    uint32_t lA = (uint32_t)__half_as_ushort(l0) | ((uint32_t)__half_as_ushort(l1) << 16);
    uint32_t lB = (uint32_t)__half_as_ushort(l2) | ((uint32_t)__half_as_ushort(l3) << 16);
    *reinterpret_cast<uint2*>(out + i) = make_uint2(hA, hB);
    *reinterpret_cast<uint2*>(out + n + i) = make_uint2(lA, lB);
}

// fp32 -> fp16 hi only (for W)
__global__ void __launch_bounds__(256) splitH(const float* __restrict__ in,
                                              __half* __restrict__ out, long n)
{
    long i = ((long)blockIdx.x * 256 + threadIdx.x) * 4;
    if (i >= n) return;
    float4 v = *reinterpret_cast<const float4*>(in + i);
    __half h0 = __float2half(v.x), h1 = __float2half(v.y);
    __half h2 = __float2half(v.z), h3 = __float2half(v.w);
    uint32_t hA = (uint32_t)__half_as_ushort(h0) | ((uint32_t)__half_as_ushort(h1) << 16);
    uint32_t hB = (uint32_t)__half_as_ushort(h2) | ((uint32_t)__half_as_ushort(h3) << 16);
    *reinterpret_cast<uint2*>(out + i) = make_uint2(hA, hB);
}

// ---------------------------------------------------------------------------
// fp16 transpose: [B][S][E] -> [B][E][S]
// ---------------------------------------------------------------------------
__global__ void __launch_bounds__(256) transpose_f16(const __half* __restrict__ in,
                                                     __half* __restrict__ out)
{
    __shared__ unsigned short t[32][33];
    const int b = blockIdx.z;
    const long off = (long)b * SEQ * EMB;
    const unsigned short* ip = reinterpret_cast<const unsigned short*>(in) + off;
    unsigned short* op = reinterpret_cast<unsigned short*>(out) + off;
    const int c0 = blockIdx.x * 32, r0 = blockIdx.y * 32;
    for (int i = threadIdx.y; i < 32; i += 8)
        t[i][threadIdx.x] = ip[(long)(r0 + i) * EMB + c0 + threadIdx.x];
    __syncthreads();
    for (int i = threadIdx.y; i < 32; i += 8)
        op[(long)(c0 + i) * SEQ + r0 + threadIdx.x] = t[threadIdx.x][i];
}

// ---------------------------------------------------------------------------
// Causal row softmax: fp32 scores -> fp16 hi/lo probs (zero tail)
// ---------------------------------------------------------------------------
__global__ void __launch_bounds__(256)
softmax_causal(float* __restrict__ P, __half* __restrict__ Ph,
               __half* __restrict__ Pl)
{
    const int row = blockIdx.x;
    const int q = row & (SEQ - 1);
    float* p = P + (long)row * SEQ;
    __half* ph = Ph + (long)row * SEQ;
    __half* pl = Pl + (long)row * SEQ;
    const int n = q + 1;
    const int tid = threadIdx.x;

    __shared__ float red[8];

    float m = -3.4e38f;
    for (int i = tid; i < n; i += 256) m = fmaxf(m, p[i]);
#pragma unroll
    for (int o = 16; o > 0; o >>= 1) m = fmaxf(m, __shfl_xor_sync(0xffffffffu, m, o));
    if ((tid & 31) == 0) red[tid >> 5] = m;
    __syncthreads();
    m = red[0];
#pragma unroll
    for (int w = 1; w < 8; w++) m = fmaxf(m, red[w]);
    __syncthreads();

    float s = 0.f;
    for (int i = tid; i < n; i += 256) {
        float e = __expf(p[i] - m);
        p[i] = e;
        s += e;
    }
#pragma unroll
    for (int o = 16; o > 0; o >>= 1) s += __shfl_xor_sync(0xffffffffu, s, o);
    if ((tid & 31) == 0) red[tid >> 5] = s;
    __syncthreads();
    float tot = red[0];
#pragma unroll
    for (int w = 1; w < 8; w++) tot += red[w];
    const float inv = 1.f / tot;

    for (int i = tid; i < n; i += 256) {
        float pr = p[i] * inv;
        __half h = __float2half(pr);
        __half lo = __float2half(pr - __half2float(h));
        ph[i] = h;
        pl[i] = lo;
    }
    const __half z = __float2half(0.f);
    for (int i = n + tid; i < SEQ; i += 256) { ph[i] = z; pl[i] = z; }
}

// ---------------------------------------------------------------------------
extern "C" void kernel_launch(void* const* d_in, const int* in_sizes, int n_in,
                              void* d_out, int out_size)
{
    (void)in_sizes; (void)n_in; (void)out_size;
    const float* xq = (const float*)d_in[0];
    const float* xk = (const float*)d_in[1];
    const float* xv = (const float*)d_in[2];
    const float* Wq = (const float*)d_in[3];
    const float* bq = (const float*)d_in[4];
    float* out = (float*)d_out;

    void *xq2, *xk2, *xv2, *W1, *Q2, *K1, *V1, *VT1, *P2, *Pf;
    cudaGetSymbolAddress(&xq2, g_xq2);
    cudaGetSymbolAddress(&xk2, g_xk2);
    cudaGetSymbolAddress(&xv2, g_xv2);
    cudaGetSymbolAddress(&W1, g_W1);
    cudaGetSymbolAddress(&Q2, g_Q2);
    cudaGetSymbolAddress(&K1, g_K1);
    cudaGetSymbolAddress(&V1, g_V1);
    cudaGetSymbolAddress(&VT1, g_VT1);
    cudaGetSymbolAddress(&P2, g_P2);
    cudaGetSymbolAddress(&Pf, g_Pf);

    auto kProjQ = gemm_mma<false, false, true, false, true, false>;   // WHL
    auto kProjKV = gemm_mma<false, false, true, false, false, true>;  // WH
    auto kQK    = gemm_mma<true,  false, false, true, false, false>;  // WF32
    auto kPV    = gemm_mma<false, true,  false, true, false, false>;  // WF32
    cudaFuncSetAttribute(kProjQ,  cudaFuncAttributeMaxDynamicSharedMemorySize, SMEM_REQ);
    cudaFuncSetAttribute(kProjKV, cudaFuncAttributeMaxDynamicSharedMemorySize, SMEM_REQ);
    cudaFuncSetAttribute(kQK,     cudaFuncAttributeMaxDynamicSharedMemorySize, SMEM_REQ);
    cudaFuncSetAttribute(kPV,     cudaFuncAttributeMaxDynamicSharedMemorySize, SMEM_REQ);

    // 1) splits
    split4x3<<<dim3((unsigned)(NELEM / 4 / 256), 3), 256>>>(
        xq, xk, xv, (__half*)xq2, (__half*)xk2, (__half*)xv2, NELEM);
    splitH<<<(unsigned)((long)EMB * EMB / 4 / 256), 256>>>(Wq, (__half*)W1, (long)EMB * EMB);

    // 2) projections: Q (hi/lo), K (hi), V (hi)
    {
        dim3 g(EMB / 64, MTOT / 128, 1);
        kProjQ<<<g, 128, SMEM_REQ>>>((const __half*)xq2, 0, NELEM,
                                     (const __half*)W1, 0,
                                     EMB, 1.0f, bq, nullptr,
                                     (__half*)Q2, NELEM, EMB, 0);
        kProjKV<<<g, 128, SMEM_REQ>>>((const __half*)xk2, 0, NELEM,
                                      (const __half*)W1, 0,
                                      EMB, 1.0f, bq, nullptr,
                                      (__half*)K1, 0, EMB, 0);
        kProjKV<<<g, 128, SMEM_REQ>>>((const __half*)xv2, 0, NELEM,
                                      (const __half*)W1, 0,
                                      EMB, 1.0f, bq, nullptr,
                                      (__half*)V1, 0, EMB, 0);
    }

    // 3) V transpose -> [B][E][S]
    transpose_f16<<<dim3(EMB / 32, SEQ / 32, BATCH), dim3(32, 8)>>>(
        (const __half*)V1, (__half*)VT1);

    // 4) scores = scale * Q @ K^T (causal tile skip) -> fp32
    {
        dim3 g(SEQ / 64, SEQ / 128, BATCH);
        kQK<<<g, 128, SMEM_REQ>>>((const __half*)Q2, (long)SEQ * EMB, NELEM,
                                  (const __half*)K1, (long)SEQ * EMB,
                                  EMB, 0.03125f, nullptr,
                                  (float*)Pf, nullptr, 0, SEQ, (long)SEQ * SEQ);
    }

    // 5) softmax -> fp16 hi/lo probs
    softmax_causal<<<MTOT, 256>>>((float*)Pf, (__half*)P2, (__half*)P2 + NP);

    // 6) out = P @ VT^T (K-truncated, longest-first) -> fp32
    {
        dim3 g(EMB / 64, SEQ / 128, BATCH);
        kPV<<<g, 128, SMEM_REQ>>>((const __half*)P2, (long)SEQ * SEQ, NP,
                                  (const __half*)VT1, (long)SEQ * EMB,
                                  SEQ, 1.0f, nullptr,
                                  out, nullptr, 0, EMB, (long)SEQ * EMB);
    }
}

// round 8
// speedup vs baseline: 6.3646x; 1.7676x over previous
#include <cuda_runtime.h>
#include <cuda_fp16.h>
#include <cstdint>

#define BATCH 4
#define SEQ   2048
#define EMB   1024
#define MTOT  (BATCH * SEQ)                 // 8192
#define NELEM ((long)MTOT * EMB)            // 8388608
#define NP    ((long)BATCH * SEQ * SEQ)     // 16777216

// ---------------------------------------------------------------------------
// Scratch — everything single-plane fp16 now.
// ---------------------------------------------------------------------------
__device__ __half g_xq1[NELEM];
__device__ __half g_xk1[NELEM];
__device__ __half g_xv1[NELEM];
__device__ __half g_W1[(long)EMB * EMB];
__device__ __half g_Q1[NELEM];
__device__ __half g_K1[NELEM];
__device__ __half g_V1[NELEM];
__device__ __half g_VT1[NELEM];              // [B][E][S]
__device__ __half g_P1[NP];                  // probs
__device__ float  g_Pf[NP];                  // fp32 scores

// ---------------------------------------------------------------------------
__device__ __forceinline__ uint32_t smem_u32(const void* p) {
    uint32_t a;
    asm("{ .reg .u64 t; cvta.to.shared.u64 t, %1; cvt.u32.u64 %0, t; }" : "=r"(a) : "l"(p));
    return a;
}

#define LDSM4(r, addr) \
    asm volatile("ldmatrix.sync.aligned.m8n8.x4.shared.b16 {%0,%1,%2,%3}, [%4];" \
        : "=r"((r)[0]), "=r"((r)[1]), "=r"((r)[2]), "=r"((r)[3]) : "r"(addr))

#define MMA_F16(d, a, b0, b1) \
    asm volatile("mma.sync.aligned.m16n8k16.row.col.f32.f16.f16.f32 " \
        "{%0,%1,%2,%3}, {%4,%5,%6,%7}, {%8,%9}, {%0,%1,%2,%3};" \
        : "+f"((d)[0]), "+f"((d)[1]), "+f"((d)[2]), "+f"((d)[3]) \
        : "r"((a)[0]), "r"((a)[1]), "r"((a)[2]), "r"((a)[3]), "r"(b0), "r"(b1))

// CTA tile 128x64, BK=32. Stage: A 10240 + B 5120 = 15360 bytes.
// row pitch 80B (32 fp16 + 8 pad) -> ldmatrix conflict-free
#define STAGE_B   15360
#define SMEM_REQ  (2 * STAGE_B)

// ---------------------------------------------------------------------------
// Plain fp16 TC GEMM (fp32 accum): C[128x64] = alpha * A @ B^T (+ bias)
// 128 threads, 4 warps (2m x 2n), warp tile 64x32, 4 CTAs/SM.
// A: [rowsA][K] fp16; B: [rowsB][K] fp16. Output fp32 (WF32) or fp16.
// ---------------------------------------------------------------------------
template <bool CAUSAL, bool TRUNCK, bool BIAS, bool WF32>
__global__ void __launch_bounds__(128, 4)
gemm_f16(const __half* __restrict__ A, long strideAz,
         const __half* __restrict__ B, long strideBz,
         int K, float alpha, const float* __restrict__ bias,
         float* __restrict__ Cf, __half* __restrict__ Ch,
         int ldc, long strideCz)
{
    const int bx = blockIdx.x, bz = blockIdx.z;
    const int by = TRUNCK ? (gridDim.y - 1 - blockIdx.y) : blockIdx.y;
    if (CAUSAL && bx > 2 * by + 1) return;   // 64-col tile vs 128-row tile

    extern __shared__ char smem[];
    const uint32_t sbase = smem_u32(smem);

    const __half* Ab = A + (long)bz * strideAz;
    const __half* Bb = B + (long)bz * strideBz;

    const int tid = threadIdx.x, wid = tid >> 5, l = tid & 31;
    const int wr = wid >> 1, wc = wid & 1;     // warp 64m x 32n
    const int kEnd = TRUNCK ? min(K, (by + 1) * 128) : K;
    const int nst = kEnd >> 5;                 // BK=32 stages
    const int rowA0 = by * 128, rowB0 = bx * 64;

    float acc[4][4][4];
#pragma unroll
    for (int m = 0; m < 4; m++)
#pragma unroll
        for (int n = 0; n < 4; n++)
#pragma unroll
            for (int j = 0; j < 4; j++) acc[m][n][j] = 0.f;

    // 768 x 16B chunks per stage: A 512 (128 rows x 4 segs), B 256 (64 x 4)
#define LOAD_STAGE(sidx, buf) do { \
        const int k0_ = (sidx) * 32; \
        const uint32_t st_ = sbase + (buf) * STAGE_B; \
        _Pragma("unroll") \
        for (int i_ = 0; i_ < 6; i_++) { \
            int c_ = i_ * 128 + tid; \
            uint32_t dst_; const void* src_; \
            if (c_ < 512) { \
                int row_ = c_ >> 2, seg_ = c_ & 3; \
                dst_ = st_ + row_ * 80 + seg_ * 16; \
                src_ = Ab + (long)(rowA0 + row_) * K + k0_ + seg_ * 8; \
            } else { \
                int w_ = c_ - 512; \
                int row_ = w_ >> 2, seg_ = w_ & 3; \
                dst_ = st_ + 10240 + row_ * 80 + seg_ * 16; \
                src_ = Bb + (long)(rowB0 + row_) * K + k0_ + seg_ * 8; \
            } \
            asm volatile("cp.async.cg.shared.global [%0], [%1], 16;" :: "r"(dst_), "l"(src_)); \
        } \
        asm volatile("cp.async.commit_group;"); \
    } while (0)

    LOAD_STAGE(0, 0);

    const int lr = l & 15, lh = l >> 4;

    for (int s = 0; s < nst; s++) {
        const int b = s & 1;
        asm volatile("cp.async.wait_group 0;");
        __syncthreads();
        if (s + 1 < nst) LOAD_STAGE(s + 1, b ^ 1);

        const uint32_t st = sbase + b * STAGE_B;
#pragma unroll
        for (int kk = 0; kk < 32; kk += 16) {
            uint32_t AH[4][4], BH[2][4];
            const uint32_t kb = (kk + lh * 8) * 2;
#pragma unroll
            for (int mt = 0; mt < 4; mt++) {
                uint32_t a0 = st + (wr * 64 + mt * 16 + lr) * 80 + kb;
                LDSM4(AH[mt], a0);
            }
#pragma unroll
            for (int np = 0; np < 2; np++) {
                uint32_t b0 = st + 10240 + (wc * 32 + np * 16 + lr) * 80 + kb;
                LDSM4(BH[np], b0);
            }
#pragma unroll
            for (int mt = 0; mt < 4; mt++)
#pragma unroll
                for (int np = 0; np < 2; np++) {
                    MMA_F16(acc[mt][2 * np],     AH[mt], BH[np][0], BH[np][2]);
                    MMA_F16(acc[mt][2 * np + 1], AH[mt], BH[np][1], BH[np][3]);
                }
        }
    }
#undef LOAD_STAGE

    // --- epilogue ---
    const int rql = l >> 2, cpl = (l & 3) * 2;
#pragma unroll
    for (int mt = 0; mt < 4; mt++) {
#pragma unroll
        for (int nt = 0; nt < 4; nt++) {
            const int col = bx * 64 + wc * 32 + nt * 8 + cpl;
            const long row = (long)by * 128 + wr * 64 + mt * 16 + rql;
            float v0 = acc[mt][nt][0] * alpha, v1 = acc[mt][nt][1] * alpha;
            float v2 = acc[mt][nt][2] * alpha, v3 = acc[mt][nt][3] * alpha;
            if (BIAS) {
                float b0 = bias[col], b1 = bias[col + 1];
                v0 += b0; v1 += b1; v2 += b0; v3 += b1;
            }
            const long o0 = (long)bz * strideCz + row * ldc + col;
            const long o1 = o0 + 8L * ldc;
            if (WF32) {
                *reinterpret_cast<float2*>(Cf + o0) = make_float2(v0, v1);
                *reinterpret_cast<float2*>(Cf + o1) = make_float2(v2, v3);
            } else {
                __half h0 = __float2half(v0), h1 = __float2half(v1);
                __half h2 = __float2half(v2), h3 = __float2half(v3);
                uint32_t hA = (uint32_t)__half_as_ushort(h0) | ((uint32_t)__half_as_ushort(h1) << 16);
                uint32_t hB = (uint32_t)__half_as_ushort(h2) | ((uint32_t)__half_as_ushort(h3) << 16);
                *reinterpret_cast<uint32_t*>(Ch + o0) = hA;
                *reinterpret_cast<uint32_t*>(Ch + o1) = hB;
            }
        }
    }
}

// ---------------------------------------------------------------------------
// fp32 -> fp16; y-dim selects among up to 3 arrays
// ---------------------------------------------------------------------------
__global__ void __launch_bounds__(256) cvtH3(const float* __restrict__ i0,
                                             const float* __restrict__ i1,
                                             const float* __restrict__ i2,
                                             __half* __restrict__ o0,
                                             __half* __restrict__ o1,
                                             __half* __restrict__ o2,
                                             long n)
{
    const float* in = (blockIdx.y == 0) ? i0 : (blockIdx.y == 1) ? i1 : i2;
    __half* out = (blockIdx.y == 0) ? o0 : (blockIdx.y == 1) ? o1 : o2;
    long i = ((long)blockIdx.x * 256 + threadIdx.x) * 4;
    if (i >= n) return;
    float4 v = *reinterpret_cast<const float4*>(in + i);
    __half h0 = __float2half(v.x), h1 = __float2half(v.y);
    __half h2 = __float2half(v.z), h3 = __float2half(v.w);
    uint32_t hA = (uint32_t)__half_as_ushort(h0) | ((uint32_t)__half_as_ushort(h1) << 16);
    uint32_t hB = (uint32_t)__half_as_ushort(h2) | ((uint32_t)__half_as_ushort(h3) << 16);
    *reinterpret_cast<uint2*>(out + i) = make_uint2(hA, hB);
}

// ---------------------------------------------------------------------------
// fp16 transpose: [B][S][E] -> [B][E][S]
// ---------------------------------------------------------------------------
__global__ void __launch_bounds__(256) transpose_f16(const __half* __restrict__ in,
                                                     __half* __restrict__ out)
{
    __shared__ unsigned short t[32][33];
    const int b = blockIdx.z;
    const long off = (long)b * SEQ * EMB;
    const unsigned short* ip = reinterpret_cast<const unsigned short*>(in) + off;
    unsigned short* op = reinterpret_cast<unsigned short*>(out) + off;
    const int c0 = blockIdx.x * 32, r0 = blockIdx.y * 32;
    for (int i = threadIdx.y; i < 32; i += 8)
        t[i][threadIdx.x] = ip[(long)(r0 + i) * EMB + c0 + threadIdx.x];
    __syncthreads();
    for (int i = threadIdx.y; i < 32; i += 8)
        op[(long)(c0 + i) * SEQ + r0 + threadIdx.x] = t[threadIdx.x][i];
}

// ---------------------------------------------------------------------------
// Causal row softmax: fp32 scores -> fp16 probs (zero tail)
// ---------------------------------------------------------------------------
__global__ void __launch_bounds__(256)
softmax_causal(float* __restrict__ P, __half* __restrict__ Ph)
{
    const int row = blockIdx.x;
    const int q = row & (SEQ - 1);
    float* p = P + (long)row * SEQ;
    __half* ph = Ph + (long)row * SEQ;
    const int n = q + 1;
    const int tid = threadIdx.x;

    __shared__ float red[8];

    float m = -3.4e38f;
    for (int i = tid; i < n; i += 256) m = fmaxf(m, p[i]);
#pragma unroll
    for (int o = 16; o > 0; o >>= 1) m = fmaxf(m, __shfl_xor_sync(0xffffffffu, m, o));
    if ((tid & 31) == 0) red[tid >> 5] = m;
    __syncthreads();
    m = red[0];
#pragma unroll
    for (int w = 1; w < 8; w++) m = fmaxf(m, red[w]);
    __syncthreads();

    float s = 0.f;
    for (int i = tid; i < n; i += 256) {
        float e = __expf(p[i] - m);
        p[i] = e;
        s += e;
    }
#pragma unroll
    for (int o = 16; o > 0; o >>= 1) s += __shfl_xor_sync(0xffffffffu, s, o);
    if ((tid & 31) == 0) red[tid >> 5] = s;
    __syncthreads();
    float tot = red[0];
#pragma unroll
    for (int w = 1; w < 8; w++) tot += red[w];
    const float inv = 1.f / tot;

    for (int i = tid; i < n; i += 256)
        ph[i] = __float2half(p[i] * inv);
    const __half z = __float2half(0.f);
    for (int i = n + tid; i < SEQ; i += 256) ph[i] = z;
}

// ---------------------------------------------------------------------------
extern "C" void kernel_launch(void* const* d_in, const int* in_sizes, int n_in,
                              void* d_out, int out_size)
{
    (void)in_sizes; (void)n_in; (void)out_size;
    const float* xq = (const float*)d_in[0];
    const float* xk = (const float*)d_in[1];
    const float* xv = (const float*)d_in[2];
    const float* Wq = (const float*)d_in[3];
    const float* bq = (const float*)d_in[4];
    float* out = (float*)d_out;

    void *xq1, *xk1, *xv1, *W1, *Q1, *K1, *V1, *VT1, *P1, *Pf;
    cudaGetSymbolAddress(&xq1, g_xq1);
    cudaGetSymbolAddress(&xk1, g_xk1);
    cudaGetSymbolAddress(&xv1, g_xv1);
    cudaGetSymbolAddress(&W1, g_W1);
    cudaGetSymbolAddress(&Q1, g_Q1);
    cudaGetSymbolAddress(&K1, g_K1);
    cudaGetSymbolAddress(&V1, g_V1);
    cudaGetSymbolAddress(&VT1, g_VT1);
    cudaGetSymbolAddress(&P1, g_P1);
    cudaGetSymbolAddress(&Pf, g_Pf);

    auto kProj = gemm_f16<false, false, true, false>;   // fp16 out
    auto kQK   = gemm_f16<true,  false, false, true>;   // fp32 out
    auto kPV   = gemm_f16<false, true,  false, true>;   // fp32 out
    cudaFuncSetAttribute(kProj, cudaFuncAttributeMaxDynamicSharedMemorySize, SMEM_REQ);
    cudaFuncSetAttribute(kQK,   cudaFuncAttributeMaxDynamicSharedMemorySize, SMEM_REQ);
    cudaFuncSetAttribute(kPV,   cudaFuncAttributeMaxDynamicSharedMemorySize, SMEM_REQ);

    // 1) fp32 -> fp16 conversions
    cvtH3<<<dim3((unsigned)(NELEM / 4 / 256), 3), 256>>>(
        xq, xk, xv, (__half*)xq1, (__half*)xk1, (__half*)xv1, NELEM);
    cvtH3<<<dim3((unsigned)((long)EMB * EMB / 4 / 256), 1), 256>>>(
        Wq, nullptr, nullptr, (__half*)W1, nullptr, nullptr, (long)EMB * EMB);

    // 2) projections: Q/K/V = x @ W^T + b -> fp16
    {
        dim3 g(EMB / 64, MTOT / 128, 1);
        kProj<<<g, 128, SMEM_REQ>>>((const __half*)xq1, 0, (const __half*)W1, 0,
                                    EMB, 1.0f, bq, nullptr, (__half*)Q1, EMB, 0);
        kProj<<<g, 128, SMEM_REQ>>>((const __half*)xk1, 0, (const __half*)W1, 0,
                                    EMB, 1.0f, bq, nullptr, (__half*)K1, EMB, 0);
        kProj<<<g, 128, SMEM_REQ>>>((const __half*)xv1, 0, (const __half*)W1, 0,
                                    EMB, 1.0f, bq, nullptr, (__half*)V1, EMB, 0);
    }

    // 3) V transpose -> [B][E][S]
    transpose_f16<<<dim3(EMB / 32, SEQ / 32, BATCH), dim3(32, 8)>>>(
        (const __half*)V1, (__half*)VT1);

    // 4) scores = scale * Q @ K^T (causal tile skip) -> fp32
    {
        dim3 g(SEQ / 64, SEQ / 128, BATCH);
        kQK<<<g, 128, SMEM_REQ>>>((const __half*)Q1, (long)SEQ * EMB,
                                  (const __half*)K1, (long)SEQ * EMB,
                                  EMB, 0.03125f, nullptr,
                                  (float*)Pf, nullptr, SEQ, (long)SEQ * SEQ);
    }

    // 5) softmax -> fp16 probs
    softmax_causal<<<MTOT, 256>>>((float*)Pf, (__half*)P1);

    // 6) out = P @ VT^T (K-truncated, longest-first) -> fp32
    {
        dim3 g(EMB / 64, SEQ / 128, BATCH);
        kPV<<<g, 128, SMEM_REQ>>>((const __half*)P1, (long)SEQ * SEQ,
                                  (const __half*)VT1, (long)SEQ * EMB,
                                  SEQ, 1.0f, nullptr,
                                  out, nullptr, EMB, (long)SEQ * EMB);
    }
}

// round 9
// speedup vs baseline: 6.6358x; 1.0426x over previous
#include <cuda_runtime.h>
#include <cuda_fp16.h>
#include <cstdint>

#define BATCH 4
#define SEQ   2048
#define EMB   1024
#define MTOT  (BATCH * SEQ)                 // 8192
#define NELEM ((long)MTOT * EMB)            // 8388608
#define NP    ((long)BATCH * SEQ * SEQ)     // 16777216

// ---------------------------------------------------------------------------
// Scratch — packed fp16 planes.
// ---------------------------------------------------------------------------
__device__ __half g_x1[3 * NELEM];           // [xq | xk | xv] fp16
__device__ __half g_W1[(long)EMB * EMB];
__device__ __half g_QKV[3 * NELEM];          // [Q | K | V] fp16
__device__ __half g_VT1[NELEM];              // [B][E][S]
__device__ __half g_P1[NP];                  // un-normalized exp(s - m), fp16
__device__ float  g_invS[MTOT];              // per-row 1/sum
__device__ float  g_Pf[NP];                  // fp32 scores

// ---------------------------------------------------------------------------
__device__ __forceinline__ uint32_t smem_u32(const void* p) {
    uint32_t a;
    asm("{ .reg .u64 t; cvta.to.shared.u64 t, %1; cvt.u32.u64 %0, t; }" : "=r"(a) : "l"(p));
    return a;
}

#define LDSM4(r, addr) \
    asm volatile("ldmatrix.sync.aligned.m8n8.x4.shared.b16 {%0,%1,%2,%3}, [%4];" \
        : "=r"((r)[0]), "=r"((r)[1]), "=r"((r)[2]), "=r"((r)[3]) : "r"(addr))

#define MMA_F16(d, a, b0, b1) \
    asm volatile("mma.sync.aligned.m16n8k16.row.col.f32.f16.f16.f32 " \
        "{%0,%1,%2,%3}, {%4,%5,%6,%7}, {%8,%9}, {%0,%1,%2,%3};" \
        : "+f"((d)[0]), "+f"((d)[1]), "+f"((d)[2]), "+f"((d)[3]) \
        : "r"((a)[0]), "r"((a)[1]), "r"((a)[2]), "r"((a)[3]), "r"(b0), "r"(b1))

// CTA tile 128x64, BK=32. Stage: A 10240 + B 5120 = 15360 bytes.
// row pitch 80B (32 fp16 + 8 pad) -> ldmatrix conflict-free
#define STAGE_B   15360
#define SMEM_REQ  (2 * STAGE_B)

// ---------------------------------------------------------------------------
// Plain fp16 TC GEMM (fp32 accum): C[128x64] = alpha * A @ B^T (+ bias)
// 128 threads, 4 warps (2m x 2n), warp tile 64x32, 4 CTAs/SM.
// RSCALE: multiply output row r by invS[bz*SEQ + r] (deferred softmax norm).
// ---------------------------------------------------------------------------
template <bool CAUSAL, bool TRUNCK, bool BIAS, bool WF32, bool RSCALE>
__global__ void __launch_bounds__(128, 4)
gemm_f16(const __half* __restrict__ A, long strideAz,
         const __half* __restrict__ B, long strideBz,
         int K, float alpha, const float* __restrict__ bias,
         const float* __restrict__ invS,
         float* __restrict__ Cf, __half* __restrict__ Ch,
         int ldc, long strideCz)
{
    const int bx = blockIdx.x, bz = blockIdx.z;
    const int by = TRUNCK ? (gridDim.y - 1 - blockIdx.y) : blockIdx.y;
    if (CAUSAL && bx > 2 * by + 1) return;   // 64-col tile vs 128-row tile

    extern __shared__ char smem[];
    const uint32_t sbase = smem_u32(smem);

    const __half* Ab = A + (long)bz * strideAz;
    const __half* Bb = B + (long)bz * strideBz;

    const int tid = threadIdx.x, wid = tid >> 5, l = tid & 31;
    const int wr = wid >> 1, wc = wid & 1;     // warp 64m x 32n
    const int kEnd = TRUNCK ? min(K, (by + 1) * 128) : K;
    const int nst = kEnd >> 5;                 // BK=32 stages
    const int rowA0 = by * 128, rowB0 = bx * 64;

    float acc[4][4][4];
#pragma unroll
    for (int m = 0; m < 4; m++)
#pragma unroll
        for (int n = 0; n < 4; n++)
#pragma unroll
            for (int j = 0; j < 4; j++) acc[m][n][j] = 0.f;

    // 768 x 16B chunks per stage: A 512 (128 rows x 4 segs), B 256 (64 x 4)
#define LOAD_STAGE(sidx, buf) do { \
        const int k0_ = (sidx) * 32; \
        const uint32_t st_ = sbase + (buf) * STAGE_B; \
        _Pragma("unroll") \
        for (int i_ = 0; i_ < 6; i_++) { \
            int c_ = i_ * 128 + tid; \
            uint32_t dst_; const void* src_; \
            if (c_ < 512) { \
                int row_ = c_ >> 2, seg_ = c_ & 3; \
                dst_ = st_ + row_ * 80 + seg_ * 16; \
                src_ = Ab + (long)(rowA0 + row_) * K + k0_ + seg_ * 8; \
            } else { \
                int w_ = c_ - 512; \
                int row_ = w_ >> 2, seg_ = w_ & 3; \
                dst_ = st_ + 10240 + row_ * 80 + seg_ * 16; \
                src_ = Bb + (long)(rowB0 + row_) * K + k0_ + seg_ * 8; \
            } \
            asm volatile("cp.async.cg.shared.global [%0], [%1], 16;" :: "r"(dst_), "l"(src_)); \
        } \
        asm volatile("cp.async.commit_group;"); \
    } while (0)

    LOAD_STAGE(0, 0);

    const int lr = l & 15, lh = l >> 4;

    for (int s = 0; s < nst; s++) {
        const int b = s & 1;
        asm volatile("cp.async.wait_group 0;");
        __syncthreads();
        if (s + 1 < nst) LOAD_STAGE(s + 1, b ^ 1);

        const uint32_t st = sbase + b * STAGE_B;
#pragma unroll
        for (int kk = 0; kk < 32; kk += 16) {
            uint32_t AH[4][4], BH[2][4];
            const uint32_t kb = (kk + lh * 8) * 2;
#pragma unroll
            for (int mt = 0; mt < 4; mt++) {
                uint32_t a0 = st + (wr * 64 + mt * 16 + lr) * 80 + kb;
                LDSM4(AH[mt], a0);
            }
#pragma unroll
            for (int np = 0; np < 2; np++) {
                uint32_t b0 = st + 10240 + (wc * 32 + np * 16 + lr) * 80 + kb;
                LDSM4(BH[np], b0);
            }
#pragma unroll
            for (int mt = 0; mt < 4; mt++)
#pragma unroll
                for (int np = 0; np < 2; np++) {
                    MMA_F16(acc[mt][2 * np],     AH[mt], BH[np][0], BH[np][2]);
                    MMA_F16(acc[mt][2 * np + 1], AH[mt], BH[np][1], BH[np][3]);
                }
        }
    }
#undef LOAD_STAGE

    // --- epilogue ---
    const int rql = l >> 2, cpl = (l & 3) * 2;
#pragma unroll
    for (int mt = 0; mt < 4; mt++) {
        const long row = (long)by * 128 + wr * 64 + mt * 16 + rql;
        float s0 = 1.f, s1 = 1.f;
        if (RSCALE) {
            s0 = invS[(long)bz * SEQ + row];
            s1 = invS[(long)bz * SEQ + row + 8];
        }
#pragma unroll
        for (int nt = 0; nt < 4; nt++) {
            const int col = bx * 64 + wc * 32 + nt * 8 + cpl;
            float v0 = acc[mt][nt][0] * alpha, v1 = acc[mt][nt][1] * alpha;
            float v2 = acc[mt][nt][2] * alpha, v3 = acc[mt][nt][3] * alpha;
            if (RSCALE) { v0 *= s0; v1 *= s0; v2 *= s1; v3 *= s1; }
            if (BIAS) {
                float b0 = bias[col], b1 = bias[col + 1];
                v0 += b0; v1 += b1; v2 += b0; v3 += b1;
            }
            const long o0 = (long)bz * strideCz + row * ldc + col;
            const long o1 = o0 + 8L * ldc;
            if (WF32) {
                *reinterpret_cast<float2*>(Cf + o0) = make_float2(v0, v1);
                *reinterpret_cast<float2*>(Cf + o1) = make_float2(v2, v3);
            } else {
                __half h0 = __float2half(v0), h1 = __float2half(v1);
                __half h2 = __float2half(v2), h3 = __float2half(v3);
                uint32_t hA = (uint32_t)__half_as_ushort(h0) | ((uint32_t)__half_as_ushort(h1) << 16);
                uint32_t hB = (uint32_t)__half_as_ushort(h2) | ((uint32_t)__half_as_ushort(h3) << 16);
                *reinterpret_cast<uint32_t*>(Ch + o0) = hA;
                *reinterpret_cast<uint32_t*>(Ch + o1) = hB;
            }
        }
    }
}

// ---------------------------------------------------------------------------
// fp32 -> fp16; y-dim selects among up to 3 arrays
// ---------------------------------------------------------------------------
__global__ void __launch_bounds__(256) cvtH3(const float* __restrict__ i0,
                                             const float* __restrict__ i1,
                                             const float* __restrict__ i2,
                                             __half* __restrict__ o0,
                                             __half* __restrict__ o1,
                                             __half* __restrict__ o2,
                                             long n)
{
    const float* in = (blockIdx.y == 0) ? i0 : (blockIdx.y == 1) ? i1 : i2;
    __half* out = (blockIdx.y == 0) ? o0 : (blockIdx.y == 1) ? o1 : o2;
    long i = ((long)blockIdx.x * 256 + threadIdx.x) * 4;
    if (i >= n) return;
    float4 v = *reinterpret_cast<const float4*>(in + i);
    __half h0 = __float2half(v.x), h1 = __float2half(v.y);
    __half h2 = __float2half(v.z), h3 = __float2half(v.w);
    uint32_t hA = (uint32_t)__half_as_ushort(h0) | ((uint32_t)__half_as_ushort(h1) << 16);
    uint32_t hB = (uint32_t)__half_as_ushort(h2) | ((uint32_t)__half_as_ushort(h3) << 16);
    *reinterpret_cast<uint2*>(out + i) = make_uint2(hA, hB);
}

// ---------------------------------------------------------------------------
// fp16 transpose: [B][S][E] -> [B][E][S]
// ---------------------------------------------------------------------------
__global__ void __launch_bounds__(256) transpose_f16(const __half* __restrict__ in,
                                                     const __half* __restrict__ /*unused*/,
                                                     __half* __restrict__ out)
{
    __shared__ unsigned short t[32][33];
    const int b = blockIdx.z;
    const long off = (long)b * SEQ * EMB;
    const unsigned short* ip = reinterpret_cast<const unsigned short*>(in) + off;
    unsigned short* op = reinterpret_cast<unsigned short*>(out) + off;
    const int c0 = blockIdx.x * 32, r0 = blockIdx.y * 32;
    for (int i = threadIdx.y; i < 32; i += 8)
        t[i][threadIdx.x] = ip[(long)(r0 + i) * EMB + c0 + threadIdx.x];
    __syncthreads();
    for (int i = threadIdx.y; i < 32; i += 8)
        op[(long)(c0 + i) * SEQ + r0 + threadIdx.x] = t[threadIdx.x][i];
}

// ---------------------------------------------------------------------------
// Causal softmax, 2 passes: max; exp -> fp16 (un-normalized) + invS store.
// Zero-fills only the diagonal-tile remainder (PV never reads past it).
// ---------------------------------------------------------------------------
__global__ void __launch_bounds__(256)
softmax_causal(const float* __restrict__ P, __half* __restrict__ Ph,
               float* __restrict__ invS)
{
    const int row = blockIdx.x;
    const int q = row & (SEQ - 1);
    const float* p = P + (long)row * SEQ;
    __half* ph = Ph + (long)row * SEQ;
    const int n = q + 1;
    const int nTile = ((q >> 7) + 1) << 7;     // PV k-loop end for this row
    const int tid = threadIdx.x;

    __shared__ float red[8];

    float m = -3.4e38f;
    for (int i = tid; i < n; i += 256) m = fmaxf(m, p[i]);
#pragma unroll
    for (int o = 16; o > 0; o >>= 1) m = fmaxf(m, __shfl_xor_sync(0xffffffffu, m, o));
    if ((tid & 31) == 0) red[tid >> 5] = m;
    __syncthreads();
    m = red[0];
#pragma unroll
    for (int w = 1; w < 8; w++) m = fmaxf(m, red[w]);
    __syncthreads();

    float s = 0.f;
    for (int i = tid; i < n; i += 256) {
        float e = __expf(p[i] - m);
        ph[i] = __float2half(e);
        s += e;
    }
#pragma unroll
    for (int o = 16; o > 0; o >>= 1) s += __shfl_xor_sync(0xffffffffu, s, o);
    if ((tid & 31) == 0) red[tid >> 5] = s;
    __syncthreads();
    if (tid == 0) {
        float tot = red[0];
#pragma unroll
        for (int w = 1; w < 8; w++) tot += red[w];
        invS[row] = 1.f / tot;
    }
    const __half z = __float2half(0.f);
    for (int i = n + tid; i < nTile; i += 256) ph[i] = z;
}

// ---------------------------------------------------------------------------
extern "C" void kernel_launch(void* const* d_in, const int* in_sizes, int n_in,
                              void* d_out, int out_size)
{
    (void)in_sizes; (void)n_in; (void)out_size;
    const float* xq = (const float*)d_in[0];
    const float* xk = (const float*)d_in[1];
    const float* xv = (const float*)d_in[2];
    const float* Wq = (const float*)d_in[3];
    const float* bq = (const float*)d_in[4];
    float* out = (float*)d_out;

    void *x1, *W1, *QKV, *VT1, *P1, *invS, *Pf;
    cudaGetSymbolAddress(&x1, g_x1);
    cudaGetSymbolAddress(&W1, g_W1);
    cudaGetSymbolAddress(&QKV, g_QKV);
    cudaGetSymbolAddress(&VT1, g_VT1);
    cudaGetSymbolAddress(&P1, g_P1);
    cudaGetSymbolAddress(&invS, g_invS);
    cudaGetSymbolAddress(&Pf, g_Pf);

    __half* X = (__half*)x1;
    __half* Q1 = (__half*)QKV;
    __half* K1 = Q1 + NELEM;
    __half* V1 = Q1 + 2 * NELEM;

    auto kProj = gemm_f16<false, false, true, false, false>;   // fp16 out
    auto kQK   = gemm_f16<true,  false, false, true, false>;   // fp32 out
    auto kPV   = gemm_f16<false, true,  false, true, true>;    // fp32 out, row-scale
    cudaFuncSetAttribute(kProj, cudaFuncAttributeMaxDynamicSharedMemorySize, SMEM_REQ);
    cudaFuncSetAttribute(kQK,   cudaFuncAttributeMaxDynamicSharedMemorySize, SMEM_REQ);
    cudaFuncSetAttribute(kPV,   cudaFuncAttributeMaxDynamicSharedMemorySize, SMEM_REQ);

    // 1) fp32 -> fp16 conversions
    cvtH3<<<dim3((unsigned)(NELEM / 4 / 256), 3), 256>>>(
        xq, xk, xv, X, X + NELEM, X + 2 * NELEM, NELEM);
    cvtH3<<<dim3((unsigned)((long)EMB * EMB / 4 / 256), 1), 256>>>(
        Wq, nullptr, nullptr, (__half*)W1, nullptr, nullptr, (long)EMB * EMB);

    // 2) one launch: Q/K/V = x @ W^T + b -> fp16 (z selects input/output plane)
    {
        dim3 g(EMB / 64, MTOT / 128, 3);
        kProj<<<g, 128, SMEM_REQ>>>(X, NELEM, (const __half*)W1, 0,
                                    EMB, 1.0f, bq, nullptr,
                                    nullptr, Q1, EMB, NELEM);
    }

    // 3) V transpose -> [B][E][S]
    transpose_f16<<<dim3(EMB / 32, SEQ / 32, BATCH), dim3(32, 8)>>>(
        V1, nullptr, (__half*)VT1);

    // 4) scores = scale * Q @ K^T (causal tile skip) -> fp32
    {
        dim3 g(SEQ / 64, SEQ / 128, BATCH);
        kQK<<<g, 128, SMEM_REQ>>>(Q1, (long)SEQ * EMB, K1, (long)SEQ * EMB,
                                  EMB, 0.03125f, nullptr, nullptr,
                                  (float*)Pf, nullptr, SEQ, (long)SEQ * SEQ);
    }

    // 5) softmax (2 passes) -> fp16 un-normalized exp + invS
    softmax_causal<<<MTOT, 256>>>((const float*)Pf, (__half*)P1, (float*)invS);

    // 6) out = invS * (E @ VT^T) (K-truncated, longest-first) -> fp32
    {
        dim3 g(EMB / 64, SEQ / 128, BATCH);
        kPV<<<g, 128, SMEM_REQ>>>((const __half*)P1, (long)SEQ * SEQ,
                                  (const __half*)VT1, (long)SEQ * EMB,
                                  SEQ, 1.0f, nullptr, (const float*)invS,
                                  out, nullptr, EMB, (long)SEQ * EMB);
    }
}

// round 11
// speedup vs baseline: 6.9144x; 1.0420x over previous
#include <cuda_runtime.h>
#include <cuda_fp16.h>
#include <cstdint>

#define BATCH 4
#define SEQ   2048
#define EMB   1024
#define MTOT  (BATCH * SEQ)                 // 8192
#define NELEM ((long)MTOT * EMB)            // 8388608
#define NP    ((long)BATCH * SEQ * SEQ)     // 16777216

// ---------------------------------------------------------------------------
// Scratch — packed fp16 planes. No fp32 score buffer.
// ---------------------------------------------------------------------------
__device__ __half g_x1[3 * NELEM];           // [xq | xk | xv] fp16
__device__ __half g_W1[(long)EMB * EMB];
__device__ __half g_QKV[3 * NELEM];          // [Q | K | V] fp16
__device__ __half g_VT1[NELEM];              // [B][E][S]
__device__ __half g_P1[NP];                  // un-normalized exp(s), fp16
__device__ float  g_part[(long)MTOT * 32];   // per-(row, col-tile) partial sums
__device__ float  g_invS[MTOT];              // per-row 1/sum

// ---------------------------------------------------------------------------
__device__ __forceinline__ uint32_t smem_u32(const void* p) {
    uint32_t a;
    asm("{ .reg .u64 t; cvta.to.shared.u64 t, %1; cvt.u32.u64 %0, t; }" : "=r"(a) : "l"(p));
    return a;
}

#define LDSM4(r, addr) \
    asm volatile("ldmatrix.sync.aligned.m8n8.x4.shared.b16 {%0,%1,%2,%3}, [%4];" \
        : "=r"((r)[0]), "=r"((r)[1]), "=r"((r)[2]), "=r"((r)[3]) : "r"(addr))

#define MMA_F16(d, a, b0, b1) \
    asm volatile("mma.sync.aligned.m16n8k16.row.col.f32.f16.f16.f32 " \
        "{%0,%1,%2,%3}, {%4,%5,%6,%7}, {%8,%9}, {%0,%1,%2,%3};" \
        : "+f"((d)[0]), "+f"((d)[1]), "+f"((d)[2]), "+f"((d)[3]) \
        : "r"((a)[0]), "r"((a)[1]), "r"((a)[2]), "r"((a)[3]), "r"(b0), "r"(b1))

// CTA tile 128x64, BK=32. Stage: A 10240 + B 5120 = 15360 bytes.
#define STAGE_B   15360
#define SMEM_REQ  (2 * STAGE_B)

// ---------------------------------------------------------------------------
// fp16 TC GEMM (fp32 accum): 128x64 tile, 4 warps (2m x 2n), 4 CTAs/SM.
// EXP: QK mode — epilogue does exp + causal mask + fp16 store + row partials.
// RSCALE: PV mode — multiply row r by invS[bz*SEQ+r].
// ---------------------------------------------------------------------------
template <bool CAUSAL, bool TRUNCK, bool BIAS, bool WF32, bool RSCALE, bool EXP>
__global__ void __launch_bounds__(128, 4)
gemm_f16(const __half* __restrict__ A, long strideAz,
         const __half* __restrict__ B, long strideBz,
         int K, float alpha, const float* __restrict__ bias,
         const float* __restrict__ invS, float* __restrict__ part,
         float* __restrict__ Cf, __half* __restrict__ Ch,
         int ldc, long strideCz)
{
    const int bx = blockIdx.x, bz = blockIdx.z;
    const int by = TRUNCK ? (gridDim.y - 1 - blockIdx.y) : blockIdx.y;
    if (CAUSAL && bx > 2 * by + 1) return;

    extern __shared__ char smem[];
    const uint32_t sbase = smem_u32(smem);

    const __half* Ab = A + (long)bz * strideAz;
    const __half* Bb = B + (long)bz * strideBz;

    const int tid = threadIdx.x, wid = tid >> 5, l = tid & 31;
    const int wr = wid >> 1, wc = wid & 1;
    const int kEnd = TRUNCK ? min(K, (by + 1) * 128) : K;
    const int nst = kEnd >> 5;
    const int rowA0 = by * 128, rowB0 = bx * 64;

    float acc[4][4][4];
#pragma unroll
    for (int m = 0; m < 4; m++)
#pragma unroll
        for (int n = 0; n < 4; n++)
#pragma unroll
            for (int j = 0; j < 4; j++) acc[m][n][j] = 0.f;

#define LOAD_STAGE(sidx, buf) do { \
        const int k0_ = (sidx) * 32; \
        const uint32_t st_ = sbase + (buf) * STAGE_B; \
        _Pragma("unroll") \
        for (int i_ = 0; i_ < 6; i_++) { \
            int c_ = i_ * 128 + tid; \
            uint32_t dst_; const void* src_; \
            if (c_ < 512) { \
                int row_ = c_ >> 2, seg_ = c_ & 3; \
                dst_ = st_ + row_ * 80 + seg_ * 16; \
                src_ = Ab + (long)(rowA0 + row_) * K + k0_ + seg_ * 8; \
            } else { \
                int w_ = c_ - 512; \
                int row_ = w_ >> 2, seg_ = w_ & 3; \
                dst_ = st_ + 10240 + row_ * 80 + seg_ * 16; \
                src_ = Bb + (long)(rowB0 + row_) * K + k0_ + seg_ * 8; \
            } \
            asm volatile("cp.async.cg.shared.global [%0], [%1], 16;" :: "r"(dst_), "l"(src_)); \
        } \
        asm volatile("cp.async.commit_group;"); \
    } while (0)

    LOAD_STAGE(0, 0);

    const int lr = l & 15, lh = l >> 4;

    for (int s = 0; s < nst; s++) {
        const int b = s & 1;
        asm volatile("cp.async.wait_group 0;");
        __syncthreads();
        if (s + 1 < nst) LOAD_STAGE(s + 1, b ^ 1);

        const uint32_t st = sbase + b * STAGE_B;
#pragma unroll
        for (int kk = 0; kk < 32; kk += 16) {
            uint32_t AH[4][4], BH[2][4];
            const uint32_t kb = (kk + lh * 8) * 2;
#pragma unroll
            for (int mt = 0; mt < 4; mt++) {
                uint32_t a0 = st + (wr * 64 + mt * 16 + lr) * 80 + kb;
                LDSM4(AH[mt], a0);
            }
#pragma unroll
            for (int np = 0; np < 2; np++) {
                uint32_t b0 = st + 10240 + (wc * 32 + np * 16 + lr) * 80 + kb;
                LDSM4(BH[np], b0);
            }
#pragma unroll
            for (int mt = 0; mt < 4; mt++)
#pragma unroll
                for (int np = 0; np < 2; np++) {
                    MMA_F16(acc[mt][2 * np],     AH[mt], BH[np][0], BH[np][2]);
                    MMA_F16(acc[mt][2 * np + 1], AH[mt], BH[np][1], BH[np][3]);
                }
        }
    }
#undef LOAD_STAGE

    const int rql = l >> 2, cpl = (l & 3) * 2;

    if (EXP) {
        // ---- QK epilogue: exp + causal mask + fp16 store + row partials ----
        __syncthreads();                       // stage smem free for reuse
        float* partS = reinterpret_cast<float*>(smem);   // [2][128]
#pragma unroll
        for (int mt = 0; mt < 4; mt++) {
            const int rl = wr * 64 + mt * 16 + rql;      // local row 0..127
            const int grow = by * 128 + rl;              // row within seq
            float p0 = 0.f, p1 = 0.f;
#pragma unroll
            for (int nt = 0; nt < 4; nt++) {
                const int col = bx * 64 + wc * 32 + nt * 8 + cpl;
                float e0 = (col     <= grow)     ? __expf(acc[mt][nt][0] * alpha) : 0.f;
                float e1 = (col + 1 <= grow)     ? __expf(acc[mt][nt][1] * alpha) : 0.f;
                float e2 = (col     <= grow + 8) ? __expf(acc[mt][nt][2] * alpha) : 0.f;
                float e3 = (col + 1 <= grow + 8) ? __expf(acc[mt][nt][3] * alpha) : 0.f;
                __half h0 = __float2half(e0), h1 = __float2half(e1);
                __half h2 = __float2half(e2), h3 = __float2half(e3);
                const long o0 = (long)bz * strideCz + (long)grow * ldc + col;
                *reinterpret_cast<uint32_t*>(Ch + o0) =
                    (uint32_t)__half_as_ushort(h0) | ((uint32_t)__half_as_ushort(h1) << 16);
                *reinterpret_cast<uint32_t*>(Ch + o0 + 8L * ldc) =
                    (uint32_t)__half_as_ushort(h2) | ((uint32_t)__half_as_ushort(h3) << 16);
                p0 += e0 + e1;
                p1 += e2 + e3;
            }
            p0 += __shfl_xor_sync(0xffffffffu, p0, 1);
            p0 += __shfl_xor_sync(0xffffffffu, p0, 2);
            p1 += __shfl_xor_sync(0xffffffffu, p1, 1);
            p1 += __shfl_xor_sync(0xffffffffu, p1, 2);
            if ((l & 3) == 0) {
                partS[wc * 128 + rl] = p0;
                partS[wc * 128 + rl + 8] = p1;
            }
        }
        __syncthreads();
        if (tid < 128) {
            float sv = partS[tid] + partS[128 + tid];
            part[((long)bz * SEQ + by * 128 + tid) * 32 + bx] = sv;
        }
        return;
    }

    // ---- standard epilogue ----
#pragma unroll
    for (int mt = 0; mt < 4; mt++) {
        const long row = (long)by * 128 + wr * 64 + mt * 16 + rql;
        float s0 = 1.f, s1 = 1.f;
        if (RSCALE) {
            s0 = invS[(long)bz * SEQ + row];
            s1 = invS[(long)bz * SEQ + row + 8];
        }
#pragma unroll
        for (int nt = 0; nt < 4; nt++) {
            const int col = bx * 64 + wc * 32 + nt * 8 + cpl;
            float v0 = acc[mt][nt][0] * alpha, v1 = acc[mt][nt][1] * alpha;
            float v2 = acc[mt][nt][2] * alpha, v3 = acc[mt][nt][3] * alpha;
            if (RSCALE) { v0 *= s0; v1 *= s0; v2 *= s1; v3 *= s1; }
            if (BIAS) {
                float b0 = bias[col], b1 = bias[col + 1];
                v0 += b0; v1 += b1; v2 += b0; v3 += b1;
            }
            const long o0 = (long)bz * strideCz + row * ldc + col;
            const long o1 = o0 + 8L * ldc;
            if (WF32) {
                *reinterpret_cast<float2*>(Cf + o0) = make_float2(v0, v1);
                *reinterpret_cast<float2*>(Cf + o1) = make_float2(v2, v3);
            } else {
                __half h0 = __float2half(v0), h1 = __float2half(v1);
                __half h2 = __float2half(v2), h3 = __float2half(v3);
                *reinterpret_cast<uint32_t*>(Ch + o0) =
                    (uint32_t)__half_as_ushort(h0) | ((uint32_t)__half_as_ushort(h1) << 16);
                *reinterpret_cast<uint32_t*>(Ch + o1) =
                    (uint32_t)__half_as_ushort(h2) | ((uint32_t)__half_as_ushort(h3) << 16);
            }
        }
    }
}

// ---------------------------------------------------------------------------
// fp32 -> fp16; y-dim selects among up to 3 arrays
// ---------------------------------------------------------------------------
__global__ void __launch_bounds__(256) cvtH3(const float* __restrict__ i0,
                                             const float* __restrict__ i1,
                                             const float* __restrict__ i2,
                                             __half* __restrict__ o0,
                                             __half* __restrict__ o1,
                                             __half* __restrict__ o2,
                                             long n)
{
    const float* in = (blockIdx.y == 0) ? i0 : (blockIdx.y == 1) ? i1 : i2;
    __half* out = (blockIdx.y == 0) ? o0 : (blockIdx.y == 1) ? o1 : o2;
    long i = ((long)blockIdx.x * 256 + threadIdx.x) * 4;
    if (i >= n) return;
    float4 v = *reinterpret_cast<const float4*>(in + i);
    __half h0 = __float2half(v.x), h1 = __float2half(v.y);
    __half h2 = __float2half(v.z), h3 = __float2half(v.w);
    uint32_t hA = (uint32_t)__half_as_ushort(h0) | ((uint32_t)__half_as_ushort(h1) << 16);
    uint32_t hB = (uint32_t)__half_as_ushort(h2) | ((uint32_t)__half_as_ushort(h3) << 16);
    *reinterpret_cast<uint2*>(out + i) = make_uint2(hA, hB);
}

// ---------------------------------------------------------------------------
// Vectorized fp16 transpose: 64x64 tiles, uint4 global accesses, FULL tile
// (2 iterations x 256 threads x 16B = 8KB). [B][S][E] -> [B][E][S]
// ---------------------------------------------------------------------------
__global__ void __launch_bounds__(256) transpose_f16v(const __half* __restrict__ in,
                                                      __half* __restrict__ out)
{
    __shared__ unsigned short sm[64][65];
    const int b = blockIdx.z;
    const unsigned short* ip = reinterpret_cast<const unsigned short*>(in) + (long)b * SEQ * EMB;
    unsigned short* op = reinterpret_cast<unsigned short*>(out) + (long)b * SEQ * EMB;
    const int c0 = blockIdx.x * 64, r0 = blockIdx.y * 64;
    const int t = threadIdx.x;
    const int seg = t & 7;          // 8 x 8 halves = 64 cols
#pragma unroll
    for (int it = 0; it < 2; it++) {
        const int r = it * 32 + (t >> 3);
        uint4 v = *reinterpret_cast<const uint4*>(ip + (long)(r0 + r) * EMB + c0 + seg * 8);
        unsigned short* d = &sm[r][seg * 8];
        d[0] = (unsigned short)(v.x & 0xffff); d[1] = (unsigned short)(v.x >> 16);
        d[2] = (unsigned short)(v.y & 0xffff); d[3] = (unsigned short)(v.y >> 16);
        d[4] = (unsigned short)(v.z & 0xffff); d[5] = (unsigned short)(v.z >> 16);
        d[6] = (unsigned short)(v.w & 0xffff); d[7] = (unsigned short)(v.w >> 16);
    }
    __syncthreads();
#pragma unroll
    for (int it = 0; it < 2; it++) {
        const int c = it * 32 + (t >> 3);
        unsigned short e[8];
#pragma unroll
        for (int j = 0; j < 8; j++) e[j] = sm[seg * 8 + j][c];
        uint4 v;
        v.x = (uint32_t)e[0] | ((uint32_t)e[1] << 16);
        v.y = (uint32_t)e[2] | ((uint32_t)e[3] << 16);
        v.z = (uint32_t)e[4] | ((uint32_t)e[5] << 16);
        v.w = (uint32_t)e[6] | ((uint32_t)e[7] << 16);
        *reinterpret_cast<uint4*>(op + (long)(c0 + c) * SEQ + r0 + seg * 8) = v;
    }
}

// ---------------------------------------------------------------------------
// Sum the valid col-tile partials per row, invert.
// ---------------------------------------------------------------------------
__global__ void __launch_bounds__(256) reduce_invS(const float* __restrict__ part,
                                                   float* __restrict__ invS)
{
    const int r = blockIdx.x * 256 + threadIdx.x;
    if (r >= MTOT) return;
    const int q = r & (SEQ - 1);
    const int ntile = (q >> 6) + 1;            // 64-wide col tiles with data
    const float* p = part + (long)r * 32;
    float s = 0.f;
    for (int i = 0; i < ntile; i++) s += p[i];
    invS[r] = 1.f / s;
}

// ---------------------------------------------------------------------------
extern "C" void kernel_launch(void* const* d_in, const int* in_sizes, int n_in,
                              void* d_out, int out_size)
{
    (void)in_sizes; (void)n_in; (void)out_size;
    const float* xq = (const float*)d_in[0];
    const float* xk = (const float*)d_in[1];
    const float* xv = (const float*)d_in[2];
    const float* Wq = (const float*)d_in[3];
    const float* bq = (const float*)d_in[4];
    float* out = (float*)d_out;

    void *x1, *W1, *QKV, *VT1, *P1, *part, *invS;
    cudaGetSymbolAddress(&x1, g_x1);
    cudaGetSymbolAddress(&W1, g_W1);
    cudaGetSymbolAddress(&QKV, g_QKV);
    cudaGetSymbolAddress(&VT1, g_VT1);
    cudaGetSymbolAddress(&P1, g_P1);
    cudaGetSymbolAddress(&part, g_part);
    cudaGetSymbolAddress(&invS, g_invS);

    __half* X = (__half*)x1;
    __half* Q1 = (__half*)QKV;
    __half* K1 = Q1 + NELEM;
    __half* V1 = Q1 + 2 * NELEM;

    auto kProj = gemm_f16<false, false, true, false, false, false>;  // fp16 out
    auto kQK   = gemm_f16<true,  false, false, false, false, true>;  // exp epilogue
    auto kPV   = gemm_f16<false, true,  false, true,  true,  false>; // fp32 out, row-scale
    cudaFuncSetAttribute(kProj, cudaFuncAttributeMaxDynamicSharedMemorySize, SMEM_REQ);
    cudaFuncSetAttribute(kQK,   cudaFuncAttributeMaxDynamicSharedMemorySize, SMEM_REQ);
    cudaFuncSetAttribute(kPV,   cudaFuncAttributeMaxDynamicSharedMemorySize, SMEM_REQ);

    // 1) fp32 -> fp16 conversions
    cvtH3<<<dim3((unsigned)(NELEM / 4 / 256), 3), 256>>>(
        xq, xk, xv, X, X + NELEM, X + 2 * NELEM, NELEM);
    cvtH3<<<dim3((unsigned)((long)EMB * EMB / 4 / 256), 1), 256>>>(
        Wq, nullptr, nullptr, (__half*)W1, nullptr, nullptr, (long)EMB * EMB);

    // 2) one launch: Q/K/V = x @ W^T + b -> fp16
    {
        dim3 g(EMB / 64, MTOT / 128, 3);
        kProj<<<g, 128, SMEM_REQ>>>(X, NELEM, (const __half*)W1, 0,
                                    EMB, 1.0f, bq, nullptr, nullptr,
                                    nullptr, Q1, EMB, NELEM);
    }

    // 3) V transpose -> [B][E][S]
    transpose_f16v<<<dim3(EMB / 64, SEQ / 64, BATCH), 256>>>(V1, (__half*)VT1);

    // 4) QK + exp + mask + partial sums (no fp32 score buffer)
    {
        dim3 g(SEQ / 64, SEQ / 128, BATCH);
        kQK<<<g, 128, SMEM_REQ>>>(Q1, (long)SEQ * EMB, K1, (long)SEQ * EMB,
                                  EMB, 0.03125f, nullptr, nullptr, (float*)part,
                                  nullptr, (__half*)P1, SEQ, (long)SEQ * SEQ);
    }

    // 5) invS = 1 / row-sum
    reduce_invS<<<MTOT / 256, 256>>>((const float*)part, (float*)invS);

    // 6) out = invS * (E @ VT^T) (K-truncated, longest-first) -> fp32
    {
        dim3 g(EMB / 64, SEQ / 128, BATCH);
        kPV<<<g, 128, SMEM_REQ>>>((const __half*)P1, (long)SEQ * SEQ,
                                  (const __half*)VT1, (long)SEQ * EMB,
                                  SEQ, 1.0f, nullptr, (const float*)invS, nullptr,
                                  out, nullptr, EMB, (long)SEQ * EMB);
    }
}

// round 12
// speedup vs baseline: 7.1053x; 1.0276x over previous
#include <cuda_runtime.h>
#include <cuda_fp16.h>
#include <cstdint>

#define BATCH 4
#define SEQ   2048
#define EMB   1024
#define MTOT  (BATCH * SEQ)                 // 8192
#define NELEM ((long)MTOT * EMB)            // 8388608
#define NP    ((long)BATCH * SEQ * SEQ)     // 16777216

// ---------------------------------------------------------------------------
// Scratch — packed fp16 planes. No fp32 score buffer, no VT buffer.
// ---------------------------------------------------------------------------
__device__ __half g_x1[3 * NELEM];           // [xq | xk | xv] fp16
__device__ __half g_W1[(long)EMB * EMB];
__device__ __half g_QKV[3 * NELEM];          // [Q | K | V] fp16
__device__ __half g_P1[NP];                  // un-normalized exp(s), fp16
__device__ float  g_part[(long)MTOT * 32];   // per-(row, col-tile) partial sums
__device__ float  g_invS[MTOT];              // per-row 1/sum

// ---------------------------------------------------------------------------
__device__ __forceinline__ uint32_t smem_u32(const void* p) {
    uint32_t a;
    asm("{ .reg .u64 t; cvta.to.shared.u64 t, %1; cvt.u32.u64 %0, t; }" : "=r"(a) : "l"(p));
    return a;
}

#define LDSM4(r, addr) \
    asm volatile("ldmatrix.sync.aligned.m8n8.x4.shared.b16 {%0,%1,%2,%3}, [%4];" \
        : "=r"((r)[0]), "=r"((r)[1]), "=r"((r)[2]), "=r"((r)[3]) : "r"(addr))

#define LDSM4_T(r, addr) \
    asm volatile("ldmatrix.sync.aligned.m8n8.x4.trans.shared.b16 {%0,%1,%2,%3}, [%4];" \
        : "=r"((r)[0]), "=r"((r)[1]), "=r"((r)[2]), "=r"((r)[3]) : "r"(addr))

#define MMA_F16(d, a, b0, b1) \
    asm volatile("mma.sync.aligned.m16n8k16.row.col.f32.f16.f16.f32 " \
        "{%0,%1,%2,%3}, {%4,%5,%6,%7}, {%8,%9}, {%0,%1,%2,%3};" \
        : "+f"((d)[0]), "+f"((d)[1]), "+f"((d)[2]), "+f"((d)[3]) \
        : "r"((a)[0]), "r"((a)[1]), "r"((a)[2]), "r"((a)[3]), "r"(b0), "r"(b1))

// CTA tile 128x64, BK=32.
// A tile: 128 rows x 80B (32 fp16 + pad) = 10240.
// B tile: [N][K] mode 64 x 80B = 5120; [K][N] (TRB) mode 32 x 144B = 4608.
#define STAGE_B   15360
#define SMEM_REQ  (2 * STAGE_B)

// ---------------------------------------------------------------------------
// fp16 TC GEMM (fp32 accum): 128x64 tile, 4 warps (2m x 2n), 4 CTAs/SM.
// EXP: QK mode — epilogue does exp + causal mask + fp16 store + row partials.
// RSCALE: PV mode — multiply row r by invS[bz*SEQ+r].
// TRB: B stored [K][N] row-major (V direct); fragments via ldmatrix.trans.
// ---------------------------------------------------------------------------
template <bool CAUSAL, bool TRUNCK, bool BIAS, bool WF32, bool RSCALE, bool EXP, bool TRB>
__global__ void __launch_bounds__(128, 4)
gemm_f16(const __half* __restrict__ A, long strideAz,
         const __half* __restrict__ B, long strideBz, int ldb,
         int K, float alpha, const float* __restrict__ bias,
         const float* __restrict__ invS, float* __restrict__ part,
         float* __restrict__ Cf, __half* __restrict__ Ch,
         int ldc, long strideCz)
{
    const int bx = blockIdx.x, bz = blockIdx.z;
    const int by = TRUNCK ? (gridDim.y - 1 - blockIdx.y) : blockIdx.y;
    if (CAUSAL && bx > 2 * by + 1) return;

    extern __shared__ char smem[];
    const uint32_t sbase = smem_u32(smem);

    const __half* Ab = A + (long)bz * strideAz;
    const __half* Bb = B + (long)bz * strideBz;

    const int tid = threadIdx.x, wid = tid >> 5, l = tid & 31;
    const int wr = wid >> 1, wc = wid & 1;
    const int kEnd = TRUNCK ? min(K, (by + 1) * 128) : K;
    const int nst = kEnd >> 5;
    const int rowA0 = by * 128, rowB0 = bx * 64;

    float acc[4][4][4];
#pragma unroll
    for (int m = 0; m < 4; m++)
#pragma unroll
        for (int n = 0; n < 4; n++)
#pragma unroll
            for (int j = 0; j < 4; j++) acc[m][n][j] = 0.f;

    // 768 x 16B chunks per stage: A 512; B 256 (64x4 [N][K] or 32x8 [K][N])
#define LOAD_STAGE(sidx, buf) do { \
        const int k0_ = (sidx) * 32; \
        const uint32_t st_ = sbase + (buf) * STAGE_B; \
        _Pragma("unroll") \
        for (int i_ = 0; i_ < 6; i_++) { \
            int c_ = i_ * 128 + tid; \
            uint32_t dst_; const void* src_; \
            if (c_ < 512) { \
                int row_ = c_ >> 2, seg_ = c_ & 3; \
                dst_ = st_ + row_ * 80 + seg_ * 16; \
                src_ = Ab + (long)(rowA0 + row_) * K + k0_ + seg_ * 8; \
            } else if (TRB) { \
                int w_ = c_ - 512; \
                int row_ = w_ >> 3, seg_ = w_ & 7; \
                dst_ = st_ + 10240 + row_ * 144 + seg_ * 16; \
                src_ = Bb + (long)(k0_ + row_) * ldb + rowB0 + seg_ * 8; \
            } else { \
                int w_ = c_ - 512; \
                int row_ = w_ >> 2, seg_ = w_ & 3; \
                dst_ = st_ + 10240 + row_ * 80 + seg_ * 16; \
                src_ = Bb + (long)(rowB0 + row_) * ldb + k0_ + seg_ * 8; \
            } \
            asm volatile("cp.async.cg.shared.global [%0], [%1], 16;" :: "r"(dst_), "l"(src_)); \
        } \
        asm volatile("cp.async.commit_group;"); \
    } while (0)

    LOAD_STAGE(0, 0);

    const int lr = l & 15, lh = l >> 4;

    for (int s = 0; s < nst; s++) {
        const int b = s & 1;
        asm volatile("cp.async.wait_group 0;");
        __syncthreads();
        if (s + 1 < nst) LOAD_STAGE(s + 1, b ^ 1);

        const uint32_t st = sbase + b * STAGE_B;
#pragma unroll
        for (int kk = 0; kk < 32; kk += 16) {
            uint32_t AH[4][4], BH[2][4];
            const uint32_t kb = (kk + lh * 8) * 2;
#pragma unroll
            for (int mt = 0; mt < 4; mt++) {
                uint32_t a0 = st + (wr * 64 + mt * 16 + lr) * 80 + kb;
                LDSM4(AH[mt], a0);
            }
            if (TRB) {
                // B smem [32 k][64 n], pitch 144B. Tiles: (k8, n8) x4 per np.
#pragma unroll
                for (int np = 0; np < 2; np++) {
                    uint32_t b0 = st + 10240 + (kk + lr) * 144
                                + (wc * 32 + np * 16 + lh * 8) * 2;
                    LDSM4_T(BH[np], b0);
                }
#pragma unroll
                for (int mt = 0; mt < 4; mt++)
#pragma unroll
                    for (int np = 0; np < 2; np++) {
                        MMA_F16(acc[mt][2 * np],     AH[mt], BH[np][0], BH[np][1]);
                        MMA_F16(acc[mt][2 * np + 1], AH[mt], BH[np][2], BH[np][3]);
                    }
            } else {
#pragma unroll
                for (int np = 0; np < 2; np++) {
                    uint32_t b0 = st + 10240 + (wc * 32 + np * 16 + lr) * 80 + kb;
                    LDSM4(BH[np], b0);
                }
#pragma unroll
                for (int mt = 0; mt < 4; mt++)
#pragma unroll
                    for (int np = 0; np < 2; np++) {
                        MMA_F16(acc[mt][2 * np],     AH[mt], BH[np][0], BH[np][2]);
                        MMA_F16(acc[mt][2 * np + 1], AH[mt], BH[np][1], BH[np][3]);
                    }
            }
        }
    }
#undef LOAD_STAGE

    const int rql = l >> 2, cpl = (l & 3) * 2;

    if (EXP) {
        // ---- QK epilogue: exp + causal mask + fp16 store + row partials ----
        __syncthreads();
        float* partS = reinterpret_cast<float*>(smem);   // [2][128]
#pragma unroll
        for (int mt = 0; mt < 4; mt++) {
            const int rl = wr * 64 + mt * 16 + rql;
            const int grow = by * 128 + rl;
#pragma unroll
            for (int dummy = 0; dummy < 1; dummy++) {}
            float p0 = 0.f, p1 = 0.f;
#pragma unroll
            for (int nt = 0; nt < 4; nt++) {
                const int col = bx * 64 + wc * 32 + nt * 8 + cpl;
                float e0 = (col     <= grow)     ? __expf(acc[mt][nt][0] * alpha) : 0.f;
                float e1 = (col + 1 <= grow)     ? __expf(acc[mt][nt][1] * alpha) : 0.f;
                float e2 = (col     <= grow + 8) ? __expf(acc[mt][nt][2] * alpha) : 0.f;
                float e3 = (col + 1 <= grow + 8) ? __expf(acc[mt][nt][3] * alpha) : 0.f;
                __half h0 = __float2half(e0), h1 = __float2half(e1);
                __half h2 = __float2half(e2), h3 = __float2half(e3);
                const long o0 = (long)bz * strideCz + (long)grow * ldc + col;
                *reinterpret_cast<uint32_t*>(Ch + o0) =
                    (uint32_t)__half_as_ushort(h0) | ((uint32_t)__half_as_ushort(h1) << 16);
                *reinterpret_cast<uint32_t*>(Ch + o0 + 8L * ldc) =
                    (uint32_t)__half_as_ushort(h2) | ((uint32_t)__half_as_ushort(h3) << 16);
                p0 += e0 + e1;
                p1 += e2 + e3;
            }
            p0 += __shfl_xor_sync(0xffffffffu, p0, 1);
            p0 += __shfl_xor_sync(0xffffffffu, p0, 2);
            p1 += __shfl_xor_sync(0xffffffffu, p1, 1);
            p1 += __shfl_xor_sync(0xffffffffu, p1, 2);
            if ((l & 3) == 0) {
                partS[wc * 128 + rl] = p0;
                partS[wc * 128 + rl + 8] = p1;
            }
        }
        __syncthreads();
        if (tid < 128) {
            float sv = partS[tid] + partS[128 + tid];
            part[((long)bz * SEQ + by * 128 + tid) * 32 + bx] = sv;
        }
        return;
    }

    // ---- standard epilogue ----
#pragma unroll
    for (int mt = 0; mt < 4; mt++) {
        const long row = (long)by * 128 + wr * 64 + mt * 16 + rql;
        float s0 = 1.f, s1 = 1.f;
        if (RSCALE) {
            s0 = invS[(long)bz * SEQ + row];
            s1 = invS[(long)bz * SEQ + row + 8];
        }
#pragma unroll
        for (int nt = 0; nt < 4; nt++) {
            const int col = bx * 64 + wc * 32 + nt * 8 + cpl;
            float v0 = acc[mt][nt][0] * alpha, v1 = acc[mt][nt][1] * alpha;
            float v2 = acc[mt][nt][2] * alpha, v3 = acc[mt][nt][3] * alpha;
            if (RSCALE) { v0 *= s0; v1 *= s0; v2 *= s1; v3 *= s1; }
            if (BIAS) {
                float b0 = bias[col], b1 = bias[col + 1];
                v0 += b0; v1 += b1; v2 += b0; v3 += b1;
            }
            const long o0 = (long)bz * strideCz + row * ldc + col;
            const long o1 = o0 + 8L * ldc;
            if (WF32) {
                *reinterpret_cast<float2*>(Cf + o0) = make_float2(v0, v1);
                *reinterpret_cast<float2*>(Cf + o1) = make_float2(v2, v3);
            } else {
                __half h0 = __float2half(v0), h1 = __float2half(v1);
                __half h2 = __float2half(v2), h3 = __float2half(v3);
                *reinterpret_cast<uint32_t*>(Ch + o0) =
                    (uint32_t)__half_as_ushort(h0) | ((uint32_t)__half_as_ushort(h1) << 16);
                *reinterpret_cast<uint32_t*>(Ch + o1) =
                    (uint32_t)__half_as_ushort(h2) | ((uint32_t)__half_as_ushort(h3) << 16);
            }
        }
    }
}

// ---------------------------------------------------------------------------
// fp32 -> fp16; y-dim: 0..2 = xq/xk/xv (n elems), 3 = W (nW elems)
// ---------------------------------------------------------------------------
__global__ void __launch_bounds__(256) cvtH4(const float* __restrict__ i0,
                                             const float* __restrict__ i1,
                                             const float* __restrict__ i2,
                                             const float* __restrict__ i3,
                                             __half* __restrict__ o0,
                                             __half* __restrict__ o1,
                                             __half* __restrict__ o2,
                                             __half* __restrict__ o3,
                                             long n, long nW)
{
    const int y = blockIdx.y;
    const float* in = (y == 0) ? i0 : (y == 1) ? i1 : (y == 2) ? i2 : i3;
    __half* out = (y == 0) ? o0 : (y == 1) ? o1 : (y == 2) ? o2 : o3;
    const long lim = (y == 3) ? nW : n;
    long i = ((long)blockIdx.x * 256 + threadIdx.x) * 4;
    if (i >= lim) return;
    float4 v = *reinterpret_cast<const float4*>(in + i);
    __half h0 = __float2half(v.x), h1 = __float2half(v.y);
    __half h2 = __float2half(v.z), h3 = __float2half(v.w);
    uint32_t hA = (uint32_t)__half_as_ushort(h0) | ((uint32_t)__half_as_ushort(h1) << 16);
    uint32_t hB = (uint32_t)__half_as_ushort(h2) | ((uint32_t)__half_as_ushort(h3) << 16);
    *reinterpret_cast<uint2*>(out + i) = make_uint2(hA, hB);
}

// ---------------------------------------------------------------------------
// Sum the valid col-tile partials per row, invert.
// ---------------------------------------------------------------------------
__global__ void __launch_bounds__(256) reduce_invS(const float* __restrict__ part,
                                                   float* __restrict__ invS)
{
    const int r = blockIdx.x * 256 + threadIdx.x;
    if (r >= MTOT) return;
    const int q = r & (SEQ - 1);
    const int ntile = (q >> 6) + 1;
    const float* p = part + (long)r * 32;
    float s = 0.f;
    for (int i = 0; i < ntile; i++) s += p[i];
    invS[r] = 1.f / s;
}

// ---------------------------------------------------------------------------
extern "C" void kernel_launch(void* const* d_in, const int* in_sizes, int n_in,
                              void* d_out, int out_size)
{
    (void)in_sizes; (void)n_in; (void)out_size;
    const float* xq = (const float*)d_in[0];
    const float* xk = (const float*)d_in[1];
    const float* xv = (const float*)d_in[2];
    const float* Wq = (const float*)d_in[3];
    const float* bq = (const float*)d_in[4];
    float* out = (float*)d_out;

    void *x1, *W1, *QKV, *P1, *part, *invS;
    cudaGetSymbolAddress(&x1, g_x1);
    cudaGetSymbolAddress(&W1, g_W1);
    cudaGetSymbolAddress(&QKV, g_QKV);
    cudaGetSymbolAddress(&P1, g_P1);
    cudaGetSymbolAddress(&part, g_part);
    cudaGetSymbolAddress(&invS, g_invS);

    __half* X = (__half*)x1;
    __half* Q1 = (__half*)QKV;
    __half* K1 = Q1 + NELEM;
    __half* V1 = Q1 + 2 * NELEM;

    auto kProj = gemm_f16<false, false, true, false, false, false, false>;
    auto kQK   = gemm_f16<true,  false, false, false, false, true,  false>;
    auto kPV   = gemm_f16<false, true,  false, true,  true,  false, true>;
    cudaFuncSetAttribute(kProj, cudaFuncAttributeMaxDynamicSharedMemorySize, SMEM_REQ);
    cudaFuncSetAttribute(kQK,   cudaFuncAttributeMaxDynamicSharedMemorySize, SMEM_REQ);
    cudaFuncSetAttribute(kPV,   cudaFuncAttributeMaxDynamicSharedMemorySize, SMEM_REQ);

    // 1) fp32 -> fp16 conversions (x planes + W, one launch)
    cvtH4<<<dim3((unsigned)(NELEM / 4 / 256), 4), 256>>>(
        xq, xk, xv, Wq, X, X + NELEM, X + 2 * NELEM, (__half*)W1,
        NELEM, (long)EMB * EMB);

    // 2) one launch: Q/K/V = x @ W^T + b -> fp16
    {
        dim3 g(EMB / 64, MTOT / 128, 3);
        kProj<<<g, 128, SMEM_REQ>>>(X, NELEM, (const __half*)W1, 0, EMB,
                                    EMB, 1.0f, bq, nullptr, nullptr,
                                    nullptr, Q1, EMB, NELEM);
    }

    // 3) QK + exp + mask + partial sums
    {
        dim3 g(SEQ / 64, SEQ / 128, BATCH);
        kQK<<<g, 128, SMEM_REQ>>>(Q1, (long)SEQ * EMB, K1, (long)SEQ * EMB, EMB,
                                  EMB, 0.03125f, nullptr, nullptr, (float*)part,
                                  nullptr, (__half*)P1, SEQ, (long)SEQ * SEQ);
    }

    // 4) invS = 1 / row-sum
    reduce_invS<<<MTOT / 256, 256>>>((const float*)part, (float*)invS);

    // 5) out = invS * (E @ V) — V consumed directly via ldmatrix.trans
    {
        dim3 g(EMB / 64, SEQ / 128, BATCH);
        kPV<<<g, 128, SMEM_REQ>>>((const __half*)P1, (long)SEQ * SEQ,
                                  V1, (long)SEQ * EMB, EMB,
                                  SEQ, 1.0f, nullptr, (const float*)invS, nullptr,
                                  out, nullptr, EMB, (long)SEQ * EMB);
    }
}

// round 13
// speedup vs baseline: 7.8516x; 1.1050x over previous
#include <cuda_runtime.h>
#include <cuda_fp16.h>
#include <cstdint>

#define BATCH 4
#define SEQ   2048
#define EMB   1024
#define MTOT  (BATCH * SEQ)                 // 8192
#define NELEM ((long)MTOT * EMB)            // 8388608
#define NP    ((long)BATCH * SEQ * SEQ)     // 16777216

// ---------------------------------------------------------------------------
// Scratch — packed fp16 planes.
// ---------------------------------------------------------------------------
__device__ __half g_x1[3 * NELEM];           // [xq | xk | xv] fp16
__device__ __half g_W1[(long)EMB * EMB];
__device__ __half g_QKV[3 * NELEM];          // [Q | K | V] fp16
__device__ __half g_P1[NP];                  // un-normalized exp(s), fp16
__device__ float  g_part[(long)MTOT * 32];   // per-(row, col-tile) partial sums
__device__ float  g_invS[MTOT];              // per-row 1/sum

// ---------------------------------------------------------------------------
__device__ __forceinline__ uint32_t smem_u32(const void* p) {
    uint32_t a;
    asm("{ .reg .u64 t; cvta.to.shared.u64 t, %1; cvt.u32.u64 %0, t; }" : "=r"(a) : "l"(p));
    return a;
}

#define LDSM4(r, addr) \
    asm volatile("ldmatrix.sync.aligned.m8n8.x4.shared.b16 {%0,%1,%2,%3}, [%4];" \
        : "=r"((r)[0]), "=r"((r)[1]), "=r"((r)[2]), "=r"((r)[3]) : "r"(addr))

#define LDSM4_T(r, addr) \
    asm volatile("ldmatrix.sync.aligned.m8n8.x4.trans.shared.b16 {%0,%1,%2,%3}, [%4];" \
        : "=r"((r)[0]), "=r"((r)[1]), "=r"((r)[2]), "=r"((r)[3]) : "r"(addr))

#define MMA_F16(d, a, b0, b1) \
    asm volatile("mma.sync.aligned.m16n8k16.row.col.f32.f16.f16.f32 " \
        "{%0,%1,%2,%3}, {%4,%5,%6,%7}, {%8,%9}, {%0,%1,%2,%3};" \
        : "+f"((d)[0]), "+f"((d)[1]), "+f"((d)[2]), "+f"((d)[3]) \
        : "r"((a)[0]), "r"((a)[1]), "r"((a)[2]), "r"((a)[3]), "r"(b0), "r"(b1))

// CTA tile 128x64, BK=64. Row pitch 144B (64 fp16 + 8 pad): 9 x 16B chunks
// per row -> consecutive rows offset by 1 bank-group (odd multiple) ->
// conflict-free for cp.async writes, LDSM row reads, and LDSM_T k-row reads.
// A tile: 128 x 144 = 18432. B tile: 64 x 144 = 9216. Stage = 27648.
#define A_BYTES   18432u
#define STAGE_B   27648u
#define SMEM_REQ  (2 * STAGE_B)

// ---------------------------------------------------------------------------
// fp16 TC GEMM (fp32 accum): 128x64 tile, 4 warps (2m x 2n), 4 CTAs/SM.
// EXP: QK mode — epilogue does exp + causal mask + fp16 store + row partials.
// RSCALE: PV mode — multiply row r by invS[bz*SEQ+r].
// TRB: B stored [K][N] row-major (V direct); fragments via ldmatrix.trans.
// ---------------------------------------------------------------------------
template <bool CAUSAL, bool TRUNCK, bool BIAS, bool WF32, bool RSCALE, bool EXP, bool TRB>
__global__ void __launch_bounds__(128, 4)
gemm_f16(const __half* __restrict__ A, long strideAz,
         const __half* __restrict__ B, long strideBz, int ldb,
         int K, float alpha, const float* __restrict__ bias,
         const float* __restrict__ invS, float* __restrict__ part,
         float* __restrict__ Cf, __half* __restrict__ Ch,
         int ldc, long strideCz)
{
    const int bx = blockIdx.x, bz = blockIdx.z;
    const int by = TRUNCK ? (gridDim.y - 1 - blockIdx.y) : blockIdx.y;
    if (CAUSAL && bx > 2 * by + 1) return;

    extern __shared__ char smem[];
    const uint32_t sbase = smem_u32(smem);

    const __half* Ab = A + (long)bz * strideAz;
    const __half* Bb = B + (long)bz * strideBz;

    const int tid = threadIdx.x, wid = tid >> 5, l = tid & 31;
    const int wr = wid >> 1, wc = wid & 1;
    const int kEnd = TRUNCK ? min(K, (by + 1) * 128) : K;
    const int nst = kEnd >> 6;                // BK=64 stages (>= 2 always)
    const int rowA0 = by * 128, rowB0 = bx * 64;

    float acc[4][4][4];
#pragma unroll
    for (int m = 0; m < 4; m++)
#pragma unroll
        for (int n = 0; n < 4; n++)
#pragma unroll
            for (int j = 0; j < 4; j++) acc[m][n][j] = 0.f;

    // 1536 x 16B chunks per stage: A 1024 (128 rows x 8 segs), B 512
#define LOAD_STAGE(sidx, buf) do { \
        const int k0_ = (sidx) * 64; \
        const uint32_t st_ = sbase + (buf) * STAGE_B; \
        _Pragma("unroll") \
        for (int i_ = 0; i_ < 12; i_++) { \
            int c_ = i_ * 128 + tid; \
            uint32_t dst_; const void* src_; \
            if (c_ < 1024) { \
                int row_ = c_ >> 3, seg_ = c_ & 7; \
                dst_ = st_ + row_ * 144 + seg_ * 16; \
                src_ = Ab + (long)(rowA0 + row_) * K + k0_ + seg_ * 8; \
            } else if (TRB) { \
                int w_ = c_ - 1024; \
                int row_ = w_ >> 3, seg_ = w_ & 7; \
                dst_ = st_ + A_BYTES + row_ * 144 + seg_ * 16; \
                src_ = Bb + (long)(k0_ + row_) * ldb + rowB0 + seg_ * 8; \
            } else { \
                int w_ = c_ - 1024; \
                int row_ = w_ >> 3, seg_ = w_ & 7; \
                dst_ = st_ + A_BYTES + row_ * 144 + seg_ * 16; \
                src_ = Bb + (long)(rowB0 + row_) * ldb + k0_ + seg_ * 8; \
            } \
            asm volatile("cp.async.cg.shared.global [%0], [%1], 16;" :: "r"(dst_), "l"(src_)); \
        } \
        asm volatile("cp.async.commit_group;"); \
    } while (0)

    LOAD_STAGE(0, 0);

    const int lr = l & 15, lh = l >> 4;

    for (int s = 0; s < nst; s++) {
        const int b = s & 1;
        asm volatile("cp.async.wait_group 0;");
        __syncthreads();
        if (s + 1 < nst) LOAD_STAGE(s + 1, b ^ 1);

        const uint32_t st = sbase + b * STAGE_B;
#pragma unroll
        for (int kk = 0; kk < 64; kk += 16) {
            uint32_t AH[4][4], BH[2][4];
            const uint32_t kb = (kk + lh * 8) * 2;
#pragma unroll
            for (int mt = 0; mt < 4; mt++) {
                uint32_t a0 = st + (wr * 64 + mt * 16 + lr) * 144 + kb;
                LDSM4(AH[mt], a0);
            }
            if (TRB) {
                // B smem [64 k][64 n], pitch 144B; (k8, n8) tiles via trans.
#pragma unroll
                for (int np = 0; np < 2; np++) {
                    uint32_t b0 = st + A_BYTES + (kk + lr) * 144
                                + (wc * 32 + np * 16 + lh * 8) * 2;
                    LDSM4_T(BH[np], b0);
                }
#pragma unroll
                for (int mt = 0; mt < 4; mt++)
#pragma unroll
                    for (int np = 0; np < 2; np++) {
                        MMA_F16(acc[mt][2 * np],     AH[mt], BH[np][0], BH[np][1]);
                        MMA_F16(acc[mt][2 * np + 1], AH[mt], BH[np][2], BH[np][3]);
                    }
            } else {
#pragma unroll
                for (int np = 0; np < 2; np++) {
                    uint32_t b0 = st + A_BYTES + (wc * 32 + np * 16 + lr) * 144 + kb;
                    LDSM4(BH[np], b0);
                }
#pragma unroll
                for (int mt = 0; mt < 4; mt++)
#pragma unroll
                    for (int np = 0; np < 2; np++) {
                        MMA_F16(acc[mt][2 * np],     AH[mt], BH[np][0], BH[np][2]);
                        MMA_F16(acc[mt][2 * np + 1], AH[mt], BH[np][1], BH[np][3]);
                    }
            }
        }
    }
#undef LOAD_STAGE

    const int rql = l >> 2, cpl = (l & 3) * 2;

    if (EXP) {
        // ---- QK epilogue: exp + causal mask + fp16 store + row partials ----
        __syncthreads();
        float* partS = reinterpret_cast<float*>(smem);   // [2][128]
#pragma unroll
        for (int mt = 0; mt < 4; mt++) {
            const int rl = wr * 64 + mt * 16 + rql;
            const int grow = by * 128 + rl;
            float p0 = 0.f, p1 = 0.f;
#pragma unroll
            for (int nt = 0; nt < 4; nt++) {
                const int col = bx * 64 + wc * 32 + nt * 8 + cpl;
                float e0 = (col     <= grow)     ? __expf(acc[mt][nt][0] * alpha) : 0.f;
                float e1 = (col + 1 <= grow)     ? __expf(acc[mt][nt][1] * alpha) : 0.f;
                float e2 = (col     <= grow + 8) ? __expf(acc[mt][nt][2] * alpha) : 0.f;
                float e3 = (col + 1 <= grow + 8) ? __expf(acc[mt][nt][3] * alpha) : 0.f;
                __half h0 = __float2half(e0), h1 = __float2half(e1);
                __half h2 = __float2half(e2), h3 = __float2half(e3);
                const long o0 = (long)bz * strideCz + (long)grow * ldc + col;
                *reinterpret_cast<uint32_t*>(Ch + o0) =
                    (uint32_t)__half_as_ushort(h0) | ((uint32_t)__half_as_ushort(h1) << 16);
                *reinterpret_cast<uint32_t*>(Ch + o0 + 8L * ldc) =
                    (uint32_t)__half_as_ushort(h2) | ((uint32_t)__half_as_ushort(h3) << 16);
                p0 += e0 + e1;
                p1 += e2 + e3;
            }
            p0 += __shfl_xor_sync(0xffffffffu, p0, 1);
            p0 += __shfl_xor_sync(0xffffffffu, p0, 2);
            p1 += __shfl_xor_sync(0xffffffffu, p1, 1);
            p1 += __shfl_xor_sync(0xffffffffu, p1, 2);
            if ((l & 3) == 0) {
                partS[wc * 128 + rl] = p0;
                partS[wc * 128 + rl + 8] = p1;
            }
        }
        __syncthreads();
        if (tid < 128) {
            float sv = partS[tid] + partS[128 + tid];
            part[((long)bz * SEQ + by * 128 + tid) * 32 + bx] = sv;
        }
        return;
    }

    // ---- standard epilogue ----
#pragma unroll
    for (int mt = 0; mt < 4; mt++) {
        const long row = (long)by * 128 + wr * 64 + mt * 16 + rql;
        float s0 = 1.f, s1 = 1.f;
        if (RSCALE) {
            s0 = invS[(long)bz * SEQ + row];
            s1 = invS[(long)bz * SEQ + row + 8];
        }
#pragma unroll
        for (int nt = 0; nt < 4; nt++) {
            const int col = bx * 64 + wc * 32 + nt * 8 + cpl;
            float v0 = acc[mt][nt][0] * alpha, v1 = acc[mt][nt][1] * alpha;
            float v2 = acc[mt][nt][2] * alpha, v3 = acc[mt][nt][3] * alpha;
            if (RSCALE) { v0 *= s0; v1 *= s0; v2 *= s1; v3 *= s1; }
            if (BIAS) {
                float b0 = bias[col], b1 = bias[col + 1];
                v0 += b0; v1 += b1; v2 += b0; v3 += b1;
            }
            const long o0 = (long)bz * strideCz + row * ldc + col;
            const long o1 = o0 + 8L * ldc;
            if (WF32) {
                *reinterpret_cast<float2*>(Cf + o0) = make_float2(v0, v1);
                *reinterpret_cast<float2*>(Cf + o1) = make_float2(v2, v3);
            } else {
                __half h0 = __float2half(v0), h1 = __float2half(v1);
                __half h2 = __float2half(v2), h3 = __float2half(v3);
                *reinterpret_cast<uint32_t*>(Ch + o0) =
                    (uint32_t)__half_as_ushort(h0) | ((uint32_t)__half_as_ushort(h1) << 16);
                *reinterpret_cast<uint32_t*>(Ch + o1) =
                    (uint32_t)__half_as_ushort(h2) | ((uint32_t)__half_as_ushort(h3) << 16);
            }
        }
    }
}

// ---------------------------------------------------------------------------
// fp32 -> fp16; y-dim: 0..2 = xq/xk/xv (n elems), 3 = W (nW elems)
// ---------------------------------------------------------------------------
__global__ void __launch_bounds__(256) cvtH4(const float* __restrict__ i0,
                                             const float* __restrict__ i1,
                                             const float* __restrict__ i2,
                                             const float* __restrict__ i3,
                                             __half* __restrict__ o0,
                                             __half* __restrict__ o1,
                                             __half* __restrict__ o2,
                                             __half* __restrict__ o3,
                                             long n, long nW)
{
    const int y = blockIdx.y;
    const float* in = (y == 0) ? i0 : (y == 1) ? i1 : (y == 2) ? i2 : i3;
    __half* out = (y == 0) ? o0 : (y == 1) ? o1 : (y == 2) ? o2 : o3;
    const long lim = (y == 3) ? nW : n;
    long i = ((long)blockIdx.x * 256 + threadIdx.x) * 4;
    if (i >= lim) return;
    float4 v = *reinterpret_cast<const float4*>(in + i);
    __half h0 = __float2half(v.x), h1 = __float2half(v.y);
    __half h2 = __float2half(v.z), h3 = __float2half(v.w);
    uint32_t hA = (uint32_t)__half_as_ushort(h0) | ((uint32_t)__half_as_ushort(h1) << 16);
    uint32_t hB = (uint32_t)__half_as_ushort(h2) | ((uint32_t)__half_as_ushort(h3) << 16);
    *reinterpret_cast<uint2*>(out + i) = make_uint2(hA, hB);
}

// ---------------------------------------------------------------------------
// Warp-per-row invS reduction: lane i loads partial i (i < ntile), shfl-sum.
// ---------------------------------------------------------------------------
__global__ void __launch_bounds__(256) reduce_invS(const float* __restrict__ part,
                                                   float* __restrict__ invS)
{
    const int r = blockIdx.x * 8 + (threadIdx.x >> 5);
    const int lane = threadIdx.x & 31;
    const int q = r & (SEQ - 1);
    const int ntile = (q >> 6) + 1;
    float s = (lane < ntile) ? part[(long)r * 32 + lane] : 0.f;
#pragma unroll
    for (int o = 16; o > 0; o >>= 1) s += __shfl_xor_sync(0xffffffffu, s, o);
    if (lane == 0) invS[r] = 1.f / s;
}

// ---------------------------------------------------------------------------
extern "C" void kernel_launch(void* const* d_in, const int* in_sizes, int n_in,
                              void* d_out, int out_size)
{
    (void)in_sizes; (void)n_in; (void)out_size;
    const float* xq = (const float*)d_in[0];
    const float* xk = (const float*)d_in[1];
    const float* xv = (const float*)d_in[2];
    const float* Wq = (const float*)d_in[3];
    const float* bq = (const float*)d_in[4];
    float* out = (float*)d_out;

    void *x1, *W1, *QKV, *P1, *part, *invS;
    cudaGetSymbolAddress(&x1, g_x1);
    cudaGetSymbolAddress(&W1, g_W1);
    cudaGetSymbolAddress(&QKV, g_QKV);
    cudaGetSymbolAddress(&P1, g_P1);
    cudaGetSymbolAddress(&part, g_part);
    cudaGetSymbolAddress(&invS, g_invS);

    __half* X = (__half*)x1;
    __half* Q1 = (__half*)QKV;
    __half* K1 = Q1 + NELEM;
    __half* V1 = Q1 + 2 * NELEM;

    auto kProj = gemm_f16<false, false, true, false, false, false, false>;
    auto kQK   = gemm_f16<true,  false, false, false, false, true,  false>;
    auto kPV   = gemm_f16<false, true,  false, true,  true,  false, true>;
    cudaFuncSetAttribute(kProj, cudaFuncAttributeMaxDynamicSharedMemorySize, SMEM_REQ);
    cudaFuncSetAttribute(kQK,   cudaFuncAttributeMaxDynamicSharedMemorySize, SMEM_REQ);
    cudaFuncSetAttribute(kPV,   cudaFuncAttributeMaxDynamicSharedMemorySize, SMEM_REQ);

    // 1) fp32 -> fp16 conversions (x planes + W, one launch)
    cvtH4<<<dim3((unsigned)(NELEM / 4 / 256), 4), 256>>>(
        xq, xk, xv, Wq, X, X + NELEM, X + 2 * NELEM, (__half*)W1,
        NELEM, (long)EMB * EMB);

    // 2) one launch: Q/K/V = x @ W^T + b -> fp16
    {
        dim3 g(EMB / 64, MTOT / 128, 3);
        kProj<<<g, 128, SMEM_REQ>>>(X, NELEM, (const __half*)W1, 0, EMB,
                                    EMB, 1.0f, bq, nullptr, nullptr,
                                    nullptr, Q1, EMB, NELEM);
    }

    // 3) QK + exp + mask + partial sums
    {
        dim3 g(SEQ / 64, SEQ / 128, BATCH);
        kQK<<<g, 128, SMEM_REQ>>>(Q1, (long)SEQ * EMB, K1, (long)SEQ * EMB, EMB,
                                  EMB, 0.03125f, nullptr, nullptr, (float*)part,
                                  nullptr, (__half*)P1, SEQ, (long)SEQ * SEQ);
    }

    // 4) invS = 1 / row-sum (warp per row)
    reduce_invS<<<MTOT / 8, 256>>>((const float*)part, (float*)invS);

    // 5) out = invS * (E @ V) — V consumed directly via ldmatrix.trans
    {
        dim3 g(EMB / 64, SEQ / 128, BATCH);
        kPV<<<g, 128, SMEM_REQ>>>((const __half*)P1, (long)SEQ * SEQ,
                                  V1, (long)SEQ * EMB, EMB,
                                  SEQ, 1.0f, nullptr, (const float*)invS, nullptr,
                                  out, nullptr, EMB, (long)SEQ * EMB);
    }
}